// round 2
// baseline (speedup 1.0000x reference)
#include <cuda_runtime.h>
#include <math.h>

#define BB 64
#define LL 128
#define DD 200
#define MPP 20
#define ATTN 50
#define OC 83

// ---------------- scratch (no cudaMalloc allowed) ----------------
__device__ __align__(16) float g_e_rt[BB * LL * ATTN];
__device__ __align__(16) float g_e_lt[BB * LL * ATTN];
__device__ __align__(16) float g_att_lt[BB * LL * DD];
__device__ int g_pos[BB * LL];

// packed fp32x2 FMA (Blackwell FFMA2; ptxas will not auto-fuse, PTX form required)
__device__ __forceinline__ float2 ffma2(float2 a, float2 b, float2 c) {
    float2 d;
    asm("{\n\t"
        ".reg .b64 ra, rb, rc, rd;\n\t"
        "mov.b64 ra, {%2, %3};\n\t"
        "mov.b64 rb, {%4, %5};\n\t"
        "mov.b64 rc, {%6, %7};\n\t"
        "fma.rn.f32x2 rd, ra, rb, rc;\n\t"
        "mov.b64 {%0, %1}, rd;\n\t"
        "}"
        : "=f"(d.x), "=f"(d.y)
        : "f"(a.x), "f"(a.y), "f"(b.x), "f"(b.y), "f"(c.x), "f"(c.y));
    return d;
}

// ================= full match: out cols [0,21) =================
__global__ __launch_bounds__(128) void full_kernel(
        const float* __restrict__ lt, const float* __restrict__ fw,
        const float* __restrict__ bw, const float* __restrict__ wf,
        float* __restrict__ out) {
    __shared__ float hw[MPP + 1][DD];  // hw[0]=h, hw[1+m]=w_full[m]*h
    int b = blockIdx.x, tid = threadIdx.x;
    for (int idx = tid; idx < (MPP + 1) * DD; idx += 128) {
        int mm = idx / DD, d = idx - mm * DD;
        float hv = (d < DD / 2) ? fw[b * (DD / 2) + d] : bw[b * (DD / 2) + d - DD / 2];
        hw[mm][d] = (mm == 0) ? hv : wf[(mm - 1) * DD + d] * hv;
    }
    __syncthreads();
    int l = tid;
    const float4* row = (const float4*)(lt + (size_t)(b * LL + l) * DD);
    float acc[MPP + 1];
#pragma unroll
    for (int mm = 0; mm <= MPP; mm++) acc[mm] = 0.f;
    for (int d4 = 0; d4 < DD / 4; d4++) {
        float4 x = __ldg(row + d4);
        int d = d4 * 4;
#pragma unroll
        for (int mm = 0; mm <= MPP; mm++)
            acc[mm] += x.x * hw[mm][d] + x.y * hw[mm][d + 1] +
                       x.z * hw[mm][d + 2] + x.w * hw[mm][d + 3];
    }
    float* o = out + (size_t)(b * LL + l) * OC;
#pragma unroll
    for (int mm = 0; mm <= MPP; mm++) o[mm] = tanhf(acc[mm]);
}

// ================= maxpool match: out cols [21,41) =================
// One CTA per (b,m): S = (lt .* w_m) @ rt^T [128x128, K=200], rowwise max, tanh.
// tanh(max) == max(tanh) since tanh monotone.
__global__ __launch_bounds__(256) void maxpool_kernel(
        const float* __restrict__ lt, const float* __restrict__ rt,
        const float* __restrict__ w, float* __restrict__ out) {
    __shared__ float As[8][128];
    __shared__ float Bs[8][128];
    __shared__ float red[128][16];
    int b = blockIdx.x, m = blockIdx.y;
    int tid = threadIdx.x;
    int tx = tid & 15, ty = tid >> 4;
    int lrow = tid >> 1, kq = tid & 1;
    const float4* ltp = (const float4*)(lt + (size_t)(b * LL + lrow) * DD);
    const float4* rtp = (const float4*)(rt + (size_t)(b * LL + lrow) * DD);
    const float4* wp = (const float4*)(w + (size_t)m * DD);
    float2 acc[8][4];
#pragma unroll
    for (int i = 0; i < 8; i++)
#pragma unroll
        for (int j = 0; j < 4; j++) acc[i][j] = make_float2(0.f, 0.f);

    for (int kc = 0; kc < DD / 8; kc++) {
        float4 av = __ldg(ltp + kc * 2 + kq);
        float4 wv = __ldg(wp + kc * 2 + kq);
        float4 bv = __ldg(rtp + kc * 2 + kq);
        int kb = kq * 4;
        As[kb + 0][lrow] = av.x * wv.x;
        As[kb + 1][lrow] = av.y * wv.y;
        As[kb + 2][lrow] = av.z * wv.z;
        As[kb + 3][lrow] = av.w * wv.w;
        Bs[kb + 0][lrow] = bv.x;
        Bs[kb + 1][lrow] = bv.y;
        Bs[kb + 2][lrow] = bv.z;
        Bs[kb + 3][lrow] = bv.w;
        __syncthreads();
#pragma unroll
        for (int k = 0; k < 8; k++) {
            float a[8];
#pragma unroll
            for (int i = 0; i < 8; i++) a[i] = As[k][ty + 16 * i];
#pragma unroll
            for (int j = 0; j < 4; j++) {
                float2 bv2 = *(const float2*)&Bs[k][2 * tx + 32 * j];
#pragma unroll
                for (int i = 0; i < 8; i++)
                    acc[i][j] = ffma2(make_float2(a[i], a[i]), bv2, acc[i][j]);
            }
        }
        __syncthreads();
    }
#pragma unroll
    for (int i = 0; i < 8; i++) {
        float mx = -3.4e38f;
#pragma unroll
        for (int j = 0; j < 4; j++) mx = fmaxf(mx, fmaxf(acc[i][j].x, acc[i][j].y));
        red[ty + 16 * i][tx] = mx;
    }
    __syncthreads();
    if (tid < 128) {
        float mx = red[tid][0];
#pragma unroll
        for (int t = 1; t < 16; t++) mx = fmaxf(mx, red[tid][t]);
        out[(size_t)(b * LL + tid) * OC + 21 + m] = tanhf(mx);
    }
}

// ================= attention projections: e_rt, e_lt =================
__global__ __launch_bounds__(256) void proj_kernel(
        const float* __restrict__ lt, const float* __restrict__ rt,
        const float* __restrict__ w1, const float* __restrict__ w2,
        const float* __restrict__ diag) {
    extern __shared__ float sm[];
    float* w1s = sm;                 // DD*ATTN
    float* w2s = sm + DD * ATTN;     // DD*ATTN
    float* dg = sm + 2 * DD * ATTN;  // ATTN
    int b = blockIdx.x, tid = threadIdx.x;
    for (int i = tid; i < DD * ATTN; i += 256) {
        w1s[i] = w1[i];
        w2s[i] = w2[i];
    }
    if (tid < ATTN) dg[tid] = diag[tid];
    __syncthreads();
    int is_rt = (tid < 128) ? 1 : 0;
    int l = tid & 127;
    const float* base = is_rt ? rt : lt;
    const float4* row = (const float4*)(base + (size_t)(b * LL + l) * DD);
    const float* ws = is_rt ? w1s : w2s;
    float2 acc[ATTN / 2];
#pragma unroll
    for (int a = 0; a < ATTN / 2; a++) acc[a] = make_float2(0.f, 0.f);
    for (int d4 = 0; d4 < DD / 4; d4++) {
        float4 x = __ldg(row + d4);
#pragma unroll
        for (int c = 0; c < 4; c++) {
            float xc = (c == 0) ? x.x : (c == 1) ? x.y : (c == 2) ? x.z : x.w;
            const float2* wr = (const float2*)(ws + (d4 * 4 + c) * ATTN);
            float2 x2 = make_float2(xc, xc);
#pragma unroll
            for (int a = 0; a < ATTN / 2; a++) acc[a] = ffma2(x2, wr[a], acc[a]);
        }
    }
    float* e = (is_rt ? g_e_rt : g_e_lt) + (size_t)(b * LL + l) * ATTN;
#pragma unroll
    for (int a = 0; a < ATTN / 2; a++) {
        float v0 = tanhf(acc[a].x), v1 = tanhf(acc[a].y);
        if (is_rt) {
            v0 *= dg[2 * a];
            v1 *= dg[2 * a + 1];
        }
        e[2 * a] = v0;
        e[2 * a + 1] = v1;
    }
}

// ================= attentive match core: logits + softmax + att_lt =================
// smem layout (floats): Z[128*129] | ers[128*50] | eltsT[50*128] (reused as Bs[8*128] in phase 2)
__global__ __launch_bounds__(256) void attn_kernel(const float* __restrict__ lt) {
    extern __shared__ float sm[];
    float* Z = sm;                      // 16512
    float* ers = sm + 16512;            // 6400
    float* eltsT = sm + 16512 + 6400;   // 6400 (phase1), Bs aliases this (phase2)
    float* Bs = eltsT;
    int b = blockIdx.x, tid = threadIdx.x;
    int tx = tid & 15, ty = tid >> 4;

    for (int i = tid; i < LL * ATTN; i += 256) {
        ers[i] = g_e_rt[(size_t)b * LL * ATTN + i];
        int l = i / ATTN, a = i - l * ATTN;
        eltsT[a * LL + l] = g_e_lt[(size_t)b * LL * ATTN + i];
    }
    __syncthreads();

    // phase 1: Z[r][c] = sum_a ers[r][a] * eltsT[a][c]
    {
        float2 acc[8][4];
#pragma unroll
        for (int i = 0; i < 8; i++)
#pragma unroll
            for (int j = 0; j < 4; j++) acc[i][j] = make_float2(0.f, 0.f);
        for (int k = 0; k < ATTN; k++) {
            float a[8];
#pragma unroll
            for (int i = 0; i < 8; i++) a[i] = ers[(ty + 16 * i) * ATTN + k];
#pragma unroll
            for (int j = 0; j < 4; j++) {
                float2 bv = *(const float2*)&eltsT[k * LL + 2 * tx + 32 * j];
#pragma unroll
                for (int i = 0; i < 8; i++)
                    acc[i][j] = ffma2(make_float2(a[i], a[i]), bv, acc[i][j]);
            }
        }
#pragma unroll
        for (int i = 0; i < 8; i++)
#pragma unroll
            for (int j = 0; j < 4; j++) {
                int r = ty + 16 * i, c = 2 * tx + 32 * j;
                Z[r * 129 + c] = acc[i][j].x;
                Z[r * 129 + c + 1] = acc[i][j].y;
            }
    }
    __syncthreads();

    // softmax over each row of Z
    if (tid < 128) {
        float* zr = Z + tid * 129;
        float mx = zr[0];
        for (int k = 1; k < 128; k++) mx = fmaxf(mx, zr[k]);
        float s = 0.f;
        for (int k = 0; k < 128; k++) {
            float e = expf(zr[k] - mx);
            zr[k] = e;
            s += e;
        }
        float inv = 1.f / s;
        for (int k = 0; k < 128; k++) zr[k] *= inv;
    }
    __syncthreads();

    // phase 2: att_lt[r][d] = sum_ll Z[r][ll] * lt[ll][d]  (d in two 128-wide blocks)
    for (int nb = 0; nb < 2; nb++) {
        float2 acc[8][4];
#pragma unroll
        for (int i = 0; i < 8; i++)
#pragma unroll
            for (int j = 0; j < 4; j++) acc[i][j] = make_float2(0.f, 0.f);
        for (int kc = 0; kc < 16; kc++) {
            int k = tid >> 5;
            int c4 = tid & 31;
            int gcol = nb * 128 + c4 * 4;
            int grow = kc * 8 + k;
            float4 v = make_float4(0.f, 0.f, 0.f, 0.f);
            if (gcol + 3 < DD)
                v = __ldg((const float4*)(lt + (size_t)(b * LL + grow) * DD + gcol));
            *(float4*)&Bs[k * 128 + c4 * 4] = v;
            __syncthreads();
#pragma unroll
            for (int kk = 0; kk < 8; kk++) {
                float a[8];
#pragma unroll
                for (int i = 0; i < 8; i++) a[i] = Z[(ty + 16 * i) * 129 + kc * 8 + kk];
#pragma unroll
                for (int j = 0; j < 4; j++) {
                    float2 bv = *(const float2*)&Bs[kk * 128 + 2 * tx + 32 * j];
#pragma unroll
                    for (int i = 0; i < 8; i++)
                        acc[i][j] = ffma2(make_float2(a[i], a[i]), bv, acc[i][j]);
                }
            }
            __syncthreads();
        }
#pragma unroll
        for (int i = 0; i < 8; i++)
#pragma unroll
            for (int j = 0; j < 4; j++) {
                int r = ty + 16 * i;
                int d = nb * 128 + 2 * tx + 32 * j;
                if (d < DD - 1)
                    *(float2*)(g_att_lt + (size_t)(b * LL + r) * DD + d) =
                        make_float2(acc[i][j].x, acc[i][j].y);
            }
    }
}

// ================= max-attentive: argmax of normalized cosine =================
// rel[lr][ll] = (rt[lr].lt[ll]) / (||rt[lr]|| * ||lt[ll]||); ||rt|| > 0 drops out of argmax.
__global__ __launch_bounds__(256) void maxatt_kernel(
        const float* __restrict__ lt, const float* __restrict__ rt) {
    __shared__ float As[8][128];
    __shared__ float Bs[8][128];
    __shared__ float nlt[128];
    __shared__ float redv[128][16];
    __shared__ int redi[128][16];
    int b = blockIdx.x, tid = threadIdx.x;
    int tx = tid & 15, ty = tid >> 4;
    if (tid < 128) {
        const float4* p = (const float4*)(lt + (size_t)(b * LL + tid) * DD);
        float s = 0.f;
        for (int i = 0; i < DD / 4; i++) {
            float4 v = __ldg(p + i);
            s += v.x * v.x + v.y * v.y + v.z * v.z + v.w * v.w;
        }
        nlt[tid] = rsqrtf(fmaxf(s, 1e-6f));
    }
    int lrow = tid >> 1, kq = tid & 1;
    const float4* ap = (const float4*)(rt + (size_t)(b * LL + lrow) * DD);
    const float4* bp = (const float4*)(lt + (size_t)(b * LL + lrow) * DD);
    float2 acc[8][4];
#pragma unroll
    for (int i = 0; i < 8; i++)
#pragma unroll
        for (int j = 0; j < 4; j++) acc[i][j] = make_float2(0.f, 0.f);
    for (int kc = 0; kc < DD / 8; kc++) {
        float4 av = __ldg(ap + kc * 2 + kq);
        float4 bv = __ldg(bp + kc * 2 + kq);
        int kb = kq * 4;
        As[kb + 0][lrow] = av.x;
        As[kb + 1][lrow] = av.y;
        As[kb + 2][lrow] = av.z;
        As[kb + 3][lrow] = av.w;
        Bs[kb + 0][lrow] = bv.x;
        Bs[kb + 1][lrow] = bv.y;
        Bs[kb + 2][lrow] = bv.z;
        Bs[kb + 3][lrow] = bv.w;
        __syncthreads();
#pragma unroll
        for (int k = 0; k < 8; k++) {
            float a[8];
#pragma unroll
            for (int i = 0; i < 8; i++) a[i] = As[k][ty + 16 * i];
#pragma unroll
            for (int j = 0; j < 4; j++) {
                float2 bv2 = *(const float2*)&Bs[k][2 * tx + 32 * j];
#pragma unroll
                for (int i = 0; i < 8; i++)
                    acc[i][j] = ffma2(make_float2(a[i], a[i]), bv2, acc[i][j]);
            }
        }
        __syncthreads();
    }
#pragma unroll
    for (int i = 0; i < 8; i++) {
        int r = ty + 16 * i;
        float best = -3.4e38f;
        int bi = 0;
#pragma unroll
        for (int j = 0; j < 4; j++) {
            int c = 2 * tx + 32 * j;
            float v0 = acc[i][j].x * nlt[c];
            float v1 = acc[i][j].y * nlt[c + 1];
            if (v0 > best) { best = v0; bi = c; }
            if (v1 > best) { best = v1; bi = c + 1; }
        }
        redv[r][tx] = best;
        redi[r][tx] = bi;
    }
    __syncthreads();
    if (tid < 128) {
        float best = redv[tid][0];
        int bi = redi[tid][0];
#pragma unroll
        for (int t = 1; t < 16; t++) {
            float v = redv[tid][t];
            int ii = redi[tid][t];
            if (v > best || (v == best && ii < bi)) { best = v; bi = ii; }
        }
        g_pos[b * LL + tid] = bi;
    }
}

// ================= elementwise mp match (used for attentive + max-attentive) =================
// mode 0: X = g_att_lt row l, Y = reps_rt row l            -> cols [41,62)
// mode 1: X = reps_rt row l, Y = reps_lt row g_pos[b,l]     -> cols [62,83)
__global__ __launch_bounds__(128) void mp_elem_kernel(
        const float* __restrict__ reps_lt, const float* __restrict__ reps_rt,
        const float* __restrict__ w, float* __restrict__ out,
        int mode, int col_base) {
    __shared__ float wsT[DD][MPP];  // transposed for f32x2 over m
    int b = blockIdx.x, tid = threadIdx.x;
    for (int i = tid; i < DD * MPP; i += 128) {
        int d = i / MPP, m = i - d * MPP;
        wsT[d][m] = w[m * DD + d];
    }
    __syncthreads();
    int l = tid;
    const float4* xr;
    const float4* yr;
    if (mode == 0) {
        xr = (const float4*)(g_att_lt + (size_t)(b * LL + l) * DD);
        yr = (const float4*)(reps_rt + (size_t)(b * LL + l) * DD);
    } else {
        xr = (const float4*)(reps_rt + (size_t)(b * LL + l) * DD);
        int yl = g_pos[b * LL + l];
        yr = (const float4*)(reps_lt + (size_t)(b * LL + yl) * DD);
    }
    float cos_acc = 0.f;
    float2 macc[MPP / 2];
#pragma unroll
    for (int mm = 0; mm < MPP / 2; mm++) macc[mm] = make_float2(0.f, 0.f);
    for (int d4 = 0; d4 < DD / 4; d4++) {
        float4 x = __ldg(xr + d4);
        float4 y = __ldg(yr + d4);
        float p[4] = {x.x * y.x, x.y * y.y, x.z * y.z, x.w * y.w};
#pragma unroll
        for (int c = 0; c < 4; c++) {
            cos_acc += p[c];
            const float2* wr = (const float2*)&wsT[d4 * 4 + c][0];
            float2 p2 = make_float2(p[c], p[c]);
#pragma unroll
            for (int mm = 0; mm < MPP / 2; mm++) macc[mm] = ffma2(p2, wr[mm], macc[mm]);
        }
    }
    float* o = out + (size_t)(b * LL + l) * OC + col_base;
    o[0] = tanhf(cos_acc);
#pragma unroll
    for (int mm = 0; mm < MPP / 2; mm++) {
        o[1 + 2 * mm] = tanhf(macc[mm].x);
        o[2 + 2 * mm] = tanhf(macc[mm].y);
    }
}

// ================= launch =================
extern "C" void kernel_launch(void* const* d_in, const int* in_sizes, int n_in,
                              void* d_out, int out_size) {
    const float* reps_lt = (const float*)d_in[0];
    const float* reps_rt = (const float*)d_in[1];
    const float* fw_h = (const float*)d_in[2];
    const float* bw_h = (const float*)d_in[3];
    const float* w_full = (const float*)d_in[4];
    const float* w_maxpool = (const float*)d_in[5];
    const float* w_att = (const float*)d_in[6];
    const float* w_maxatt = (const float*)d_in[7];
    const float* attn_w1 = (const float*)d_in[8];
    const float* attn_w2 = (const float*)d_in[9];
    const float* diag_w = (const float*)d_in[10];
    float* out = (float*)d_out;

    int proj_smem = (2 * DD * ATTN + 64) * 4;                 // ~80.3 KB
    int attn_smem = (128 * 129 + LL * ATTN + ATTN * LL) * 4;  // ~117.2 KB
    cudaFuncSetAttribute(proj_kernel, cudaFuncAttributeMaxDynamicSharedMemorySize, proj_smem);
    cudaFuncSetAttribute(attn_kernel, cudaFuncAttributeMaxDynamicSharedMemorySize, attn_smem);

    full_kernel<<<BB, 128>>>(reps_lt, fw_h, bw_h, w_full, out);
    maxpool_kernel<<<dim3(BB, MPP), 256>>>(reps_lt, reps_rt, w_maxpool, out);
    proj_kernel<<<BB, 256, proj_smem>>>(reps_lt, reps_rt, attn_w1, attn_w2, diag_w);
    attn_kernel<<<BB, 256, attn_smem>>>(reps_lt);
    maxatt_kernel<<<BB, 256>>>(reps_lt, reps_rt);
    mp_elem_kernel<<<BB, 128>>>(reps_lt, reps_rt, w_att, out, 0, 41);
    mp_elem_kernel<<<BB, 128>>>(reps_lt, reps_rt, w_maxatt, out, 1, 62);
}

// round 3
// speedup vs baseline: 1.3062x; 1.3062x over previous
#include <cuda_runtime.h>
#include <math.h>

#define BB 64
#define LL 128
#define DD 200
#define MPP 20
#define ATTN 50
#define OC 83

typedef unsigned long long ull;

// ---------------- scratch (no cudaMalloc allowed) ----------------
__device__ __align__(16) float g_e_rt[BB * LL * ATTN];
__device__ __align__(16) float g_e_lt[BB * LL * ATTN];
__device__ __align__(16) float g_att_lt[BB * LL * DD];
__device__ int g_pos[BB * LL];

// -------- packed fp32x2 helpers (clean "l"-constraint codegen) --------
__device__ __forceinline__ ull ffma2u(ull a, ull b, ull c) {
    ull d;
    asm("fma.rn.f32x2 %0, %1, %2, %3;" : "=l"(d) : "l"(a), "l"(b), "l"(c));
    return d;
}
__device__ __forceinline__ ull bcast2(float x) {
    ull r;
    asm("mov.b64 %0, {%1, %1};" : "=l"(r) : "f"(x));
    return r;
}
__device__ __forceinline__ float2 unpack2(ull v) {
    float2 f;
    asm("mov.b64 {%0, %1}, %2;" : "=f"(f.x), "=f"(f.y) : "l"(v));
    return f;
}

// ================= branch: maxpool (cols [21,41)) =================
// S = (lt .* w_m) @ rt^T [128x128,K=200], rowwise max over k, tanh (monotone).
__device__ __forceinline__ void maxpool_block(
        const float* __restrict__ lt, const float* __restrict__ rt,
        const float* __restrict__ w, float* __restrict__ out,
        int b, int m, float* sm) {
    float* As = sm;          // [8][128]
    float* Bs = sm + 1024;   // [8][128]
    float* red = sm + 2048;  // [128][16]
    int tid = threadIdx.x;
    int tx = tid & 15, ty = tid >> 4;
    int lrow = tid >> 1, kq = tid & 1;
    const float4* ltp = (const float4*)(lt + (size_t)(b * LL + lrow) * DD);
    const float4* rtp = (const float4*)(rt + (size_t)(b * LL + lrow) * DD);
    const float4* wp = (const float4*)(w + (size_t)m * DD);
    ull acc[8][4];
#pragma unroll
    for (int i = 0; i < 8; i++)
#pragma unroll
        for (int j = 0; j < 4; j++) acc[i][j] = 0ULL;

    for (int kc = 0; kc < DD / 8; kc++) {
        float4 av = __ldg(ltp + kc * 2 + kq);
        float4 wv = __ldg(wp + kc * 2 + kq);
        float4 bv = __ldg(rtp + kc * 2 + kq);
        int kb = kq * 4;
        As[(kb + 0) * 128 + lrow] = av.x * wv.x;
        As[(kb + 1) * 128 + lrow] = av.y * wv.y;
        As[(kb + 2) * 128 + lrow] = av.z * wv.z;
        As[(kb + 3) * 128 + lrow] = av.w * wv.w;
        Bs[(kb + 0) * 128 + lrow] = bv.x;
        Bs[(kb + 1) * 128 + lrow] = bv.y;
        Bs[(kb + 2) * 128 + lrow] = bv.z;
        Bs[(kb + 3) * 128 + lrow] = bv.w;
        __syncthreads();
#pragma unroll
        for (int k = 0; k < 8; k++) {
            ull a[8];
#pragma unroll
            for (int i = 0; i < 8; i++) a[i] = bcast2(As[k * 128 + ty + 16 * i]);
#pragma unroll
            for (int j = 0; j < 4; j++) {
                ull bb = *(const ull*)&Bs[k * 128 + 2 * tx + 32 * j];
#pragma unroll
                for (int i = 0; i < 8; i++) acc[i][j] = ffma2u(a[i], bb, acc[i][j]);
            }
        }
        __syncthreads();
    }
#pragma unroll
    for (int i = 0; i < 8; i++) {
        float mx = -3.4e38f;
#pragma unroll
        for (int j = 0; j < 4; j++) {
            float2 f = unpack2(acc[i][j]);
            mx = fmaxf(mx, fmaxf(f.x, f.y));
        }
        red[(ty + 16 * i) * 16 + tx] = mx;
    }
    __syncthreads();
    if (tid < 128) {
        float mx = red[tid * 16];
#pragma unroll
        for (int t = 1; t < 16; t++) mx = fmaxf(mx, red[tid * 16 + t]);
        out[(size_t)(b * LL + tid) * OC + 21 + m] = tanhf(mx);
    }
}

// ================= branch: full match (cols [0,21)) =================
__device__ __forceinline__ void full_block(
        const float* __restrict__ lt, const float* __restrict__ fw,
        const float* __restrict__ bw, const float* __restrict__ wf,
        float* __restrict__ out, int b, float* sm) {
    float* hw = sm;  // [21][200]
    int tid = threadIdx.x;
    for (int idx = tid; idx < (MPP + 1) * DD; idx += 256) {
        int mm = idx / DD, d = idx - mm * DD;
        float hv = (d < DD / 2) ? fw[b * (DD / 2) + d] : bw[b * (DD / 2) + d - DD / 2];
        hw[idx] = (mm == 0) ? hv : wf[(mm - 1) * DD + d] * hv;
    }
    __syncthreads();
    if (tid < 128) {
        const ull* row = (const ull*)(lt + (size_t)(b * LL + tid) * DD);
        ull acc[MPP + 1];
#pragma unroll
        for (int mm = 0; mm <= MPP; mm++) acc[mm] = 0ULL;
        for (int d2 = 0; d2 < DD / 2; d2++) {
            ull x = __ldg(row + d2);
#pragma unroll
            for (int mm = 0; mm <= MPP; mm++)
                acc[mm] = ffma2u(x, *(const ull*)&hw[mm * DD + 2 * d2], acc[mm]);
        }
        float* o = out + (size_t)(b * LL + tid) * OC;
#pragma unroll
        for (int mm = 0; mm <= MPP; mm++) {
            float2 f = unpack2(acc[mm]);
            o[mm] = tanhf(f.x + f.y);
        }
    }
}

// ================= branch: attention projection (one side per CTA) =================
// side 0: rt -> w1, *diag -> g_e_rt ; side 1: lt -> w2 -> g_e_lt
__device__ __forceinline__ void proj_block(
        const float* __restrict__ lt, const float* __restrict__ rt,
        const float* __restrict__ w1, const float* __restrict__ w2,
        const float* __restrict__ diag, int b, int side, float* sm) {
    float* ws = sm;            // [200][50]
    float* pbuf = sm + 10000;  // [50][128]
    int tid = threadIdx.x;
    const float* wsrc = side == 0 ? w1 : w2;
    for (int i = tid; i < DD * ATTN; i += 256) ws[i] = wsrc[i];
    __syncthreads();
    int l = tid & 127, dh = tid >> 7;
    const float* base = side == 0 ? rt : lt;
    const float4* row = (const float4*)(base + (size_t)(b * LL + l) * DD + dh * 100);
    ull acc[ATTN / 2];
#pragma unroll
    for (int a = 0; a < ATTN / 2; a++) acc[a] = 0ULL;
    for (int d4 = 0; d4 < 25; d4++) {
        float4 x = __ldg(row + d4);
        int d = dh * 100 + d4 * 4;
#pragma unroll
        for (int c = 0; c < 4; c++) {
            float xc = (c == 0) ? x.x : (c == 1) ? x.y : (c == 2) ? x.z : x.w;
            ull x2 = bcast2(xc);
            const ull* wr = (const ull*)&ws[(d + c) * ATTN];
#pragma unroll
            for (int a = 0; a < ATTN / 2; a++) acc[a] = ffma2u(x2, wr[a], acc[a]);
        }
    }
    if (dh == 1) {
#pragma unroll
        for (int a = 0; a < ATTN / 2; a++) {
            float2 f = unpack2(acc[a]);
            pbuf[(2 * a) * 128 + l] = f.x;
            pbuf[(2 * a + 1) * 128 + l] = f.y;
        }
    }
    __syncthreads();
    if (dh == 0) {
        float* e = (side == 0 ? g_e_rt : g_e_lt) + (size_t)(b * LL + l) * ATTN;
#pragma unroll
        for (int a = 0; a < ATTN / 2; a++) {
            float2 f = unpack2(acc[a]);
            float v0 = tanhf(f.x + pbuf[(2 * a) * 128 + l]);
            float v1 = tanhf(f.y + pbuf[(2 * a + 1) * 128 + l]);
            if (side == 0) {
                v0 *= __ldg(diag + 2 * a);
                v1 *= __ldg(diag + 2 * a + 1);
            }
            e[2 * a] = v0;
            e[2 * a + 1] = v1;
        }
    }
}

// ================= branch: max-attentive argmax (64 rows per CTA) =================
__device__ __forceinline__ void maxatt_block(
        const float* __restrict__ lt, const float* __restrict__ rt,
        int b, int rh, float* sm) {
    float* As = sm;           // [8][64]
    float* Bs = sm + 512;     // [8][128]
    float* nlt = sm + 1536;   // [128]
    float* redv = sm + 1664;  // [64][16]
    int* redi = (int*)(sm + 2688);  // [64][16]
    int tid = threadIdx.x;
    int tx = tid & 15, ty = tid >> 4;
    if (tid < 128) {
        const float4* p = (const float4*)(lt + (size_t)(b * LL + tid) * DD);
        float s = 0.f;
        for (int i = 0; i < DD / 4; i++) {
            float4 v = __ldg(p + i);
            s += v.x * v.x + v.y * v.y + v.z * v.z + v.w * v.w;
        }
        nlt[tid] = rsqrtf(fmaxf(s, 1e-6f));
    }
    int lrow = tid >> 1, kq = tid & 1;
    int arow = (tid >> 1) & 63;
    const float4* bp = (const float4*)(lt + (size_t)(b * LL + lrow) * DD);
    const float4* ap = (const float4*)(rt + (size_t)(b * LL + rh * 64 + arow) * DD);
    ull acc[4][4];
#pragma unroll
    for (int i = 0; i < 4; i++)
#pragma unroll
        for (int j = 0; j < 4; j++) acc[i][j] = 0ULL;
    for (int kc = 0; kc < DD / 8; kc++) {
        float4 bv = __ldg(bp + kc * 2 + kq);
        int kb = kq * 4;
        Bs[(kb + 0) * 128 + lrow] = bv.x;
        Bs[(kb + 1) * 128 + lrow] = bv.y;
        Bs[(kb + 2) * 128 + lrow] = bv.z;
        Bs[(kb + 3) * 128 + lrow] = bv.w;
        if (tid < 128) {
            float4 av = __ldg(ap + kc * 2 + kq);
            As[(kb + 0) * 64 + arow] = av.x;
            As[(kb + 1) * 64 + arow] = av.y;
            As[(kb + 2) * 64 + arow] = av.z;
            As[(kb + 3) * 64 + arow] = av.w;
        }
        __syncthreads();
#pragma unroll
        for (int k = 0; k < 8; k++) {
            ull a[4];
#pragma unroll
            for (int i = 0; i < 4; i++) a[i] = bcast2(As[k * 64 + ty + 16 * i]);
#pragma unroll
            for (int j = 0; j < 4; j++) {
                ull bb = *(const ull*)&Bs[k * 128 + 2 * tx + 32 * j];
#pragma unroll
                for (int i = 0; i < 4; i++) acc[i][j] = ffma2u(a[i], bb, acc[i][j]);
            }
        }
        __syncthreads();
    }
#pragma unroll
    for (int i = 0; i < 4; i++) {
        int r = ty + 16 * i;
        float best = -3.4e38f;
        int bi = 0;
#pragma unroll
        for (int j = 0; j < 4; j++) {
            int c = 2 * tx + 32 * j;
            float2 f = unpack2(acc[i][j]);
            float v0 = f.x * nlt[c];
            float v1 = f.y * nlt[c + 1];
            if (v0 > best) { best = v0; bi = c; }
            if (v1 > best) { best = v1; bi = c + 1; }
        }
        redv[r * 16 + tx] = best;
        redi[r * 16 + tx] = bi;
    }
    __syncthreads();
    if (tid < 64) {
        float best = redv[tid * 16];
        int bi = redi[tid * 16];
#pragma unroll
        for (int t = 1; t < 16; t++) {
            float v = redv[tid * 16 + t];
            int ii = redi[tid * 16 + t];
            if (v > best || (v == best && ii < bi)) { best = v; bi = ii; }
        }
        g_pos[b * LL + rh * 64 + tid] = bi;
    }
}

// ================= kernel A: all independent work =================
#define GRID_MAXPOOL (BB * MPP)
#define GRID_A (GRID_MAXPOOL + BB + 2 * BB + 2 * BB)
#define SMEM_A 66048

__global__ __launch_bounds__(256, 2) void kernelA(
        const float* __restrict__ lt, const float* __restrict__ rt,
        const float* __restrict__ fw, const float* __restrict__ bw,
        const float* __restrict__ w_full, const float* __restrict__ w_maxpool,
        const float* __restrict__ w1, const float* __restrict__ w2,
        const float* __restrict__ diag, float* __restrict__ out) {
    extern __shared__ float sm[];
    int bx = blockIdx.x;
    if (bx < GRID_MAXPOOL) {
        maxpool_block(lt, rt, w_maxpool, out, bx & 63, bx >> 6, sm);
    } else if (bx < GRID_MAXPOOL + BB) {
        full_block(lt, fw, bw, w_full, out, bx - GRID_MAXPOOL, sm);
    } else if (bx < GRID_MAXPOOL + BB + 2 * BB) {
        int i = bx - GRID_MAXPOOL - BB;
        proj_block(lt, rt, w1, w2, diag, i >> 1, i & 1, sm);
    } else {
        int i = bx - GRID_MAXPOOL - BB - 2 * BB;
        maxatt_block(lt, rt, i >> 1, i & 1, sm);
    }
}

// ================= kernel B: attentive match (logits+softmax+att_lt) =================
// grid (b, rhalf); smem: Z[64*129] | ers[64*50] | eltsT[50*128] | lts[128*200+64]
#define SMEM_B ((64 * 129 + 64 * 50 + 50 * 128 + 128 * 200 + 64) * 4)

__global__ __launch_bounds__(256) void kernelB(const float* __restrict__ lt) {
    extern __shared__ float sm[];
    float* Z = sm;                    // 8256
    float* ers = Z + 64 * 129;        // 3200
    float* eltsT = ers + 64 * 50;     // 6400
    float* lts = eltsT + 50 * 128;    // 25664
    int b = blockIdx.x, rh = blockIdx.y;
    int tid = threadIdx.x, tx = tid & 15, ty = tid >> 4;

    for (int i = tid; i < 64 * ATTN; i += 256)
        ers[i] = g_e_rt[((size_t)b * LL + rh * 64) * ATTN + i];
    for (int i = tid; i < LL * ATTN; i += 256) {
        int l = i / ATTN, a = i - l * ATTN;
        eltsT[a * LL + l] = g_e_lt[(size_t)b * LL * ATTN + i];
    }
    {
        const float4* src = (const float4*)(lt + (size_t)b * LL * DD);
        float4* dst = (float4*)lts;
        for (int i = tid; i < LL * DD / 4; i += 256) dst[i] = __ldg(src + i);
    }
    __syncthreads();

    // phase 1: Z[r][c] = sum_a ers[r][a] * e_lt[c][a]
    {
        ull acc[4][4];
#pragma unroll
        for (int i = 0; i < 4; i++)
#pragma unroll
            for (int j = 0; j < 4; j++) acc[i][j] = 0ULL;
        for (int k = 0; k < ATTN; k++) {
            ull a[4];
#pragma unroll
            for (int i = 0; i < 4; i++) a[i] = bcast2(ers[(ty + 16 * i) * ATTN + k]);
#pragma unroll
            for (int j = 0; j < 4; j++) {
                ull bb = *(const ull*)&eltsT[k * LL + 2 * tx + 32 * j];
#pragma unroll
                for (int i = 0; i < 4; i++) acc[i][j] = ffma2u(a[i], bb, acc[i][j]);
            }
        }
#pragma unroll
        for (int i = 0; i < 4; i++)
#pragma unroll
            for (int j = 0; j < 4; j++) {
                int r = ty + 16 * i, c = 2 * tx + 32 * j;
                float2 f = unpack2(acc[i][j]);
                Z[r * 129 + c] = f.x;
                Z[r * 129 + c + 1] = f.y;
            }
    }
    __syncthreads();

    if (tid < 64) {
        float* zr = Z + tid * 129;
        float mx = zr[0];
        for (int k = 1; k < 128; k++) mx = fmaxf(mx, zr[k]);
        float s = 0.f;
        for (int k = 0; k < 128; k++) {
            float e = expf(zr[k] - mx);
            zr[k] = e;
            s += e;
        }
        float inv = 1.f / s;
        for (int k = 0; k < 128; k++) zr[k] *= inv;
    }
    __syncthreads();

    // phase 2: att_lt[r][d] = sum_ll Z[r][ll] * lt[ll][d]
    for (int nb = 0; nb < 2; nb++) {
        ull acc[4][4];
#pragma unroll
        for (int i = 0; i < 4; i++)
#pragma unroll
            for (int j = 0; j < 4; j++) acc[i][j] = 0ULL;
        for (int k = 0; k < 128; k++) {
            ull a[4];
#pragma unroll
            for (int i = 0; i < 4; i++) a[i] = bcast2(Z[(ty + 16 * i) * 129 + k]);
#pragma unroll
            for (int j = 0; j < 4; j++) {
                ull bb = *(const ull*)&lts[k * DD + nb * 128 + 2 * tx + 32 * j];
#pragma unroll
                for (int i = 0; i < 4; i++) acc[i][j] = ffma2u(a[i], bb, acc[i][j]);
            }
        }
#pragma unroll
        for (int i = 0; i < 4; i++)
#pragma unroll
            for (int j = 0; j < 4; j++) {
                int r = rh * 64 + ty + 16 * i;
                int d = nb * 128 + 2 * tx + 32 * j;
                if (d < DD - 1) {
                    float2 f = unpack2(acc[i][j]);
                    *(float2*)(g_att_lt + (size_t)(b * LL + r) * DD + d) = f;
                }
            }
    }
}

// ================= kernel C: elementwise mp match (both modes) =================
__global__ __launch_bounds__(128) void kernelC(
        const float* __restrict__ reps_lt, const float* __restrict__ reps_rt,
        const float* __restrict__ w_att, const float* __restrict__ w_maxatt,
        float* __restrict__ out) {
    __shared__ float wsT[DD * MPP];  // [d][m]
    int b = blockIdx.x, mode = blockIdx.y, tid = threadIdx.x;
    const float* w = mode ? w_maxatt : w_att;
    for (int i = tid; i < DD * MPP; i += 128) {
        int d = i / MPP, m = i - d * MPP;
        wsT[d * MPP + m] = w[m * DD + d];
    }
    __syncthreads();
    const float4* xr;
    const float4* yr;
    if (mode == 0) {
        xr = (const float4*)(g_att_lt + (size_t)(b * LL + tid) * DD);
        yr = (const float4*)(reps_rt + (size_t)(b * LL + tid) * DD);
    } else {
        xr = (const float4*)(reps_rt + (size_t)(b * LL + tid) * DD);
        int yl = g_pos[b * LL + tid];
        yr = (const float4*)(reps_lt + (size_t)(b * LL + yl) * DD);
    }
    float cos_acc = 0.f;
    ull macc[MPP / 2];
#pragma unroll
    for (int mm = 0; mm < MPP / 2; mm++) macc[mm] = 0ULL;
    for (int d4 = 0; d4 < DD / 4; d4++) {
        float4 x = __ldg(xr + d4);
        float4 y = __ldg(yr + d4);
        float p[4] = {x.x * y.x, x.y * y.y, x.z * y.z, x.w * y.w};
#pragma unroll
        for (int c = 0; c < 4; c++) {
            cos_acc += p[c];
            ull p2 = bcast2(p[c]);
            const ull* wr = (const ull*)&wsT[(d4 * 4 + c) * MPP];
#pragma unroll
            for (int mm = 0; mm < MPP / 2; mm++) macc[mm] = ffma2u(p2, wr[mm], macc[mm]);
        }
    }
    float* o = out + (size_t)(b * LL + tid) * OC + (mode ? 62 : 41);
    o[0] = tanhf(cos_acc);
#pragma unroll
    for (int mm = 0; mm < MPP / 2; mm++) {
        float2 f = unpack2(macc[mm]);
        o[1 + 2 * mm] = tanhf(f.x);
        o[2 + 2 * mm] = tanhf(f.y);
    }
}

// ================= launch =================
extern "C" void kernel_launch(void* const* d_in, const int* in_sizes, int n_in,
                              void* d_out, int out_size) {
    const float* reps_lt = (const float*)d_in[0];
    const float* reps_rt = (const float*)d_in[1];
    const float* fw_h = (const float*)d_in[2];
    const float* bw_h = (const float*)d_in[3];
    const float* w_full = (const float*)d_in[4];
    const float* w_maxpool = (const float*)d_in[5];
    const float* w_att = (const float*)d_in[6];
    const float* w_maxatt = (const float*)d_in[7];
    const float* attn_w1 = (const float*)d_in[8];
    const float* attn_w2 = (const float*)d_in[9];
    const float* diag_w = (const float*)d_in[10];
    float* out = (float*)d_out;

    cudaFuncSetAttribute(kernelA, cudaFuncAttributeMaxDynamicSharedMemorySize, SMEM_A);
    cudaFuncSetAttribute(kernelB, cudaFuncAttributeMaxDynamicSharedMemorySize, SMEM_B);

    kernelA<<<GRID_A, 256, SMEM_A>>>(reps_lt, reps_rt, fw_h, bw_h, w_full,
                                     w_maxpool, attn_w1, attn_w2, diag_w, out);
    kernelB<<<dim3(BB, 2), 256, SMEM_B>>>(reps_lt);
    kernelC<<<dim3(BB, 2), 128>>>(reps_lt, reps_rt, w_att, w_maxatt, out);
}

// round 5
// speedup vs baseline: 1.7805x; 1.3631x over previous
#include <cuda_runtime.h>
#include <cuda_bf16.h>
#include <math.h>
#include <stdint.h>

#define BB 64
#define LL 128
#define DD 200
#define MPP 20
#define ATTN 50
#define OC 83

typedef unsigned long long ull;

// ---------------- scratch (no cudaMalloc allowed) ----------------
__device__ __align__(16) float g_e_rt[BB * LL * ATTN];
__device__ __align__(16) float g_e_lt[BB * LL * ATTN];
__device__ __align__(16) float g_att_lt[BB * LL * DD];
__device__ int g_pos[BB * LL];

// -------- packed fp32x2 helpers --------
__device__ __forceinline__ ull ffma2u(ull a, ull b, ull c) {
    ull d;
    asm("fma.rn.f32x2 %0, %1, %2, %3;" : "=l"(d) : "l"(a), "l"(b), "l"(c));
    return d;
}
__device__ __forceinline__ ull bcast2(float x) {
    ull r;
    asm("mov.b64 %0, {%1, %1};" : "=l"(r) : "f"(x));
    return r;
}
__device__ __forceinline__ float2 unpack2(ull v) {
    float2 f;
    asm("mov.b64 {%0, %1}, %2;" : "=f"(f.x), "=f"(f.y) : "l"(v));
    return f;
}

// -------- warp MMA helpers (baseline PTX, works on plain sm_103 target) -----
__device__ __forceinline__ uint32_t smem_to_u32(const void* p) {
    uint32_t a;
    asm("{ .reg .u64 t; cvta.to.shared.u64 t, %1; cvt.u32.u64 %0, t; }" : "=r"(a) : "l"(p));
    return a;
}
__device__ __forceinline__ void ldsm_x4(uint32_t* r, uint32_t addr) {
    asm volatile("ldmatrix.sync.aligned.m8n8.x4.shared.b16 {%0,%1,%2,%3}, [%4];"
                 : "=r"(r[0]), "=r"(r[1]), "=r"(r[2]), "=r"(r[3]) : "r"(addr));
}
__device__ __forceinline__ void mma16816(float* c, const uint32_t* a, const uint32_t* b) {
    asm volatile(
        "mma.sync.aligned.m16n8k16.row.col.f32.bf16.bf16.f32 "
        "{%0,%1,%2,%3}, {%4,%5,%6,%7}, {%8,%9}, {%0,%1,%2,%3};"
        : "+f"(c[0]), "+f"(c[1]), "+f"(c[2]), "+f"(c[3])
        : "r"(a[0]), "r"(a[1]), "r"(a[2]), "r"(a[3]), "r"(b[0]), "r"(b[1]));
}

// ======================================================================
// maxpool via mma.sync bf16x3 split:
// S_m = lt @ (w_m .* rt)^T  [128x128, K=200->208], rowmax, tanh -> out col 21+m
// CTA = (b, m), 256 threads (8 warps, 4x2 warp grid).
// smem tiles bf16 stride 216 (432B rows: conflict-free ldmatrix, 16B aligned)
// ======================================================================
#define STRD 216
#define TILE_B (LL * STRD * 2)          // 55296 bytes per tile
#define OFF_AH 0
#define OFF_AL (TILE_B)
#define OFF_BH (2 * TILE_B)
#define OFF_BL (3 * TILE_B)
#define SMEM_MP (4 * TILE_B)            // 221184

__device__ __forceinline__ void split2(float2 x, uint32_t& hi, uint32_t& lo) {
    __nv_bfloat162 h2 = __float22bfloat162_rn(x);
    float2 hf = __bfloat1622float2(h2);
    __nv_bfloat162 l2 = __float22bfloat162_rn(make_float2(x.x - hf.x, x.y - hf.y));
    hi = *(uint32_t*)&h2;
    lo = *(uint32_t*)&l2;
}

__global__ __launch_bounds__(256, 1) void maxpool_mma(
        const float* __restrict__ lt, const float* __restrict__ rt,
        const float* __restrict__ w, float* __restrict__ out) {
    extern __shared__ char smc[];
    __shared__ float red[128][2];
    uint32_t sbase = smem_to_u32(smc);
    int tid = threadIdx.x, lane = tid & 31, wid = tid >> 5;
    int b = blockIdx.x, m = blockIdx.y;

    // zero pad cols [200,208) of all 4 tiles
    for (int i = tid; i < 128 * 4; i += 256) {
        int r = i >> 2, c = i & 3;
        int off = (r * STRD + 200 + 2 * c) * 2;
        *(uint32_t*)(smc + OFF_AH + off) = 0;
        *(uint32_t*)(smc + OFF_AL + off) = 0;
        *(uint32_t*)(smc + OFF_BH + off) = 0;
        *(uint32_t*)(smc + OFF_BL + off) = 0;
    }
    // convert A = lt (split) and B = w_m .* rt (split)
    const float* ltb = lt + (size_t)b * LL * DD;
    const float* rtb = rt + (size_t)b * LL * DD;
    const float* wm = w + (size_t)m * DD;
    for (int i = tid; i < LL * 100; i += 256) {
        int r = i / 100, kp = i - r * 100, k = kp * 2;
        int off = (r * STRD + k) * 2;
        uint32_t hi, lo;
        float2 xa = *(const float2*)(ltb + r * DD + k);
        split2(xa, hi, lo);
        *(uint32_t*)(smc + OFF_AH + off) = hi;
        *(uint32_t*)(smc + OFF_AL + off) = lo;
        float2 xb = *(const float2*)(rtb + r * DD + k);
        float2 ww = *(const float2*)(wm + k);
        xb.x *= ww.x;
        xb.y *= ww.y;
        split2(xb, hi, lo);
        *(uint32_t*)(smc + OFF_BH + off) = hi;
        *(uint32_t*)(smc + OFF_BL + off) = lo;
    }
    __syncthreads();

    int mbase = (wid >> 1) * 32, nbase = (wid & 1) * 64;
    // ldmatrix lane->address mapping
    int a_row = lane & 15;
    int a_col8 = (lane & 16) ? 8 : 0;
    int b_row = (lane & 7) + ((lane & 16) ? 8 : 0);
    int b_col8 = (lane & 8) ? 8 : 0;

    float acc[2][8][4];
#pragma unroll
    for (int mt = 0; mt < 2; mt++)
#pragma unroll
        for (int nt = 0; nt < 8; nt++)
#pragma unroll
            for (int q = 0; q < 4; q++) acc[mt][nt][q] = 0.f;

#pragma unroll 1
    for (int kg = 0; kg < 13; kg++) {
        int kc = kg * 16;
        uint32_t ah[2][4], al[2][4];
#pragma unroll
        for (int mt = 0; mt < 2; mt++) {
            uint32_t row = mbase + 16 * mt + a_row;
            uint32_t boff = (row * STRD + kc + a_col8) * 2;
            ldsm_x4(ah[mt], sbase + OFF_AH + boff);
            ldsm_x4(al[mt], sbase + OFF_AL + boff);
        }
#pragma unroll
        for (int np = 0; np < 4; np++) {
            uint32_t row = nbase + np * 16 + b_row;
            uint32_t boff = (row * STRD + kc + b_col8) * 2;
            uint32_t bh[4], bl[4];
            ldsm_x4(bh, sbase + OFF_BH + boff);
            ldsm_x4(bl, sbase + OFF_BL + boff);
#pragma unroll
            for (int mt = 0; mt < 2; mt++) {
                mma16816(acc[mt][2 * np], ah[mt], bh);
                mma16816(acc[mt][2 * np], ah[mt], bl);
                mma16816(acc[mt][2 * np], al[mt], bh);
                mma16816(acc[mt][2 * np + 1], ah[mt], bh + 2);
                mma16816(acc[mt][2 * np + 1], ah[mt], bl + 2);
                mma16816(acc[mt][2 * np + 1], al[mt], bh + 2);
            }
        }
    }

    // epilogue: rowmax over this warp's 64 cols, then cross-warp via smem
    int wn = wid & 1;
#pragma unroll
    for (int mt = 0; mt < 2; mt++) {
        float lo = -3.4e38f, hi = -3.4e38f;
#pragma unroll
        for (int nt = 0; nt < 8; nt++) {
            lo = fmaxf(lo, fmaxf(acc[mt][nt][0], acc[mt][nt][1]));
            hi = fmaxf(hi, fmaxf(acc[mt][nt][2], acc[mt][nt][3]));
        }
        lo = fmaxf(lo, __shfl_xor_sync(0xffffffffu, lo, 1));
        lo = fmaxf(lo, __shfl_xor_sync(0xffffffffu, lo, 2));
        hi = fmaxf(hi, __shfl_xor_sync(0xffffffffu, hi, 1));
        hi = fmaxf(hi, __shfl_xor_sync(0xffffffffu, hi, 2));
        if ((lane & 3) == 0) {
            int r = mbase + 16 * mt + (lane >> 2);
            red[r][wn] = lo;
            red[r + 8][wn] = hi;
        }
    }
    __syncthreads();
    if (tid < 128) {
        float v = fmaxf(red[tid][0], red[tid][1]);
        out[(size_t)(b * LL + tid) * OC + 21 + m] = tanhf(v);
    }
}

// ================= branch: full match (cols [0,21)) =================
__device__ __forceinline__ void full_block(
        const float* __restrict__ lt, const float* __restrict__ fw,
        const float* __restrict__ bw, const float* __restrict__ wf,
        float* __restrict__ out, int b, float* sm) {
    float* hw = sm;  // [21][200]
    int tid = threadIdx.x;
    for (int idx = tid; idx < (MPP + 1) * DD; idx += 256) {
        int mm = idx / DD, d = idx - mm * DD;
        float hv = (d < DD / 2) ? fw[b * (DD / 2) + d] : bw[b * (DD / 2) + d - DD / 2];
        hw[idx] = (mm == 0) ? hv : wf[(mm - 1) * DD + d] * hv;
    }
    __syncthreads();
    if (tid < 128) {
        const ull* row = (const ull*)(lt + (size_t)(b * LL + tid) * DD);
        ull acc[MPP + 1];
#pragma unroll
        for (int mm = 0; mm <= MPP; mm++) acc[mm] = 0ULL;
        for (int d2 = 0; d2 < DD / 2; d2++) {
            ull x = __ldg(row + d2);
#pragma unroll
            for (int mm = 0; mm <= MPP; mm++)
                acc[mm] = ffma2u(x, *(const ull*)&hw[mm * DD + 2 * d2], acc[mm]);
        }
        float* o = out + (size_t)(b * LL + tid) * OC;
#pragma unroll
        for (int mm = 0; mm <= MPP; mm++) {
            float2 f = unpack2(acc[mm]);
            o[mm] = tanhf(f.x + f.y);
        }
    }
}

// ================= branch: attention projection =================
__device__ __forceinline__ void proj_block(
        const float* __restrict__ lt, const float* __restrict__ rt,
        const float* __restrict__ w1, const float* __restrict__ w2,
        const float* __restrict__ diag, int b, int side, float* sm) {
    float* ws = sm;            // [200][50]
    float* pbuf = sm + 10000;  // [50][128]
    int tid = threadIdx.x;
    const float* wsrc = side == 0 ? w1 : w2;
    for (int i = tid; i < DD * ATTN; i += 256) ws[i] = wsrc[i];
    __syncthreads();
    int l = tid & 127, dh = tid >> 7;
    const float* base = side == 0 ? rt : lt;
    const float4* row = (const float4*)(base + (size_t)(b * LL + l) * DD + dh * 100);
    ull acc[ATTN / 2];
#pragma unroll
    for (int a = 0; a < ATTN / 2; a++) acc[a] = 0ULL;
    for (int d4 = 0; d4 < 25; d4++) {
        float4 x = __ldg(row + d4);
        int d = dh * 100 + d4 * 4;
#pragma unroll
        for (int c = 0; c < 4; c++) {
            float xc = (c == 0) ? x.x : (c == 1) ? x.y : (c == 2) ? x.z : x.w;
            ull x2 = bcast2(xc);
            const ull* wr = (const ull*)&ws[(d + c) * ATTN];
#pragma unroll
            for (int a = 0; a < ATTN / 2; a++) acc[a] = ffma2u(x2, wr[a], acc[a]);
        }
    }
    if (dh == 1) {
#pragma unroll
        for (int a = 0; a < ATTN / 2; a++) {
            float2 f = unpack2(acc[a]);
            pbuf[(2 * a) * 128 + l] = f.x;
            pbuf[(2 * a + 1) * 128 + l] = f.y;
        }
    }
    __syncthreads();
    if (dh == 0) {
        float* e = (side == 0 ? g_e_rt : g_e_lt) + (size_t)(b * LL + l) * ATTN;
#pragma unroll
        for (int a = 0; a < ATTN / 2; a++) {
            float2 f = unpack2(acc[a]);
            float v0 = tanhf(f.x + pbuf[(2 * a) * 128 + l]);
            float v1 = tanhf(f.y + pbuf[(2 * a + 1) * 128 + l]);
            if (side == 0) {
                v0 *= __ldg(diag + 2 * a);
                v1 *= __ldg(diag + 2 * a + 1);
            }
            e[2 * a] = v0;
            e[2 * a + 1] = v1;
        }
    }
}

// ================= branch: max-attentive argmax =================
__device__ __forceinline__ void maxatt_block(
        const float* __restrict__ lt, const float* __restrict__ rt,
        int b, int rh, float* sm) {
    float* As = sm;
    float* Bs = sm + 512;
    float* nlt = sm + 1536;
    float* redv = sm + 1664;
    int* redi = (int*)(sm + 2688);
    int tid = threadIdx.x;
    int tx = tid & 15, ty = tid >> 4;
    if (tid < 128) {
        const float4* p = (const float4*)(lt + (size_t)(b * LL + tid) * DD);
        float s = 0.f;
        for (int i = 0; i < DD / 4; i++) {
            float4 v = __ldg(p + i);
            s += v.x * v.x + v.y * v.y + v.z * v.z + v.w * v.w;
        }
        nlt[tid] = rsqrtf(fmaxf(s, 1e-6f));
    }
    int lrow = tid >> 1, kq = tid & 1;
    int arow = (tid >> 1) & 63;
    const float4* bp = (const float4*)(lt + (size_t)(b * LL + lrow) * DD);
    const float4* ap = (const float4*)(rt + (size_t)(b * LL + rh * 64 + arow) * DD);
    ull acc[4][4];
#pragma unroll
    for (int i = 0; i < 4; i++)
#pragma unroll
        for (int j = 0; j < 4; j++) acc[i][j] = 0ULL;
    for (int kc = 0; kc < DD / 8; kc++) {
        float4 bv = __ldg(bp + kc * 2 + kq);
        int kb = kq * 4;
        Bs[(kb + 0) * 128 + lrow] = bv.x;
        Bs[(kb + 1) * 128 + lrow] = bv.y;
        Bs[(kb + 2) * 128 + lrow] = bv.z;
        Bs[(kb + 3) * 128 + lrow] = bv.w;
        if (tid < 128) {
            float4 av = __ldg(ap + kc * 2 + kq);
            As[(kb + 0) * 64 + arow] = av.x;
            As[(kb + 1) * 64 + arow] = av.y;
            As[(kb + 2) * 64 + arow] = av.z;
            As[(kb + 3) * 64 + arow] = av.w;
        }
        __syncthreads();
#pragma unroll
        for (int k = 0; k < 8; k++) {
            ull a[4];
#pragma unroll
            for (int i = 0; i < 4; i++) a[i] = bcast2(As[k * 64 + ty + 16 * i]);
#pragma unroll
            for (int j = 0; j < 4; j++) {
                ull bb = *(const ull*)&Bs[k * 128 + 2 * tx + 32 * j];
#pragma unroll
                for (int i = 0; i < 4; i++) acc[i][j] = ffma2u(a[i], bb, acc[i][j]);
            }
        }
        __syncthreads();
    }
#pragma unroll
    for (int i = 0; i < 4; i++) {
        int r = ty + 16 * i;
        float best = -3.4e38f;
        int bi = 0;
#pragma unroll
        for (int j = 0; j < 4; j++) {
            int c = 2 * tx + 32 * j;
            float2 f = unpack2(acc[i][j]);
            float v0 = f.x * nlt[c];
            float v1 = f.y * nlt[c + 1];
            if (v0 > best) { best = v0; bi = c; }
            if (v1 > best) { best = v1; bi = c + 1; }
        }
        redv[r * 16 + tx] = best;
        redi[r * 16 + tx] = bi;
    }
    __syncthreads();
    if (tid < 64) {
        float best = redv[tid * 16];
        int bi = redi[tid * 16];
#pragma unroll
        for (int t = 1; t < 16; t++) {
            float v = redv[tid * 16 + t];
            int ii = redi[tid * 16 + t];
            if (v > best || (v == best && ii < bi)) { best = v; bi = ii; }
        }
        g_pos[b * LL + rh * 64 + tid] = bi;
    }
}

// ================= kernel A: small independent work =================
#define GRID_A (BB + 2 * BB + 2 * BB)
#define SMEM_A 66048

__global__ __launch_bounds__(256, 2) void kernelA(
        const float* __restrict__ lt, const float* __restrict__ rt,
        const float* __restrict__ fw, const float* __restrict__ bw,
        const float* __restrict__ w_full,
        const float* __restrict__ w1, const float* __restrict__ w2,
        const float* __restrict__ diag, float* __restrict__ out) {
    extern __shared__ float sm[];
    int bx = blockIdx.x;
    if (bx < BB) {
        full_block(lt, fw, bw, w_full, out, bx, sm);
    } else if (bx < BB + 2 * BB) {
        int i = bx - BB;
        proj_block(lt, rt, w1, w2, diag, i >> 1, i & 1, sm);
    } else {
        int i = bx - 3 * BB;
        maxatt_block(lt, rt, i >> 1, i & 1, sm);
    }
}

// ================= kernel B: attentive logits + softmax + att_lt =================
#define SMEM_B ((64 * 129 + 64 * 50 + 50 * 128 + 128 * 200 + 64) * 4)

__global__ __launch_bounds__(256) void kernelB(const float* __restrict__ lt) {
    extern __shared__ float sm[];
    float* Z = sm;
    float* ers = Z + 64 * 129;
    float* eltsT = ers + 64 * 50;
    float* lts = eltsT + 50 * 128;
    int b = blockIdx.x, rh = blockIdx.y;
    int tid = threadIdx.x, tx = tid & 15, ty = tid >> 4;

    for (int i = tid; i < 64 * ATTN; i += 256)
        ers[i] = g_e_rt[((size_t)b * LL + rh * 64) * ATTN + i];
    for (int i = tid; i < LL * ATTN; i += 256) {
        int l = i / ATTN, a = i - l * ATTN;
        eltsT[a * LL + l] = g_e_lt[(size_t)b * LL * ATTN + i];
    }
    {
        const float4* src = (const float4*)(lt + (size_t)b * LL * DD);
        float4* dst = (float4*)lts;
        for (int i = tid; i < LL * DD / 4; i += 256) dst[i] = __ldg(src + i);
    }
    __syncthreads();

    {
        ull acc[4][4];
#pragma unroll
        for (int i = 0; i < 4; i++)
#pragma unroll
            for (int j = 0; j < 4; j++) acc[i][j] = 0ULL;
        for (int k = 0; k < ATTN; k++) {
            ull a[4];
#pragma unroll
            for (int i = 0; i < 4; i++) a[i] = bcast2(ers[(ty + 16 * i) * ATTN + k]);
#pragma unroll
            for (int j = 0; j < 4; j++) {
                ull bb = *(const ull*)&eltsT[k * LL + 2 * tx + 32 * j];
#pragma unroll
                for (int i = 0; i < 4; i++) acc[i][j] = ffma2u(a[i], bb, acc[i][j]);
            }
        }
#pragma unroll
        for (int i = 0; i < 4; i++)
#pragma unroll
            for (int j = 0; j < 4; j++) {
                int r = ty + 16 * i, c = 2 * tx + 32 * j;
                float2 f = unpack2(acc[i][j]);
                Z[r * 129 + c] = f.x;
                Z[r * 129 + c + 1] = f.y;
            }
    }
    __syncthreads();

    if (tid < 64) {
        float* zr = Z + tid * 129;
        float mx = zr[0];
        for (int k = 1; k < 128; k++) mx = fmaxf(mx, zr[k]);
        float s = 0.f;
        for (int k = 0; k < 128; k++) {
            float e = expf(zr[k] - mx);
            zr[k] = e;
            s += e;
        }
        float inv = 1.f / s;
        for (int k = 0; k < 128; k++) zr[k] *= inv;
    }
    __syncthreads();

    for (int nb = 0; nb < 2; nb++) {
        ull acc[4][4];
#pragma unroll
        for (int i = 0; i < 4; i++)
#pragma unroll
            for (int j = 0; j < 4; j++) acc[i][j] = 0ULL;
        for (int k = 0; k < 128; k++) {
            ull a[4];
#pragma unroll
            for (int i = 0; i < 4; i++) a[i] = bcast2(Z[(ty + 16 * i) * 129 + k]);
#pragma unroll
            for (int j = 0; j < 4; j++) {
                ull bb = *(const ull*)&lts[k * DD + nb * 128 + 2 * tx + 32 * j];
#pragma unroll
                for (int i = 0; i < 4; i++) acc[i][j] = ffma2u(a[i], bb, acc[i][j]);
            }
        }
#pragma unroll
        for (int i = 0; i < 4; i++)
#pragma unroll
            for (int j = 0; j < 4; j++) {
                int r = rh * 64 + ty + 16 * i;
                int d = nb * 128 + 2 * tx + 32 * j;
                if (d < DD - 1) {
                    float2 f = unpack2(acc[i][j]);
                    *(float2*)(g_att_lt + (size_t)(b * LL + r) * DD + d) = f;
                }
            }
    }
}

// ================= kernel C: elementwise mp match (both modes) =================
__global__ __launch_bounds__(128) void kernelC(
        const float* __restrict__ reps_lt, const float* __restrict__ reps_rt,
        const float* __restrict__ w_att, const float* __restrict__ w_maxatt,
        float* __restrict__ out) {
    __shared__ float wsT[DD * MPP];
    int b = blockIdx.x, mode = blockIdx.y, tid = threadIdx.x;
    const float* w = mode ? w_maxatt : w_att;
    for (int i = tid; i < DD * MPP; i += 128) {
        int d = i / MPP, m = i - d * MPP;
        wsT[d * MPP + m] = w[m * DD + d];
    }
    __syncthreads();
    const float4* xr;
    const float4* yr;
    if (mode == 0) {
        xr = (const float4*)(g_att_lt + (size_t)(b * LL + tid) * DD);
        yr = (const float4*)(reps_rt + (size_t)(b * LL + tid) * DD);
    } else {
        xr = (const float4*)(reps_rt + (size_t)(b * LL + tid) * DD);
        int yl = g_pos[b * LL + tid];
        yr = (const float4*)(reps_lt + (size_t)(b * LL + yl) * DD);
    }
    float cos_acc = 0.f;
    ull macc[MPP / 2];
#pragma unroll
    for (int mm = 0; mm < MPP / 2; mm++) macc[mm] = 0ULL;
    for (int d4 = 0; d4 < DD / 4; d4++) {
        float4 x = __ldg(xr + d4);
        float4 y = __ldg(yr + d4);
        float p[4] = {x.x * y.x, x.y * y.y, x.z * y.z, x.w * y.w};
#pragma unroll
        for (int c = 0; c < 4; c++) {
            cos_acc += p[c];
            ull p2 = bcast2(p[c]);
            const ull* wr = (const ull*)&wsT[(d4 * 4 + c) * MPP];
#pragma unroll
            for (int mm = 0; mm < MPP / 2; mm++) macc[mm] = ffma2u(p2, wr[mm], macc[mm]);
        }
    }
    float* o = out + (size_t)(b * LL + tid) * OC + (mode ? 62 : 41);
    o[0] = tanhf(cos_acc);
#pragma unroll
    for (int mm = 0; mm < MPP / 2; mm++) {
        float2 f = unpack2(macc[mm]);
        o[1 + 2 * mm] = tanhf(f.x);
        o[2 + 2 * mm] = tanhf(f.y);
    }
}

// ================= launch =================
extern "C" void kernel_launch(void* const* d_in, const int* in_sizes, int n_in,
                              void* d_out, int out_size) {
    const float* reps_lt = (const float*)d_in[0];
    const float* reps_rt = (const float*)d_in[1];
    const float* fw_h = (const float*)d_in[2];
    const float* bw_h = (const float*)d_in[3];
    const float* w_full = (const float*)d_in[4];
    const float* w_maxpool = (const float*)d_in[5];
    const float* w_att = (const float*)d_in[6];
    const float* w_maxatt = (const float*)d_in[7];
    const float* attn_w1 = (const float*)d_in[8];
    const float* attn_w2 = (const float*)d_in[9];
    const float* diag_w = (const float*)d_in[10];
    float* out = (float*)d_out;

    cudaFuncSetAttribute(maxpool_mma, cudaFuncAttributeMaxDynamicSharedMemorySize, SMEM_MP);
    cudaFuncSetAttribute(kernelA, cudaFuncAttributeMaxDynamicSharedMemorySize, SMEM_A);
    cudaFuncSetAttribute(kernelB, cudaFuncAttributeMaxDynamicSharedMemorySize, SMEM_B);

    maxpool_mma<<<dim3(BB, MPP), 256, SMEM_MP>>>(reps_lt, reps_rt, w_maxpool, out);
    kernelA<<<GRID_A, 256, SMEM_A>>>(reps_lt, reps_rt, fw_h, bw_h, w_full,
                                     attn_w1, attn_w2, diag_w, out);
    kernelB<<<dim3(BB, 2), 256, SMEM_B>>>(reps_lt);
    kernelC<<<dim3(BB, 2), 128>>>(reps_lt, reps_rt, w_att, w_maxatt, out);
}

// round 6
// speedup vs baseline: 1.9084x; 1.0719x over previous
#include <cuda_runtime.h>
#include <cuda_bf16.h>
#include <math.h>
#include <stdint.h>

#define BB 64
#define LL 128
#define DD 200
#define MPP 20
#define ATTN 50
#define OC 83

typedef unsigned long long ull;

// ---------------- scratch (no cudaMalloc allowed) ----------------
__device__ __align__(16) float g_e_rt[BB * LL * ATTN];
__device__ __align__(16) float g_e_lt[BB * LL * ATTN];
__device__ __align__(16) float g_att_lt[BB * LL * DD];
__device__ int g_pos[BB * LL];

// -------- packed fp32x2 helpers --------
__device__ __forceinline__ ull ffma2u(ull a, ull b, ull c) {
    ull d;
    asm("fma.rn.f32x2 %0, %1, %2, %3;" : "=l"(d) : "l"(a), "l"(b), "l"(c));
    return d;
}
__device__ __forceinline__ ull addp2(ull a, ull b) {
    ull d;
    asm("add.rn.f32x2 %0, %1, %2;" : "=l"(d) : "l"(a), "l"(b));
    return d;
}
__device__ __forceinline__ ull bcast2(float x) {
    ull r;
    asm("mov.b64 %0, {%1, %1};" : "=l"(r) : "f"(x));
    return r;
}
__device__ __forceinline__ float2 unpack2(ull v) {
    float2 f;
    asm("mov.b64 {%0, %1}, %2;" : "=f"(f.x), "=f"(f.y) : "l"(v));
    return f;
}

// -------- warp MMA helpers (baseline PTX, works on plain sm_103 target) -----
__device__ __forceinline__ uint32_t smem_to_u32(const void* p) {
    uint32_t a;
    asm("{ .reg .u64 t; cvta.to.shared.u64 t, %1; cvt.u32.u64 %0, t; }" : "=r"(a) : "l"(p));
    return a;
}
__device__ __forceinline__ void ldsm_x4(uint32_t* r, uint32_t addr) {
    asm volatile("ldmatrix.sync.aligned.m8n8.x4.shared.b16 {%0,%1,%2,%3}, [%4];"
                 : "=r"(r[0]), "=r"(r[1]), "=r"(r[2]), "=r"(r[3]) : "r"(addr));
}
__device__ __forceinline__ void mma16816(float* c, const uint32_t* a, const uint32_t* b) {
    asm volatile(
        "mma.sync.aligned.m16n8k16.row.col.f32.bf16.bf16.f32 "
        "{%0,%1,%2,%3}, {%4,%5,%6,%7}, {%8,%9}, {%0,%1,%2,%3};"
        : "+f"(c[0]), "+f"(c[1]), "+f"(c[2]), "+f"(c[3])
        : "r"(a[0]), "r"(a[1]), "r"(a[2]), "r"(a[3]), "r"(b[0]), "r"(b[1]));
}

// ======================================================================
// maxpool branch: S_m = lt @ (w_m .* rt)^T [128x128, K=200->208], bf16x3
// smem tiles bf16 stride 216 (432B rows: conflict-free ldmatrix, 16B aligned)
// ======================================================================
#define STRD 216
#define TILE_B (LL * STRD * 2)          // 55296 bytes per tile
#define OFF_AH 0
#define OFF_AL (TILE_B)
#define OFF_BH (2 * TILE_B)
#define OFF_BL (3 * TILE_B)
#define SMEM_MP (4 * TILE_B)            // 221184

__device__ __forceinline__ void split2(float2 x, uint32_t& hi, uint32_t& lo) {
    __nv_bfloat162 h2 = __float22bfloat162_rn(x);
    float2 hf = __bfloat1622float2(h2);
    __nv_bfloat162 l2 = __float22bfloat162_rn(make_float2(x.x - hf.x, x.y - hf.y));
    hi = *(uint32_t*)&h2;
    lo = *(uint32_t*)&l2;
}

__device__ __forceinline__ void maxpool_block(
        const float* __restrict__ lt, const float* __restrict__ rt,
        const float* __restrict__ w, float* __restrict__ out,
        int b, int m, char* smc, float (*red)[2]) {
    uint32_t sbase = smem_to_u32(smc);
    int tid = threadIdx.x, lane = tid & 31, wid = tid >> 5;

    // zero pad cols [200,208) of all 4 tiles
    for (int i = tid; i < 128 * 4; i += 256) {
        int r = i >> 2, c = i & 3;
        int off = (r * STRD + 200 + 2 * c) * 2;
        *(uint32_t*)(smc + OFF_AH + off) = 0;
        *(uint32_t*)(smc + OFF_AL + off) = 0;
        *(uint32_t*)(smc + OFF_BH + off) = 0;
        *(uint32_t*)(smc + OFF_BL + off) = 0;
    }
    const float* ltb = lt + (size_t)b * LL * DD;
    const float* rtb = rt + (size_t)b * LL * DD;
    const float* wm = w + (size_t)m * DD;
    for (int i = tid; i < LL * 100; i += 256) {
        int r = i / 100, kp = i - r * 100, k = kp * 2;
        int off = (r * STRD + k) * 2;
        uint32_t hi, lo;
        float2 xa = *(const float2*)(ltb + r * DD + k);
        split2(xa, hi, lo);
        *(uint32_t*)(smc + OFF_AH + off) = hi;
        *(uint32_t*)(smc + OFF_AL + off) = lo;
        float2 xb = *(const float2*)(rtb + r * DD + k);
        float2 ww = *(const float2*)(wm + k);
        xb.x *= ww.x;
        xb.y *= ww.y;
        split2(xb, hi, lo);
        *(uint32_t*)(smc + OFF_BH + off) = hi;
        *(uint32_t*)(smc + OFF_BL + off) = lo;
    }
    __syncthreads();

    int mbase = (wid >> 1) * 32, nbase = (wid & 1) * 64;
    int a_row = lane & 15;
    int a_col8 = (lane & 16) ? 8 : 0;
    int b_row = (lane & 7) + ((lane & 16) ? 8 : 0);
    int b_col8 = (lane & 8) ? 8 : 0;

    float acc[2][8][4];
#pragma unroll
    for (int mt = 0; mt < 2; mt++)
#pragma unroll
        for (int nt = 0; nt < 8; nt++)
#pragma unroll
            for (int q = 0; q < 4; q++) acc[mt][nt][q] = 0.f;

#pragma unroll 1
    for (int kg = 0; kg < 13; kg++) {
        int kc = kg * 16;
        uint32_t ah[2][4], al[2][4];
#pragma unroll
        for (int mt = 0; mt < 2; mt++) {
            uint32_t row = mbase + 16 * mt + a_row;
            uint32_t boff = (row * STRD + kc + a_col8) * 2;
            ldsm_x4(ah[mt], sbase + OFF_AH + boff);
            ldsm_x4(al[mt], sbase + OFF_AL + boff);
        }
#pragma unroll
        for (int np = 0; np < 4; np++) {
            uint32_t row = nbase + np * 16 + b_row;
            uint32_t boff = (row * STRD + kc + b_col8) * 2;
            uint32_t bh[4], bl[4];
            ldsm_x4(bh, sbase + OFF_BH + boff);
            ldsm_x4(bl, sbase + OFF_BL + boff);
#pragma unroll
            for (int mt = 0; mt < 2; mt++) {
                mma16816(acc[mt][2 * np], ah[mt], bh);
                mma16816(acc[mt][2 * np], ah[mt], bl);
                mma16816(acc[mt][2 * np], al[mt], bh);
                mma16816(acc[mt][2 * np + 1], ah[mt], bh + 2);
                mma16816(acc[mt][2 * np + 1], ah[mt], bl + 2);
                mma16816(acc[mt][2 * np + 1], al[mt], bh + 2);
            }
        }
    }

    int wn = wid & 1;
#pragma unroll
    for (int mt = 0; mt < 2; mt++) {
        float lo = -3.4e38f, hi = -3.4e38f;
#pragma unroll
        for (int nt = 0; nt < 8; nt++) {
            lo = fmaxf(lo, fmaxf(acc[mt][nt][0], acc[mt][nt][1]));
            hi = fmaxf(hi, fmaxf(acc[mt][nt][2], acc[mt][nt][3]));
        }
        lo = fmaxf(lo, __shfl_xor_sync(0xffffffffu, lo, 1));
        lo = fmaxf(lo, __shfl_xor_sync(0xffffffffu, lo, 2));
        hi = fmaxf(hi, __shfl_xor_sync(0xffffffffu, hi, 1));
        hi = fmaxf(hi, __shfl_xor_sync(0xffffffffu, hi, 2));
        if ((lane & 3) == 0) {
            int r = mbase + 16 * mt + (lane >> 2);
            red[r][wn] = lo;
            red[r + 8][wn] = hi;
        }
    }
    __syncthreads();
    if (tid < 128) {
        float v = fmaxf(red[tid][0], red[tid][1]);
        out[(size_t)(b * LL + tid) * OC + 21 + m] = tanhf(v);
    }
}

// ================= branch: full match (cols [0,21)) =================
__device__ __forceinline__ void full_block(
        const float* __restrict__ lt, const float* __restrict__ fw,
        const float* __restrict__ bw, const float* __restrict__ wf,
        float* __restrict__ out, int b, float* sm) {
    float* hw = sm;  // [21][200]
    int tid = threadIdx.x;
    for (int idx = tid; idx < (MPP + 1) * DD; idx += 256) {
        int mm = idx / DD, d = idx - mm * DD;
        float hv = (d < DD / 2) ? fw[b * (DD / 2) + d] : bw[b * (DD / 2) + d - DD / 2];
        hw[idx] = (mm == 0) ? hv : wf[(mm - 1) * DD + d] * hv;
    }
    __syncthreads();
    if (tid < 128) {
        const ull* row = (const ull*)(lt + (size_t)(b * LL + tid) * DD);
        ull acc[MPP + 1];
#pragma unroll
        for (int mm = 0; mm <= MPP; mm++) acc[mm] = 0ULL;
        for (int d2 = 0; d2 < DD / 2; d2++) {
            ull x = __ldg(row + d2);
#pragma unroll
            for (int mm = 0; mm <= MPP; mm++)
                acc[mm] = ffma2u(x, *(const ull*)&hw[mm * DD + 2 * d2], acc[mm]);
        }
        float* o = out + (size_t)(b * LL + tid) * OC;
#pragma unroll
        for (int mm = 0; mm <= MPP; mm++) {
            float2 f = unpack2(acc[mm]);
            o[mm] = tanhf(f.x + f.y);
        }
    }
}

// ================= branch: attention projection =================
__device__ __forceinline__ void proj_block(
        const float* __restrict__ lt, const float* __restrict__ rt,
        const float* __restrict__ w1, const float* __restrict__ w2,
        const float* __restrict__ diag, int b, int side, float* sm) {
    float* ws = sm;            // [200][50]
    float* pbuf = sm + 10000;  // [50][128]
    int tid = threadIdx.x;
    const float* wsrc = side == 0 ? w1 : w2;
    for (int i = tid; i < DD * ATTN; i += 256) ws[i] = wsrc[i];
    __syncthreads();
    int l = tid & 127, dh = tid >> 7;
    const float* base = side == 0 ? rt : lt;
    const float4* row = (const float4*)(base + (size_t)(b * LL + l) * DD + dh * 100);
    ull acc[ATTN / 2];
#pragma unroll
    for (int a = 0; a < ATTN / 2; a++) acc[a] = 0ULL;
    for (int d4 = 0; d4 < 25; d4++) {
        float4 x = __ldg(row + d4);
        int d = dh * 100 + d4 * 4;
#pragma unroll
        for (int c = 0; c < 4; c++) {
            float xc = (c == 0) ? x.x : (c == 1) ? x.y : (c == 2) ? x.z : x.w;
            ull x2 = bcast2(xc);
            const ull* wr = (const ull*)&ws[(d + c) * ATTN];
#pragma unroll
            for (int a = 0; a < ATTN / 2; a++) acc[a] = ffma2u(x2, wr[a], acc[a]);
        }
    }
    if (dh == 1) {
#pragma unroll
        for (int a = 0; a < ATTN / 2; a++) {
            float2 f = unpack2(acc[a]);
            pbuf[(2 * a) * 128 + l] = f.x;
            pbuf[(2 * a + 1) * 128 + l] = f.y;
        }
    }
    __syncthreads();
    if (dh == 0) {
        float* e = (side == 0 ? g_e_rt : g_e_lt) + (size_t)(b * LL + l) * ATTN;
#pragma unroll
        for (int a = 0; a < ATTN / 2; a++) {
            float2 f = unpack2(acc[a]);
            float v0 = tanhf(f.x + pbuf[(2 * a) * 128 + l]);
            float v1 = tanhf(f.y + pbuf[(2 * a + 1) * 128 + l]);
            if (side == 0) {
                v0 *= __ldg(diag + 2 * a);
                v1 *= __ldg(diag + 2 * a + 1);
            }
            e[2 * a] = v0;
            e[2 * a + 1] = v1;
        }
    }
}

// ================= branch: max-attentive argmax =================
__device__ __forceinline__ void maxatt_block(
        const float* __restrict__ lt, const float* __restrict__ rt,
        int b, int rh, float* sm) {
    float* As = sm;
    float* Bs = sm + 512;
    float* nlt = sm + 1536;
    float* redv = sm + 1664;
    int* redi = (int*)(sm + 2688);
    int tid = threadIdx.x;
    int tx = tid & 15, ty = tid >> 4;
    if (tid < 128) {
        const float4* p = (const float4*)(lt + (size_t)(b * LL + tid) * DD);
        float s = 0.f;
        for (int i = 0; i < DD / 4; i++) {
            float4 v = __ldg(p + i);
            s += v.x * v.x + v.y * v.y + v.z * v.z + v.w * v.w;
        }
        nlt[tid] = rsqrtf(fmaxf(s, 1e-6f));
    }
    int lrow = tid >> 1, kq = tid & 1;
    int arow = (tid >> 1) & 63;
    const float4* bp = (const float4*)(lt + (size_t)(b * LL + lrow) * DD);
    const float4* ap = (const float4*)(rt + (size_t)(b * LL + rh * 64 + arow) * DD);
    ull acc[4][4];
#pragma unroll
    for (int i = 0; i < 4; i++)
#pragma unroll
        for (int j = 0; j < 4; j++) acc[i][j] = 0ULL;
    for (int kc = 0; kc < DD / 8; kc++) {
        float4 bv = __ldg(bp + kc * 2 + kq);
        int kb = kq * 4;
        Bs[(kb + 0) * 128 + lrow] = bv.x;
        Bs[(kb + 1) * 128 + lrow] = bv.y;
        Bs[(kb + 2) * 128 + lrow] = bv.z;
        Bs[(kb + 3) * 128 + lrow] = bv.w;
        if (tid < 128) {
            float4 av = __ldg(ap + kc * 2 + kq);
            As[(kb + 0) * 64 + arow] = av.x;
            As[(kb + 1) * 64 + arow] = av.y;
            As[(kb + 2) * 64 + arow] = av.z;
            As[(kb + 3) * 64 + arow] = av.w;
        }
        __syncthreads();
#pragma unroll
        for (int k = 0; k < 8; k++) {
            ull a[4];
#pragma unroll
            for (int i = 0; i < 4; i++) a[i] = bcast2(As[k * 64 + ty + 16 * i]);
#pragma unroll
            for (int j = 0; j < 4; j++) {
                ull bb = *(const ull*)&Bs[k * 128 + 2 * tx + 32 * j];
#pragma unroll
                for (int i = 0; i < 4; i++) acc[i][j] = ffma2u(a[i], bb, acc[i][j]);
            }
        }
        __syncthreads();
    }
#pragma unroll
    for (int i = 0; i < 4; i++) {
        int r = ty + 16 * i;
        float best = -3.4e38f;
        int bi = 0;
#pragma unroll
        for (int j = 0; j < 4; j++) {
            int c = 2 * tx + 32 * j;
            float2 f = unpack2(acc[i][j]);
            float v0 = f.x * nlt[c];
            float v1 = f.y * nlt[c + 1];
            if (v0 > best) { best = v0; bi = c; }
            if (v1 > best) { best = v1; bi = c + 1; }
        }
        redv[r * 16 + tx] = best;
        redi[r * 16 + tx] = bi;
    }
    __syncthreads();
    if (tid < 64) {
        float best = redv[tid * 16];
        int bi = redi[tid * 16];
#pragma unroll
        for (int t = 1; t < 16; t++) {
            float v = redv[tid * 16 + t];
            int ii = redi[tid * 16 + t];
            if (v > best || (v == best && ii < bi)) { best = v; bi = ii; }
        }
        g_pos[b * LL + rh * 64 + tid] = bi;
    }
}

// ================= megaA: maxpool (1280) + full (64) + proj (128) + maxatt (128) =================
#define GRID_MP (BB * MPP)
#define GRID_MEGA (GRID_MP + BB + 2 * BB + 2 * BB)

__global__ __launch_bounds__(256, 1) void megaA(
        const float* __restrict__ lt, const float* __restrict__ rt,
        const float* __restrict__ fw, const float* __restrict__ bw,
        const float* __restrict__ w_full, const float* __restrict__ w_maxpool,
        const float* __restrict__ w1, const float* __restrict__ w2,
        const float* __restrict__ diag, float* __restrict__ out) {
    extern __shared__ char smc[];
    __shared__ float red[128][2];
    int bx = blockIdx.x;
    if (bx < GRID_MP) {
        maxpool_block(lt, rt, w_maxpool, out, bx & 63, bx >> 6, smc, red);
    } else if (bx < GRID_MP + BB) {
        full_block(lt, fw, bw, w_full, out, bx - GRID_MP, (float*)smc);
    } else if (bx < GRID_MP + BB + 2 * BB) {
        int i = bx - GRID_MP - BB;
        proj_block(lt, rt, w1, w2, diag, i >> 1, i & 1, (float*)smc);
    } else {
        int i = bx - GRID_MP - 3 * BB;
        maxatt_block(lt, rt, i >> 1, i & 1, (float*)smc);
    }
}

// ================= kernel B: attentive logits + softmax + att_lt =================
#define SMEM_B ((64 * 129 + 64 * 50 + 50 * 128 + 128 * 200 + 64) * 4)

__global__ __launch_bounds__(256) void kernelB(const float* __restrict__ lt) {
    extern __shared__ float sm[];
    float* Z = sm;
    float* ers = Z + 64 * 129;
    float* eltsT = ers + 64 * 50;
    float* lts = eltsT + 50 * 128;
    int b = blockIdx.x, rh = blockIdx.y;
    int tid = threadIdx.x, tx = tid & 15, ty = tid >> 4;

    for (int i = tid; i < 64 * ATTN; i += 256)
        ers[i] = g_e_rt[((size_t)b * LL + rh * 64) * ATTN + i];
    for (int i = tid; i < LL * ATTN; i += 256) {
        int l = i / ATTN, a = i - l * ATTN;
        eltsT[a * LL + l] = g_e_lt[(size_t)b * LL * ATTN + i];
    }
    {
        const float4* src = (const float4*)(lt + (size_t)b * LL * DD);
        float4* dst = (float4*)lts;
        for (int i = tid; i < LL * DD / 4; i += 256) dst[i] = __ldg(src + i);
    }
    __syncthreads();

    {
        ull acc[4][4];
#pragma unroll
        for (int i = 0; i < 4; i++)
#pragma unroll
            for (int j = 0; j < 4; j++) acc[i][j] = 0ULL;
        for (int k = 0; k < ATTN; k++) {
            ull a[4];
#pragma unroll
            for (int i = 0; i < 4; i++) a[i] = bcast2(ers[(ty + 16 * i) * ATTN + k]);
#pragma unroll
            for (int j = 0; j < 4; j++) {
                ull bb = *(const ull*)&eltsT[k * LL + 2 * tx + 32 * j];
#pragma unroll
                for (int i = 0; i < 4; i++) acc[i][j] = ffma2u(a[i], bb, acc[i][j]);
            }
        }
#pragma unroll
        for (int i = 0; i < 4; i++)
#pragma unroll
            for (int j = 0; j < 4; j++) {
                int r = ty + 16 * i, c = 2 * tx + 32 * j;
                float2 f = unpack2(acc[i][j]);
                Z[r * 129 + c] = f.x;
                Z[r * 129 + c + 1] = f.y;
            }
    }
    __syncthreads();

    // softmax: 2 threads per row
    if (tid < 128) {
        int r = tid >> 1, h = tid & 1;
        float* zr = Z + r * 129 + h * 64;
        float mx = zr[0];
#pragma unroll 4
        for (int k = 1; k < 64; k++) mx = fmaxf(mx, zr[k]);
        mx = fmaxf(mx, __shfl_xor_sync(0xffffffffu, mx, 1));
        float s = 0.f;
#pragma unroll 4
        for (int k = 0; k < 64; k++) {
            float e = expf(zr[k] - mx);
            zr[k] = e;
            s += e;
        }
        s += __shfl_xor_sync(0xffffffffu, s, 1);
        float inv = 1.f / s;
#pragma unroll 4
        for (int k = 0; k < 64; k++) zr[k] *= inv;
    }
    __syncthreads();

    for (int nb = 0; nb < 2; nb++) {
        ull acc[4][4];
#pragma unroll
        for (int i = 0; i < 4; i++)
#pragma unroll
            for (int j = 0; j < 4; j++) acc[i][j] = 0ULL;
        for (int k = 0; k < 128; k++) {
            ull a[4];
#pragma unroll
            for (int i = 0; i < 4; i++) a[i] = bcast2(Z[(ty + 16 * i) * 129 + k]);
#pragma unroll
            for (int j = 0; j < 4; j++) {
                ull bb = *(const ull*)&lts[k * DD + nb * 128 + 2 * tx + 32 * j];
#pragma unroll
                for (int i = 0; i < 4; i++) acc[i][j] = ffma2u(a[i], bb, acc[i][j]);
            }
        }
#pragma unroll
        for (int i = 0; i < 4; i++)
#pragma unroll
            for (int j = 0; j < 4; j++) {
                int r = rh * 64 + ty + 16 * i;
                int d = nb * 128 + 2 * tx + 32 * j;
                if (d < DD - 1) {
                    float2 f = unpack2(acc[i][j]);
                    *(float2*)(g_att_lt + (size_t)(b * LL + r) * DD + d) = f;
                }
            }
    }
}

// ================= kernel C: elementwise mp match, 4 threads/row =================
__global__ __launch_bounds__(512) void kernelC(
        const float* __restrict__ reps_lt, const float* __restrict__ reps_rt,
        const float* __restrict__ w_att, const float* __restrict__ w_maxatt,
        float* __restrict__ out) {
    __shared__ float wsT[DD * MPP];  // [d][m]
    int b = blockIdx.x, mode = blockIdx.y, tid = threadIdx.x;
    const float* w = mode ? w_maxatt : w_att;
    for (int i = tid; i < DD * MPP; i += 512) {
        int d = i / MPP, m = i - d * MPP;
        wsT[d * MPP + m] = w[m * DD + d];
    }
    __syncthreads();
    int l = tid >> 2, q = tid & 3;
    const float* xrow;
    const float* yrow;
    if (mode == 0) {
        xrow = g_att_lt + (size_t)(b * LL + l) * DD;
        yrow = reps_rt + (size_t)(b * LL + l) * DD;
    } else {
        xrow = reps_rt + (size_t)(b * LL + l) * DD;
        int yl = g_pos[b * LL + l];
        yrow = reps_lt + (size_t)(b * LL + yl) * DD;
    }
    const float2* xp = (const float2*)(xrow + q * 50);
    const float2* yp = (const float2*)(yrow + q * 50);
    float cos_acc = 0.f;
    ull macc[MPP / 2];
#pragma unroll
    for (int mm = 0; mm < MPP / 2; mm++) macc[mm] = 0ULL;
#pragma unroll
    for (int i = 0; i < 25; i++) {
        float2 x = __ldg(xp + i);
        float2 y = __ldg(yp + i);
        float p0 = x.x * y.x, p1 = x.y * y.y;
        cos_acc += p0 + p1;
        int d = q * 50 + 2 * i;
        ull pb0 = bcast2(p0), pb1 = bcast2(p1);
        const ull* w0 = (const ull*)&wsT[d * MPP];
        const ull* w1 = (const ull*)&wsT[(d + 1) * MPP];
#pragma unroll
        for (int mm = 0; mm < MPP / 2; mm++) {
            macc[mm] = ffma2u(pb0, w0[mm], macc[mm]);
            macc[mm] = ffma2u(pb1, w1[mm], macc[mm]);
        }
    }
    // reduce across the 4 q-lanes (consecutive lanes)
    cos_acc += __shfl_xor_sync(0xffffffffu, cos_acc, 1);
    cos_acc += __shfl_xor_sync(0xffffffffu, cos_acc, 2);
#pragma unroll
    for (int mm = 0; mm < MPP / 2; mm++) {
        macc[mm] = addp2(macc[mm], __shfl_xor_sync(0xffffffffu, macc[mm], 1));
        macc[mm] = addp2(macc[mm], __shfl_xor_sync(0xffffffffu, macc[mm], 2));
    }
    if (q == 0) {
        float* o = out + (size_t)(b * LL + l) * OC + (mode ? 62 : 41);
        o[0] = tanhf(cos_acc);
#pragma unroll
        for (int mm = 0; mm < MPP / 2; mm++) {
            float2 f = unpack2(macc[mm]);
            o[1 + 2 * mm] = tanhf(f.x);
            o[2 + 2 * mm] = tanhf(f.y);
        }
    }
}

// ================= launch =================
extern "C" void kernel_launch(void* const* d_in, const int* in_sizes, int n_in,
                              void* d_out, int out_size) {
    const float* reps_lt = (const float*)d_in[0];
    const float* reps_rt = (const float*)d_in[1];
    const float* fw_h = (const float*)d_in[2];
    const float* bw_h = (const float*)d_in[3];
    const float* w_full = (const float*)d_in[4];
    const float* w_maxpool = (const float*)d_in[5];
    const float* w_att = (const float*)d_in[6];
    const float* w_maxatt = (const float*)d_in[7];
    const float* attn_w1 = (const float*)d_in[8];
    const float* attn_w2 = (const float*)d_in[9];
    const float* diag_w = (const float*)d_in[10];
    float* out = (float*)d_out;

    cudaFuncSetAttribute(megaA, cudaFuncAttributeMaxDynamicSharedMemorySize, SMEM_MP);
    cudaFuncSetAttribute(kernelB, cudaFuncAttributeMaxDynamicSharedMemorySize, SMEM_B);

    megaA<<<GRID_MEGA, 256, SMEM_MP>>>(reps_lt, reps_rt, fw_h, bw_h, w_full,
                                       w_maxpool, attn_w1, attn_w2, diag_w, out);
    kernelB<<<dim3(BB, 2), 256, SMEM_B>>>(reps_lt);
    kernelC<<<dim3(BB, 2), 512>>>(reps_lt, reps_rt, w_att, w_maxatt, out);
}

// round 7
// speedup vs baseline: 1.9866x; 1.0410x over previous
#include <cuda_runtime.h>
#include <cuda_bf16.h>
#include <math.h>
#include <stdint.h>

#define BB 64
#define LL 128
#define DD 200
#define MPP 20
#define ATTN 50
#define OC 83

typedef unsigned long long ull;

// ---------------- scratch (no cudaMalloc allowed) ----------------
__device__ __align__(16) float g_e_rt[BB * LL * ATTN];
__device__ __align__(16) float g_e_lt[BB * LL * ATTN];
__device__ __align__(16) float g_att_lt[BB * LL * DD];
__device__ int g_pos[BB * LL];

// -------- packed fp32x2 helpers --------
__device__ __forceinline__ ull ffma2u(ull a, ull b, ull c) {
    ull d;
    asm("fma.rn.f32x2 %0, %1, %2, %3;" : "=l"(d) : "l"(a), "l"(b), "l"(c));
    return d;
}
__device__ __forceinline__ ull addp2(ull a, ull b) {
    ull d;
    asm("add.rn.f32x2 %0, %1, %2;" : "=l"(d) : "l"(a), "l"(b));
    return d;
}
__device__ __forceinline__ ull bcast2(float x) {
    ull r;
    asm("mov.b64 %0, {%1, %1};" : "=l"(r) : "f"(x));
    return r;
}
__device__ __forceinline__ float2 unpack2(ull v) {
    float2 f;
    asm("mov.b64 {%0, %1}, %2;" : "=f"(f.x), "=f"(f.y) : "l"(v));
    return f;
}

// -------- warp MMA helpers --------
__device__ __forceinline__ uint32_t smem_to_u32(const void* p) {
    uint32_t a;
    asm("{ .reg .u64 t; cvta.to.shared.u64 t, %1; cvt.u32.u64 %0, t; }" : "=r"(a) : "l"(p));
    return a;
}
__device__ __forceinline__ void ldsm_x4(uint32_t* r, uint32_t addr) {
    asm volatile("ldmatrix.sync.aligned.m8n8.x4.shared.b16 {%0,%1,%2,%3}, [%4];"
                 : "=r"(r[0]), "=r"(r[1]), "=r"(r[2]), "=r"(r[3]) : "r"(addr));
}
__device__ __forceinline__ void mma16816(float* c, const uint32_t* a, const uint32_t* b) {
    asm volatile(
        "mma.sync.aligned.m16n8k16.row.col.f32.bf16.bf16.f32 "
        "{%0,%1,%2,%3}, {%4,%5,%6,%7}, {%8,%9}, {%0,%1,%2,%3};"
        : "+f"(c[0]), "+f"(c[1]), "+f"(c[2]), "+f"(c[3])
        : "r"(a[0]), "r"(a[1]), "r"(a[2]), "r"(a[3]), "r"(b[0]), "r"(b[1]));
}

// ======================================================================
// maxpool branch: S_m = lt @ (w_m .* rt)^T [128x128, K=200->208], bf16x3
// block = 512 (16 warps, 4x4 warp grid; each warp 32x32 output tile)
// ======================================================================
#define STRD 216
#define TILE_B (LL * STRD * 2)          // 55296 bytes per tile
#define OFF_AH 0
#define OFF_AL (TILE_B)
#define OFF_BH (2 * TILE_B)
#define OFF_BL (3 * TILE_B)
#define SMEM_MP (4 * TILE_B)            // 221184

__device__ __forceinline__ void split2(float2 x, uint32_t& hi, uint32_t& lo) {
    __nv_bfloat162 h2 = __float22bfloat162_rn(x);
    float2 hf = __bfloat1622float2(h2);
    __nv_bfloat162 l2 = __float22bfloat162_rn(make_float2(x.x - hf.x, x.y - hf.y));
    hi = *(uint32_t*)&h2;
    lo = *(uint32_t*)&l2;
}

__device__ __forceinline__ void maxpool_block(
        const float* __restrict__ lt, const float* __restrict__ rt,
        const float* __restrict__ w, float* __restrict__ out,
        int b, int m, char* smc, float (*red)[4]) {
    uint32_t sbase = smem_to_u32(smc);
    int tid = threadIdx.x, lane = tid & 31, wid = tid >> 5;

    // zero pad cols [200,208)
    for (int i = tid; i < 128 * 4; i += 512) {
        int r = i >> 2, c = i & 3;
        int off = (r * STRD + 200 + 2 * c) * 2;
        *(uint32_t*)(smc + OFF_AH + off) = 0;
        *(uint32_t*)(smc + OFF_AL + off) = 0;
        *(uint32_t*)(smc + OFF_BH + off) = 0;
        *(uint32_t*)(smc + OFF_BL + off) = 0;
    }
    const float* ltb = lt + (size_t)b * LL * DD;
    const float* rtb = rt + (size_t)b * LL * DD;
    const float* wm = w + (size_t)m * DD;
    for (int i = tid; i < LL * 100; i += 512) {
        int r = i / 100, kp = i - r * 100, k = kp * 2;
        int off = (r * STRD + k) * 2;
        uint32_t hi, lo;
        float2 xa = *(const float2*)(ltb + r * DD + k);
        split2(xa, hi, lo);
        *(uint32_t*)(smc + OFF_AH + off) = hi;
        *(uint32_t*)(smc + OFF_AL + off) = lo;
        float2 xb = *(const float2*)(rtb + r * DD + k);
        float2 ww = *(const float2*)(wm + k);
        xb.x *= ww.x;
        xb.y *= ww.y;
        split2(xb, hi, lo);
        *(uint32_t*)(smc + OFF_BH + off) = hi;
        *(uint32_t*)(smc + OFF_BL + off) = lo;
    }
    __syncthreads();

    int mbase = (wid >> 2) * 32, nbase = (wid & 3) * 32;
    int a_row = lane & 15;
    int a_col8 = (lane & 16) ? 8 : 0;
    int b_row = (lane & 7) + ((lane & 16) ? 8 : 0);
    int b_col8 = (lane & 8) ? 8 : 0;

    float acc[2][4][4];
#pragma unroll
    for (int mt = 0; mt < 2; mt++)
#pragma unroll
        for (int nt = 0; nt < 4; nt++)
#pragma unroll
            for (int q = 0; q < 4; q++) acc[mt][nt][q] = 0.f;

#pragma unroll 1
    for (int kg = 0; kg < 13; kg++) {
        int kc = kg * 16;
        uint32_t ah[2][4], al[2][4];
#pragma unroll
        for (int mt = 0; mt < 2; mt++) {
            uint32_t row = mbase + 16 * mt + a_row;
            uint32_t boff = (row * STRD + kc + a_col8) * 2;
            ldsm_x4(ah[mt], sbase + OFF_AH + boff);
            ldsm_x4(al[mt], sbase + OFF_AL + boff);
        }
#pragma unroll
        for (int np = 0; np < 2; np++) {
            uint32_t row = nbase + np * 16 + b_row;
            uint32_t boff = (row * STRD + kc + b_col8) * 2;
            uint32_t bh[4], bl[4];
            ldsm_x4(bh, sbase + OFF_BH + boff);
            ldsm_x4(bl, sbase + OFF_BL + boff);
            // pass-interleaved: 4 independent acc chains per pass
#pragma unroll
            for (int mt = 0; mt < 2; mt++) {
                mma16816(acc[mt][2 * np], ah[mt], bh);
                mma16816(acc[mt][2 * np + 1], ah[mt], bh + 2);
            }
#pragma unroll
            for (int mt = 0; mt < 2; mt++) {
                mma16816(acc[mt][2 * np], ah[mt], bl);
                mma16816(acc[mt][2 * np + 1], ah[mt], bl + 2);
            }
#pragma unroll
            for (int mt = 0; mt < 2; mt++) {
                mma16816(acc[mt][2 * np], al[mt], bh);
                mma16816(acc[mt][2 * np + 1], al[mt], bh + 2);
            }
        }
    }

    int wc = wid & 3;
#pragma unroll
    for (int mt = 0; mt < 2; mt++) {
        float lo = -3.4e38f, hi = -3.4e38f;
#pragma unroll
        for (int nt = 0; nt < 4; nt++) {
            lo = fmaxf(lo, fmaxf(acc[mt][nt][0], acc[mt][nt][1]));
            hi = fmaxf(hi, fmaxf(acc[mt][nt][2], acc[mt][nt][3]));
        }
        lo = fmaxf(lo, __shfl_xor_sync(0xffffffffu, lo, 1));
        lo = fmaxf(lo, __shfl_xor_sync(0xffffffffu, lo, 2));
        hi = fmaxf(hi, __shfl_xor_sync(0xffffffffu, hi, 1));
        hi = fmaxf(hi, __shfl_xor_sync(0xffffffffu, hi, 2));
        if ((lane & 3) == 0) {
            int r = mbase + 16 * mt + (lane >> 2);
            red[r][wc] = lo;
            red[r + 8][wc] = hi;
        }
    }
    __syncthreads();
    if (tid < 128) {
        float v = fmaxf(fmaxf(red[tid][0], red[tid][1]), fmaxf(red[tid][2], red[tid][3]));
        out[(size_t)(b * LL + tid) * OC + 21 + m] = tanhf(v);
    }
}

// ================= branch: full match (cols [0,21)) =================
__device__ __forceinline__ void full_block(
        const float* __restrict__ lt, const float* __restrict__ fw,
        const float* __restrict__ bw, const float* __restrict__ wf,
        float* __restrict__ out, int b, float* sm) {
    float* hw = sm;  // [21][200]
    int tid = threadIdx.x;
    for (int idx = tid; idx < (MPP + 1) * DD; idx += 512) {
        int mm = idx / DD, d = idx - mm * DD;
        float hv = (d < DD / 2) ? fw[b * (DD / 2) + d] : bw[b * (DD / 2) + d - DD / 2];
        hw[idx] = (mm == 0) ? hv : wf[(mm - 1) * DD + d] * hv;
    }
    __syncthreads();
    if (tid < 128) {
        const ull* row = (const ull*)(lt + (size_t)(b * LL + tid) * DD);
        ull acc[MPP + 1];
#pragma unroll
        for (int mm = 0; mm <= MPP; mm++) acc[mm] = 0ULL;
        for (int d2 = 0; d2 < DD / 2; d2++) {
            ull x = __ldg(row + d2);
#pragma unroll
            for (int mm = 0; mm <= MPP; mm++)
                acc[mm] = ffma2u(x, *(const ull*)&hw[mm * DD + 2 * d2], acc[mm]);
        }
        float* o = out + (size_t)(b * LL + tid) * OC;
#pragma unroll
        for (int mm = 0; mm <= MPP; mm++) {
            float2 f = unpack2(acc[mm]);
            o[mm] = tanhf(f.x + f.y);
        }
    }
}

// ================= branch: attention projection =================
__device__ __forceinline__ void proj_block(
        const float* __restrict__ lt, const float* __restrict__ rt,
        const float* __restrict__ w1, const float* __restrict__ w2,
        const float* __restrict__ diag, int b, int side, float* sm) {
    float* ws = sm;            // [200][50]
    float* pbuf = sm + 10000;  // [50][128]
    int tid = threadIdx.x;
    const float* wsrc = side == 0 ? w1 : w2;
    for (int i = tid; i < DD * ATTN; i += 512) ws[i] = wsrc[i];
    __syncthreads();
    int l = tid & 127, dh = (tid >> 7) & 1;
    ull acc[ATTN / 2];
    if (tid < 256) {
        const float* base = side == 0 ? rt : lt;
        const float4* row = (const float4*)(base + (size_t)(b * LL + l) * DD + dh * 100);
#pragma unroll
        for (int a = 0; a < ATTN / 2; a++) acc[a] = 0ULL;
        for (int d4 = 0; d4 < 25; d4++) {
            float4 x = __ldg(row + d4);
            int d = dh * 100 + d4 * 4;
#pragma unroll
            for (int c = 0; c < 4; c++) {
                float xc = (c == 0) ? x.x : (c == 1) ? x.y : (c == 2) ? x.z : x.w;
                ull x2 = bcast2(xc);
                const ull* wr = (const ull*)&ws[(d + c) * ATTN];
#pragma unroll
                for (int a = 0; a < ATTN / 2; a++) acc[a] = ffma2u(x2, wr[a], acc[a]);
            }
        }
        if (dh == 1) {
#pragma unroll
            for (int a = 0; a < ATTN / 2; a++) {
                float2 f = unpack2(acc[a]);
                pbuf[(2 * a) * 128 + l] = f.x;
                pbuf[(2 * a + 1) * 128 + l] = f.y;
            }
        }
    }
    __syncthreads();
    if (tid < 256 && dh == 0) {
        float* e = (side == 0 ? g_e_rt : g_e_lt) + (size_t)(b * LL + l) * ATTN;
#pragma unroll
        for (int a = 0; a < ATTN / 2; a++) {
            float2 f = unpack2(acc[a]);
            float v0 = tanhf(f.x + pbuf[(2 * a) * 128 + l]);
            float v1 = tanhf(f.y + pbuf[(2 * a + 1) * 128 + l]);
            if (side == 0) {
                v0 *= __ldg(diag + 2 * a);
                v1 *= __ldg(diag + 2 * a + 1);
            }
            e[2 * a] = v0;
            e[2 * a + 1] = v1;
        }
    }
}

// ================= branch: max-attentive argmax =================
__device__ __forceinline__ void maxatt_block(
        const float* __restrict__ lt, const float* __restrict__ rt,
        int b, int rh, float* sm) {
    float* As = sm;
    float* Bs = sm + 512;
    float* nlt = sm + 1536;
    float* redv = sm + 1664;
    int* redi = (int*)(sm + 2688);
    int tid = threadIdx.x;
    int tx = tid & 15, ty = (tid >> 4) & 15;
    if (tid < 128) {
        const float4* p = (const float4*)(lt + (size_t)(b * LL + tid) * DD);
        float s = 0.f;
        for (int i = 0; i < DD / 4; i++) {
            float4 v = __ldg(p + i);
            s += v.x * v.x + v.y * v.y + v.z * v.z + v.w * v.w;
        }
        nlt[tid] = rsqrtf(fmaxf(s, 1e-6f));
    }
    int lrow = (tid >> 1) & 127, kq = tid & 1;
    int arow = (tid >> 1) & 63;
    const float4* bp = (const float4*)(lt + (size_t)(b * LL + lrow) * DD);
    const float4* ap = (const float4*)(rt + (size_t)(b * LL + rh * 64 + arow) * DD);
    ull acc[4][4];
#pragma unroll
    for (int i = 0; i < 4; i++)
#pragma unroll
        for (int j = 0; j < 4; j++) acc[i][j] = 0ULL;
    for (int kc = 0; kc < DD / 8; kc++) {
        if (tid < 256) {
            float4 bv = __ldg(bp + kc * 2 + kq);
            int kb = kq * 4;
            Bs[(kb + 0) * 128 + lrow] = bv.x;
            Bs[(kb + 1) * 128 + lrow] = bv.y;
            Bs[(kb + 2) * 128 + lrow] = bv.z;
            Bs[(kb + 3) * 128 + lrow] = bv.w;
            if (tid < 128) {
                float4 av = __ldg(ap + kc * 2 + kq);
                As[(kb + 0) * 64 + arow] = av.x;
                As[(kb + 1) * 64 + arow] = av.y;
                As[(kb + 2) * 64 + arow] = av.z;
                As[(kb + 3) * 64 + arow] = av.w;
            }
        }
        __syncthreads();
        if (tid < 256) {
#pragma unroll
            for (int k = 0; k < 8; k++) {
                ull a[4];
#pragma unroll
                for (int i = 0; i < 4; i++) a[i] = bcast2(As[k * 64 + ty + 16 * i]);
#pragma unroll
                for (int j = 0; j < 4; j++) {
                    ull bb = *(const ull*)&Bs[k * 128 + 2 * tx + 32 * j];
#pragma unroll
                    for (int i = 0; i < 4; i++) acc[i][j] = ffma2u(a[i], bb, acc[i][j]);
                }
            }
        }
        __syncthreads();
    }
    if (tid < 256) {
#pragma unroll
        for (int i = 0; i < 4; i++) {
            int r = ty + 16 * i;
            float best = -3.4e38f;
            int bi = 0;
#pragma unroll
            for (int j = 0; j < 4; j++) {
                int c = 2 * tx + 32 * j;
                float2 f = unpack2(acc[i][j]);
                float v0 = f.x * nlt[c];
                float v1 = f.y * nlt[c + 1];
                if (v0 > best) { best = v0; bi = c; }
                if (v1 > best) { best = v1; bi = c + 1; }
            }
            redv[r * 16 + tx] = best;
            redi[r * 16 + tx] = bi;
        }
    }
    __syncthreads();
    if (tid < 64) {
        float best = redv[tid * 16];
        int bi = redi[tid * 16];
#pragma unroll
        for (int t = 1; t < 16; t++) {
            float v = redv[tid * 16 + t];
            int ii = redi[tid * 16 + t];
            if (v > best || (v == best && ii < bi)) { best = v; bi = ii; }
        }
        g_pos[b * LL + rh * 64 + tid] = bi;
    }
}

// ================= megaA: maxpool (1280) + full (64) + proj (128) + maxatt (128) =================
#define GRID_MP (BB * MPP)
#define GRID_MEGA (GRID_MP + BB + 2 * BB + 2 * BB)

__global__ __launch_bounds__(512, 1) void megaA(
        const float* __restrict__ lt, const float* __restrict__ rt,
        const float* __restrict__ fw, const float* __restrict__ bw,
        const float* __restrict__ w_full, const float* __restrict__ w_maxpool,
        const float* __restrict__ w1, const float* __restrict__ w2,
        const float* __restrict__ diag, float* __restrict__ out) {
    extern __shared__ char smc[];
    __shared__ float red[128][4];
    int bx = blockIdx.x;
    if (bx < GRID_MP) {
        maxpool_block(lt, rt, w_maxpool, out, bx & 63, bx >> 6, smc, red);
    } else if (bx < GRID_MP + BB) {
        full_block(lt, fw, bw, w_full, out, bx - GRID_MP, (float*)smc);
    } else if (bx < GRID_MP + BB + 2 * BB) {
        int i = bx - GRID_MP - BB;
        proj_block(lt, rt, w1, w2, diag, i >> 1, i & 1, (float*)smc);
    } else {
        int i = bx - GRID_MP - 3 * BB;
        maxatt_block(lt, rt, i >> 1, i & 1, (float*)smc);
    }
}

// ================= kernel B: attentive logits + softmax + att_lt =================
#define SMEM_B ((64 * 129 + 64 * 50 + 50 * 128 + 128 * 200 + 64) * 4)

__global__ __launch_bounds__(256) void kernelB(const float* __restrict__ lt) {
    extern __shared__ float sm[];
    float* Z = sm;
    float* ers = Z + 64 * 129;
    float* eltsT = ers + 64 * 50;
    float* lts = eltsT + 50 * 128;
    int b = blockIdx.x, rh = blockIdx.y;
    int tid = threadIdx.x, tx = tid & 15, ty = tid >> 4;

    for (int i = tid; i < 64 * ATTN; i += 256)
        ers[i] = g_e_rt[((size_t)b * LL + rh * 64) * ATTN + i];
    for (int i = tid; i < LL * ATTN; i += 256) {
        int l = i / ATTN, a = i - l * ATTN;
        eltsT[a * LL + l] = g_e_lt[(size_t)b * LL * ATTN + i];
    }
    {
        const float4* src = (const float4*)(lt + (size_t)b * LL * DD);
        float4* dst = (float4*)lts;
        for (int i = tid; i < LL * DD / 4; i += 256) dst[i] = __ldg(src + i);
    }
    __syncthreads();

    {
        ull acc[4][4];
#pragma unroll
        for (int i = 0; i < 4; i++)
#pragma unroll
            for (int j = 0; j < 4; j++) acc[i][j] = 0ULL;
        for (int k = 0; k < ATTN; k++) {
            ull a[4];
#pragma unroll
            for (int i = 0; i < 4; i++) a[i] = bcast2(ers[(ty + 16 * i) * ATTN + k]);
#pragma unroll
            for (int j = 0; j < 4; j++) {
                ull bb = *(const ull*)&eltsT[k * LL + 2 * tx + 32 * j];
#pragma unroll
                for (int i = 0; i < 4; i++) acc[i][j] = ffma2u(a[i], bb, acc[i][j]);
            }
        }
#pragma unroll
        for (int i = 0; i < 4; i++)
#pragma unroll
            for (int j = 0; j < 4; j++) {
                int r = ty + 16 * i, c = 2 * tx + 32 * j;
                float2 f = unpack2(acc[i][j]);
                Z[r * 129 + c] = f.x;
                Z[r * 129 + c + 1] = f.y;
            }
    }
    __syncthreads();

    if (tid < 128) {
        int r = tid >> 1, h = tid & 1;
        float* zr = Z + r * 129 + h * 64;
        float mx = zr[0];
#pragma unroll 4
        for (int k = 1; k < 64; k++) mx = fmaxf(mx, zr[k]);
        mx = fmaxf(mx, __shfl_xor_sync(0xffffffffu, mx, 1));
        float s = 0.f;
#pragma unroll 4
        for (int k = 0; k < 64; k++) {
            float e = expf(zr[k] - mx);
            zr[k] = e;
            s += e;
        }
        s += __shfl_xor_sync(0xffffffffu, s, 1);
        float inv = 1.f / s;
#pragma unroll 4
        for (int k = 0; k < 64; k++) zr[k] *= inv;
    }
    __syncthreads();

    for (int nb = 0; nb < 2; nb++) {
        ull acc[4][4];
#pragma unroll
        for (int i = 0; i < 4; i++)
#pragma unroll
            for (int j = 0; j < 4; j++) acc[i][j] = 0ULL;
        for (int k = 0; k < 128; k++) {
            ull a[4];
#pragma unroll
            for (int i = 0; i < 4; i++) a[i] = bcast2(Z[(ty + 16 * i) * 129 + k]);
#pragma unroll
            for (int j = 0; j < 4; j++) {
                ull bb = *(const ull*)&lts[k * DD + nb * 128 + 2 * tx + 32 * j];
#pragma unroll
                for (int i = 0; i < 4; i++) acc[i][j] = ffma2u(a[i], bb, acc[i][j]);
            }
        }
#pragma unroll
        for (int i = 0; i < 4; i++)
#pragma unroll
            for (int j = 0; j < 4; j++) {
                int r = rh * 64 + ty + 16 * i;
                int d = nb * 128 + 2 * tx + 32 * j;
                if (d < DD - 1) {
                    float2 f = unpack2(acc[i][j]);
                    *(float2*)(g_att_lt + (size_t)(b * LL + r) * DD + d) = f;
                }
            }
    }
}

// ================= kernel C: elementwise mp match, 4 threads/row =================
__global__ __launch_bounds__(512) void kernelC(
        const float* __restrict__ reps_lt, const float* __restrict__ reps_rt,
        const float* __restrict__ w_att, const float* __restrict__ w_maxatt,
        float* __restrict__ out) {
    __shared__ float wsT[DD * MPP];  // [d][m]
    int b = blockIdx.x, mode = blockIdx.y, tid = threadIdx.x;
    const float* w = mode ? w_maxatt : w_att;
    for (int i = tid; i < DD * MPP; i += 512) {
        int d = i / MPP, m = i - d * MPP;
        wsT[d * MPP + m] = w[m * DD + d];
    }
    __syncthreads();
    int l = tid >> 2, q = tid & 3;
    const float* xrow;
    const float* yrow;
    if (mode == 0) {
        xrow = g_att_lt + (size_t)(b * LL + l) * DD;
        yrow = reps_rt + (size_t)(b * LL + l) * DD;
    } else {
        xrow = reps_rt + (size_t)(b * LL + l) * DD;
        int yl = g_pos[b * LL + l];
        yrow = reps_lt + (size_t)(b * LL + yl) * DD;
    }
    const float2* xp = (const float2*)(xrow + q * 50);
    const float2* yp = (const float2*)(yrow + q * 50);
    float cos_acc = 0.f;
    ull macc[MPP / 2];
#pragma unroll
    for (int mm = 0; mm < MPP / 2; mm++) macc[mm] = 0ULL;
#pragma unroll
    for (int i = 0; i < 25; i++) {
        float2 x = __ldg(xp + i);
        float2 y = __ldg(yp + i);
        float p0 = x.x * y.x, p1 = x.y * y.y;
        cos_acc += p0 + p1;
        int d = q * 50 + 2 * i;
        ull pb0 = bcast2(p0), pb1 = bcast2(p1);
        const ull* w0 = (const ull*)&wsT[d * MPP];
        const ull* w1 = (const ull*)&wsT[(d + 1) * MPP];
#pragma unroll
        for (int mm = 0; mm < MPP / 2; mm++) {
            macc[mm] = ffma2u(pb0, w0[mm], macc[mm]);
            macc[mm] = ffma2u(pb1, w1[mm], macc[mm]);
        }
    }
    cos_acc += __shfl_xor_sync(0xffffffffu, cos_acc, 1);
    cos_acc += __shfl_xor_sync(0xffffffffu, cos_acc, 2);
#pragma unroll
    for (int mm = 0; mm < MPP / 2; mm++) {
        macc[mm] = addp2(macc[mm], __shfl_xor_sync(0xffffffffu, macc[mm], 1));
        macc[mm] = addp2(macc[mm], __shfl_xor_sync(0xffffffffu, macc[mm], 2));
    }
    if (q == 0) {
        float* o = out + (size_t)(b * LL + l) * OC + (mode ? 62 : 41);
        o[0] = tanhf(cos_acc);
#pragma unroll
        for (int mm = 0; mm < MPP / 2; mm++) {
            float2 f = unpack2(macc[mm]);
            o[1 + 2 * mm] = tanhf(f.x);
            o[2 + 2 * mm] = tanhf(f.y);
        }
    }
}

// ================= launch =================
extern "C" void kernel_launch(void* const* d_in, const int* in_sizes, int n_in,
                              void* d_out, int out_size) {
    const float* reps_lt = (const float*)d_in[0];
    const float* reps_rt = (const float*)d_in[1];
    const float* fw_h = (const float*)d_in[2];
    const float* bw_h = (const float*)d_in[3];
    const float* w_full = (const float*)d_in[4];
    const float* w_maxpool = (const float*)d_in[5];
    const float* w_att = (const float*)d_in[6];
    const float* w_maxatt = (const float*)d_in[7];
    const float* attn_w1 = (const float*)d_in[8];
    const float* attn_w2 = (const float*)d_in[9];
    const float* diag_w = (const float*)d_in[10];
    float* out = (float*)d_out;

    cudaFuncSetAttribute(megaA, cudaFuncAttributeMaxDynamicSharedMemorySize, SMEM_MP);
    cudaFuncSetAttribute(kernelB, cudaFuncAttributeMaxDynamicSharedMemorySize, SMEM_B);

    megaA<<<GRID_MEGA, 512, SMEM_MP>>>(reps_lt, reps_rt, fw_h, bw_h, w_full,
                                       w_maxpool, attn_w1, attn_w2, diag_w, out);
    kernelB<<<dim3(BB, 2), 256, SMEM_B>>>(reps_lt);
    kernelC<<<dim3(BB, 2), 512>>>(reps_lt, reps_rt, w_att, w_maxatt, out);
}

// round 8
// speedup vs baseline: 2.0985x; 1.0563x over previous
#include <cuda_runtime.h>
#include <cuda_bf16.h>
#include <cuda_fp16.h>
#include <math.h>
#include <stdint.h>

#define BB 64
#define LL 128
#define DD 200
#define MPP 20
#define ATTN 50
#define OC 83

typedef unsigned long long ull;

// ---------------- scratch (no cudaMalloc allowed) ----------------
__device__ __align__(16) float g_e_rt[BB * LL * ATTN];
__device__ __align__(16) float g_e_lt[BB * LL * ATTN];
#define STRD 216
__device__ __align__(16) __half g_lth[BB * LL * STRD];
__device__ __align__(16) __half g_ltl[BB * LL * STRD];

// -------- packed fp32x2 helpers --------
__device__ __forceinline__ ull ffma2u(ull a, ull b, ull c) {
    ull d;
    asm("fma.rn.f32x2 %0, %1, %2, %3;" : "=l"(d) : "l"(a), "l"(b), "l"(c));
    return d;
}
__device__ __forceinline__ ull addp2(ull a, ull b) {
    ull d;
    asm("add.rn.f32x2 %0, %1, %2;" : "=l"(d) : "l"(a), "l"(b));
    return d;
}
__device__ __forceinline__ ull bcast2(float x) {
    ull r;
    asm("mov.b64 %0, {%1, %1};" : "=l"(r) : "f"(x));
    return r;
}
__device__ __forceinline__ float2 unpack2(ull v) {
    float2 f;
    asm("mov.b64 {%0, %1}, %2;" : "=f"(f.x), "=f"(f.y) : "l"(v));
    return f;
}

// -------- warp MMA helpers --------
__device__ __forceinline__ uint32_t smem_to_u32(const void* p) {
    uint32_t a;
    asm("{ .reg .u64 t; cvta.to.shared.u64 t, %1; cvt.u32.u64 %0, t; }" : "=r"(a) : "l"(p));
    return a;
}
__device__ __forceinline__ void ldsm_x4(uint32_t* r, uint32_t addr) {
    asm volatile("ldmatrix.sync.aligned.m8n8.x4.shared.b16 {%0,%1,%2,%3}, [%4];"
                 : "=r"(r[0]), "=r"(r[1]), "=r"(r[2]), "=r"(r[3]) : "r"(addr));
}
__device__ __forceinline__ void mma16816(float* c, const uint32_t* a, const uint32_t* b) {
    asm volatile(
        "mma.sync.aligned.m16n8k16.row.col.f32.f16.f16.f32 "
        "{%0,%1,%2,%3}, {%4,%5,%6,%7}, {%8,%9}, {%0,%1,%2,%3};"
        : "+f"(c[0]), "+f"(c[1]), "+f"(c[2]), "+f"(c[3])
        : "r"(a[0]), "r"(a[1]), "r"(a[2]), "r"(a[3]), "r"(b[0]), "r"(b[1]));
}

// ======================================================================
// kernelP: precompute fp16 split of lt (per batch) in padded layout
// ======================================================================
__global__ __launch_bounds__(256) void kernelP(const float* __restrict__ lt) {
    int b = blockIdx.x, tid = threadIdx.x;
    const float* ltb = lt + (size_t)b * LL * DD;
    __half* ph = g_lth + (size_t)b * LL * STRD;
    __half* pl = g_ltl + (size_t)b * LL * STRD;
    for (int i = tid; i < 128 * 4; i += 256) {
        int r = i >> 2, c = i & 3;
        *(uint32_t*)&ph[r * STRD + 200 + 2 * c] = 0;
        *(uint32_t*)&pl[r * STRD + 200 + 2 * c] = 0;
    }
    for (int i = tid; i < LL * 100; i += 256) {
        int r = i / 100, k = (i - r * 100) * 2;
        float2 x = *(const float2*)(ltb + r * DD + k);
        __half2 h2 = __float22half2_rn(x);
        float2 hf = __half22float2(h2);
        __half2 l2 = __float22half2_rn(make_float2(x.x - hf.x, x.y - hf.y));
        *(__half2*)&ph[r * STRD + k] = h2;
        *(__half2*)&pl[r * STRD + k] = l2;
    }
}

// ======================================================================
// maxpool branch: S_m = lt @ (w_m .* rt)^T, fp16 2-pass (A split, B single)
// ======================================================================
#define TILE_B (LL * STRD * 2)          // 55296 bytes per tile
#define OFF_AH 0
#define OFF_AL (TILE_B)
#define OFF_BH (2 * TILE_B)
#define SMEM_MP (3 * TILE_B)            // 165888

__device__ __forceinline__ void maxpool_block(
        const float* __restrict__ rt, const float* __restrict__ w,
        float* __restrict__ out, int b, int m, char* smc, float (*red)[4]) {
    uint32_t sbase = smem_to_u32(smc);
    int tid = threadIdx.x, lane = tid & 31, wid = tid >> 5;

    // A: copy precomputed fp16 split tiles (55296 B each = 3456 float4)
    {
        const float4* srcH = (const float4*)(g_lth + (size_t)b * LL * STRD);
        const float4* srcL = (const float4*)(g_ltl + (size_t)b * LL * STRD);
        float4* dstH = (float4*)(smc + OFF_AH);
        float4* dstL = (float4*)(smc + OFF_AL);
        for (int i = tid; i < 3456; i += 512) {
            dstH[i] = __ldg(srcH + i);
            dstL[i] = __ldg(srcL + i);
        }
    }
    // B: w_m .* rt, single fp16
    for (int i = tid; i < 128 * 4; i += 512) {
        int r = i >> 2, c = i & 3;
        *(uint32_t*)(smc + OFF_BH + (r * STRD + 200 + 2 * c) * 2) = 0;
    }
    const float* rtb = rt + (size_t)b * LL * DD;
    const float* wm = w + (size_t)m * DD;
    for (int i = tid; i < LL * 100; i += 512) {
        int r = i / 100, k = (i - r * 100) * 2;
        float2 xb = *(const float2*)(rtb + r * DD + k);
        float2 ww = *(const float2*)(wm + k);
        __half2 h2 = __float22half2_rn(make_float2(xb.x * ww.x, xb.y * ww.y));
        *(uint32_t*)(smc + OFF_BH + (r * STRD + k) * 2) = *(uint32_t*)&h2;
    }
    __syncthreads();

    int mbase = (wid >> 2) * 32, nbase = (wid & 3) * 32;
    int a_row = lane & 15;
    int a_col8 = (lane & 16) ? 8 : 0;
    int b_row = (lane & 7) + ((lane & 16) ? 8 : 0);
    int b_col8 = (lane & 8) ? 8 : 0;

    float acc[2][4][4];
#pragma unroll
    for (int mt = 0; mt < 2; mt++)
#pragma unroll
        for (int nt = 0; nt < 4; nt++)
#pragma unroll
            for (int q = 0; q < 4; q++) acc[mt][nt][q] = 0.f;

#pragma unroll 1
    for (int kg = 0; kg < 13; kg++) {
        int kc = kg * 16;
        uint32_t ah[2][4], al[2][4];
#pragma unroll
        for (int mt = 0; mt < 2; mt++) {
            uint32_t row = mbase + 16 * mt + a_row;
            uint32_t boff = (row * STRD + kc + a_col8) * 2;
            ldsm_x4(ah[mt], sbase + OFF_AH + boff);
            ldsm_x4(al[mt], sbase + OFF_AL + boff);
        }
#pragma unroll
        for (int np = 0; np < 2; np++) {
            uint32_t row = nbase + np * 16 + b_row;
            uint32_t boff = (row * STRD + kc + b_col8) * 2;
            uint32_t bh[4];
            ldsm_x4(bh, sbase + OFF_BH + boff);
#pragma unroll
            for (int mt = 0; mt < 2; mt++) {
                mma16816(acc[mt][2 * np], ah[mt], bh);
                mma16816(acc[mt][2 * np + 1], ah[mt], bh + 2);
            }
#pragma unroll
            for (int mt = 0; mt < 2; mt++) {
                mma16816(acc[mt][2 * np], al[mt], bh);
                mma16816(acc[mt][2 * np + 1], al[mt], bh + 2);
            }
        }
    }

    int wc = wid & 3;
#pragma unroll
    for (int mt = 0; mt < 2; mt++) {
        float lo = -3.4e38f, hi = -3.4e38f;
#pragma unroll
        for (int nt = 0; nt < 4; nt++) {
            lo = fmaxf(lo, fmaxf(acc[mt][nt][0], acc[mt][nt][1]));
            hi = fmaxf(hi, fmaxf(acc[mt][nt][2], acc[mt][nt][3]));
        }
        lo = fmaxf(lo, __shfl_xor_sync(0xffffffffu, lo, 1));
        lo = fmaxf(lo, __shfl_xor_sync(0xffffffffu, lo, 2));
        hi = fmaxf(hi, __shfl_xor_sync(0xffffffffu, hi, 1));
        hi = fmaxf(hi, __shfl_xor_sync(0xffffffffu, hi, 2));
        if ((lane & 3) == 0) {
            int r = mbase + 16 * mt + (lane >> 2);
            red[r][wc] = lo;
            red[r + 8][wc] = hi;
        }
    }
    __syncthreads();
    if (tid < 128) {
        float v = fmaxf(fmaxf(red[tid][0], red[tid][1]), fmaxf(red[tid][2], red[tid][3]));
        out[(size_t)(b * LL + tid) * OC + 21 + m] = tanhf(v);
    }
}

// ================= branch: full match (cols [0,21)) =================
__device__ __forceinline__ void full_block(
        const float* __restrict__ lt, const float* __restrict__ fw,
        const float* __restrict__ bw, const float* __restrict__ wf,
        float* __restrict__ out, int b, float* sm) {
    float* hw = sm;  // [21][200]
    int tid = threadIdx.x;
    for (int idx = tid; idx < (MPP + 1) * DD; idx += 512) {
        int mm = idx / DD, d = idx - mm * DD;
        float hv = (d < DD / 2) ? fw[b * (DD / 2) + d] : bw[b * (DD / 2) + d - DD / 2];
        hw[idx] = (mm == 0) ? hv : wf[(mm - 1) * DD + d] * hv;
    }
    __syncthreads();
    if (tid < 128) {
        const ull* row = (const ull*)(lt + (size_t)(b * LL + tid) * DD);
        ull acc[MPP + 1];
#pragma unroll
        for (int mm = 0; mm <= MPP; mm++) acc[mm] = 0ULL;
        for (int d2 = 0; d2 < DD / 2; d2++) {
            ull x = __ldg(row + d2);
#pragma unroll
            for (int mm = 0; mm <= MPP; mm++)
                acc[mm] = ffma2u(x, *(const ull*)&hw[mm * DD + 2 * d2], acc[mm]);
        }
        float* o = out + (size_t)(b * LL + tid) * OC;
#pragma unroll
        for (int mm = 0; mm <= MPP; mm++) {
            float2 f = unpack2(acc[mm]);
            o[mm] = tanhf(f.x + f.y);
        }
    }
}

// ================= branch: attention projection =================
__device__ __forceinline__ void proj_block(
        const float* __restrict__ lt, const float* __restrict__ rt,
        const float* __restrict__ w1, const float* __restrict__ w2,
        const float* __restrict__ diag, int b, int side, float* sm) {
    float* ws = sm;            // [200][50]
    float* pbuf = sm + 10000;  // [50][128]
    int tid = threadIdx.x;
    const float* wsrc = side == 0 ? w1 : w2;
    for (int i = tid; i < DD * ATTN; i += 512) ws[i] = wsrc[i];
    __syncthreads();
    int l = tid & 127, dh = (tid >> 7) & 1;
    ull acc[ATTN / 2];
    if (tid < 256) {
        const float* base = side == 0 ? rt : lt;
        const float4* row = (const float4*)(base + (size_t)(b * LL + l) * DD + dh * 100);
#pragma unroll
        for (int a = 0; a < ATTN / 2; a++) acc[a] = 0ULL;
        for (int d4 = 0; d4 < 25; d4++) {
            float4 x = __ldg(row + d4);
            int d = dh * 100 + d4 * 4;
#pragma unroll
            for (int c = 0; c < 4; c++) {
                float xc = (c == 0) ? x.x : (c == 1) ? x.y : (c == 2) ? x.z : x.w;
                ull x2 = bcast2(xc);
                const ull* wr = (const ull*)&ws[(d + c) * ATTN];
#pragma unroll
                for (int a = 0; a < ATTN / 2; a++) acc[a] = ffma2u(x2, wr[a], acc[a]);
            }
        }
        if (dh == 1) {
#pragma unroll
            for (int a = 0; a < ATTN / 2; a++) {
                float2 f = unpack2(acc[a]);
                pbuf[(2 * a) * 128 + l] = f.x;
                pbuf[(2 * a + 1) * 128 + l] = f.y;
            }
        }
    }
    __syncthreads();
    if (tid < 256 && dh == 0) {
        float* e = (side == 0 ? g_e_rt : g_e_lt) + (size_t)(b * LL + l) * ATTN;
#pragma unroll
        for (int a = 0; a < ATTN / 2; a++) {
            float2 f = unpack2(acc[a]);
            float v0 = tanhf(f.x + pbuf[(2 * a) * 128 + l]);
            float v1 = tanhf(f.y + pbuf[(2 * a + 1) * 128 + l]);
            if (side == 0) {
                v0 *= __ldg(diag + 2 * a);
                v1 *= __ldg(diag + 2 * a + 1);
            }
            e[2 * a] = v0;
            e[2 * a + 1] = v1;
        }
    }
}

// ======= branch: max-attentive argmax + its mp-elementwise (cols [62,83)) =======
__device__ __forceinline__ void maxatt_block(
        const float* __restrict__ lt, const float* __restrict__ rt,
        const float* __restrict__ w_maxatt, float* __restrict__ out,
        int b, int rh, float* sm) {
    float* As = sm;
    float* Bs = sm + 512;
    float* nlt = sm + 1536;
    float* redv = sm + 1664;
    int* redi = (int*)(sm + 2688);
    float* wsT = sm + 3712;  // [200][20]
    int tid = threadIdx.x;
    int tx = tid & 15, ty = (tid >> 4) & 15;
    if (tid < 128) {
        const float4* p = (const float4*)(lt + (size_t)(b * LL + tid) * DD);
        float s = 0.f;
        for (int i = 0; i < DD / 4; i++) {
            float4 v = __ldg(p + i);
            s += v.x * v.x + v.y * v.y + v.z * v.z + v.w * v.w;
        }
        nlt[tid] = rsqrtf(fmaxf(s, 1e-6f));
    }
    for (int i = tid; i < DD * MPP; i += 512) {
        int d = i / MPP, m = i - d * MPP;
        wsT[d * MPP + m] = w_maxatt[m * DD + d];
    }
    int lrow = (tid >> 1) & 127, kq = tid & 1;
    int arow = (tid >> 1) & 63;
    const float4* bp = (const float4*)(lt + (size_t)(b * LL + lrow) * DD);
    const float4* ap = (const float4*)(rt + (size_t)(b * LL + rh * 64 + arow) * DD);
    ull acc[4][4];
#pragma unroll
    for (int i = 0; i < 4; i++)
#pragma unroll
        for (int j = 0; j < 4; j++) acc[i][j] = 0ULL;
    for (int kc = 0; kc < DD / 8; kc++) {
        if (tid < 256) {
            float4 bv = __ldg(bp + kc * 2 + kq);
            int kb = kq * 4;
            Bs[(kb + 0) * 128 + lrow] = bv.x;
            Bs[(kb + 1) * 128 + lrow] = bv.y;
            Bs[(kb + 2) * 128 + lrow] = bv.z;
            Bs[(kb + 3) * 128 + lrow] = bv.w;
            if (tid < 128) {
                float4 av = __ldg(ap + kc * 2 + kq);
                As[(kb + 0) * 64 + arow] = av.x;
                As[(kb + 1) * 64 + arow] = av.y;
                As[(kb + 2) * 64 + arow] = av.z;
                As[(kb + 3) * 64 + arow] = av.w;
            }
        }
        __syncthreads();
        if (tid < 256) {
#pragma unroll
            for (int k = 0; k < 8; k++) {
                ull a[4];
#pragma unroll
                for (int i = 0; i < 4; i++) a[i] = bcast2(As[k * 64 + ty + 16 * i]);
#pragma unroll
                for (int j = 0; j < 4; j++) {
                    ull bb = *(const ull*)&Bs[k * 128 + 2 * tx + 32 * j];
#pragma unroll
                    for (int i = 0; i < 4; i++) acc[i][j] = ffma2u(a[i], bb, acc[i][j]);
                }
            }
        }
        __syncthreads();
    }
    if (tid < 256) {
#pragma unroll
        for (int i = 0; i < 4; i++) {
            int r = ty + 16 * i;
            float best = -3.4e38f;
            int bi = 0;
#pragma unroll
            for (int j = 0; j < 4; j++) {
                int c = 2 * tx + 32 * j;
                float2 f = unpack2(acc[i][j]);
                float v0 = f.x * nlt[c];
                float v1 = f.y * nlt[c + 1];
                if (v0 > best) { best = v0; bi = c; }
                if (v1 > best) { best = v1; bi = c + 1; }
            }
            redv[r * 16 + tx] = best;
            redi[r * 16 + tx] = bi;
        }
    }
    __syncthreads();
    __shared__ int posbuf[64];
    if (tid < 64) {
        float best = redv[tid * 16];
        int bi = redi[tid * 16];
#pragma unroll
        for (int t = 1; t < 16; t++) {
            float v = redv[tid * 16 + t];
            int ii = redi[tid * 16 + t];
            if (v > best || (v == best && ii < bi)) { best = v; bi = ii; }
        }
        posbuf[tid] = bi;
    }
    __syncthreads();
    // mp-elementwise for these 64 rows: X = rt row, Y = lt[pos]
    if (tid < 256) {
        int l = tid >> 2, q = tid & 3;
        int row = rh * 64 + l;
        const float2* xp = (const float2*)(rt + (size_t)(b * LL + row) * DD + q * 50);
        const float2* yp = (const float2*)(lt + (size_t)(b * LL + posbuf[l]) * DD + q * 50);
        float cos_acc = 0.f;
        ull macc[MPP / 2];
#pragma unroll
        for (int mm = 0; mm < MPP / 2; mm++) macc[mm] = 0ULL;
#pragma unroll
        for (int i = 0; i < 25; i++) {
            float2 x = __ldg(xp + i);
            float2 y = __ldg(yp + i);
            float p0 = x.x * y.x, p1 = x.y * y.y;
            cos_acc += p0 + p1;
            int d = q * 50 + 2 * i;
            ull pb0 = bcast2(p0), pb1 = bcast2(p1);
            const ull* w0 = (const ull*)&wsT[d * MPP];
            const ull* w1 = (const ull*)&wsT[(d + 1) * MPP];
#pragma unroll
            for (int mm = 0; mm < MPP / 2; mm++) {
                macc[mm] = ffma2u(pb0, w0[mm], macc[mm]);
                macc[mm] = ffma2u(pb1, w1[mm], macc[mm]);
            }
        }
        cos_acc += __shfl_xor_sync(0xffffffffu, cos_acc, 1);
        cos_acc += __shfl_xor_sync(0xffffffffu, cos_acc, 2);
#pragma unroll
        for (int mm = 0; mm < MPP / 2; mm++) {
            macc[mm] = addp2(macc[mm], __shfl_xor_sync(0xffffffffu, macc[mm], 1));
            macc[mm] = addp2(macc[mm], __shfl_xor_sync(0xffffffffu, macc[mm], 2));
        }
        if (q == 0) {
            float* o = out + (size_t)(b * LL + row) * OC + 62;
            o[0] = tanhf(cos_acc);
#pragma unroll
            for (int mm = 0; mm < MPP / 2; mm++) {
                float2 f = unpack2(macc[mm]);
                o[1 + 2 * mm] = tanhf(f.x);
                o[2 + 2 * mm] = tanhf(f.y);
            }
        }
    }
}

// ================= megaA =================
#define GRID_MP (BB * MPP)
#define GRID_MEGA (GRID_MP + BB + 2 * BB + 2 * BB)

__global__ __launch_bounds__(512, 1) void megaA(
        const float* __restrict__ lt, const float* __restrict__ rt,
        const float* __restrict__ fw, const float* __restrict__ bw,
        const float* __restrict__ w_full, const float* __restrict__ w_maxpool,
        const float* __restrict__ w1, const float* __restrict__ w2,
        const float* __restrict__ diag, const float* __restrict__ w_maxatt,
        float* __restrict__ out) {
    extern __shared__ char smc[];
    __shared__ float red[128][4];
    int bx = blockIdx.x;
    if (bx < GRID_MP) {
        maxpool_block(rt, w_maxpool, out, bx & 63, bx >> 6, smc, red);
    } else if (bx < GRID_MP + BB) {
        full_block(lt, fw, bw, w_full, out, bx - GRID_MP, (float*)smc);
    } else if (bx < GRID_MP + BB + 2 * BB) {
        int i = bx - GRID_MP - BB;
        proj_block(lt, rt, w1, w2, diag, i >> 1, i & 1, (float*)smc);
    } else {
        int i = bx - GRID_MP - 3 * BB;
        maxatt_block(lt, rt, w_maxatt, out, i >> 1, i & 1, (float*)smc);
    }
}

// ================= kernel B: logits + softmax + att_lt + attentive mp =================
// smem floats: Z[64*129] | ers[64*50] | eltsT[50*128] | lts[128*200+64] | attbuf[64*200]
#define SMEM_B ((64 * 129 + 64 * 50 + 50 * 128 + 128 * 200 + 64 + 64 * 200) * 4)

__global__ __launch_bounds__(256) void kernelB(
        const float* __restrict__ lt, const float* __restrict__ rt,
        const float* __restrict__ w_att, float* __restrict__ out) {
    extern __shared__ float sm[];
    float* Z = sm;
    float* ers = Z + 64 * 129;
    float* eltsT = ers + 64 * 50;
    float* lts = eltsT + 50 * 128;
    float* attbuf = lts + 128 * 200 + 64;
    int b = blockIdx.x, rh = blockIdx.y;
    int tid = threadIdx.x, tx = tid & 15, ty = tid >> 4;

    for (int i = tid; i < 64 * ATTN; i += 256)
        ers[i] = g_e_rt[((size_t)b * LL + rh * 64) * ATTN + i];
    for (int i = tid; i < LL * ATTN; i += 256) {
        int l = i / ATTN, a = i - l * ATTN;
        eltsT[a * LL + l] = g_e_lt[(size_t)b * LL * ATTN + i];
    }
    {
        const float4* src = (const float4*)(lt + (size_t)b * LL * DD);
        float4* dst = (float4*)lts;
        for (int i = tid; i < LL * DD / 4; i += 256) dst[i] = __ldg(src + i);
    }
    __syncthreads();

    {
        ull acc[4][4];
#pragma unroll
        for (int i = 0; i < 4; i++)
#pragma unroll
            for (int j = 0; j < 4; j++) acc[i][j] = 0ULL;
        for (int k = 0; k < ATTN; k++) {
            ull a[4];
#pragma unroll
            for (int i = 0; i < 4; i++) a[i] = bcast2(ers[(ty + 16 * i) * ATTN + k]);
#pragma unroll
            for (int j = 0; j < 4; j++) {
                ull bb = *(const ull*)&eltsT[k * LL + 2 * tx + 32 * j];
#pragma unroll
                for (int i = 0; i < 4; i++) acc[i][j] = ffma2u(a[i], bb, acc[i][j]);
            }
        }
#pragma unroll
        for (int i = 0; i < 4; i++)
#pragma unroll
            for (int j = 0; j < 4; j++) {
                int r = ty + 16 * i, c = 2 * tx + 32 * j;
                float2 f = unpack2(acc[i][j]);
                Z[r * 129 + c] = f.x;
                Z[r * 129 + c + 1] = f.y;
            }
    }
    __syncthreads();

    if (tid < 128) {
        int r = tid >> 1, h = tid & 1;
        float* zr = Z + r * 129 + h * 64;
        float mx = zr[0];
#pragma unroll 4
        for (int k = 1; k < 64; k++) mx = fmaxf(mx, zr[k]);
        mx = fmaxf(mx, __shfl_xor_sync(0xffffffffu, mx, 1));
        float s = 0.f;
#pragma unroll 4
        for (int k = 0; k < 64; k++) {
            float e = expf(zr[k] - mx);
            zr[k] = e;
            s += e;
        }
        s += __shfl_xor_sync(0xffffffffu, s, 1);
        float inv = 1.f / s;
#pragma unroll 4
        for (int k = 0; k < 64; k++) zr[k] *= inv;
    }
    __syncthreads();

    for (int nb = 0; nb < 2; nb++) {
        ull acc[4][4];
#pragma unroll
        for (int i = 0; i < 4; i++)
#pragma unroll
            for (int j = 0; j < 4; j++) acc[i][j] = 0ULL;
        for (int k = 0; k < 128; k++) {
            ull a[4];
#pragma unroll
            for (int i = 0; i < 4; i++) a[i] = bcast2(Z[(ty + 16 * i) * 129 + k]);
#pragma unroll
            for (int j = 0; j < 4; j++) {
                ull bb = *(const ull*)&lts[k * DD + nb * 128 + 2 * tx + 32 * j];
#pragma unroll
                for (int i = 0; i < 4; i++) acc[i][j] = ffma2u(a[i], bb, acc[i][j]);
            }
        }
#pragma unroll
        for (int i = 0; i < 4; i++)
#pragma unroll
            for (int j = 0; j < 4; j++) {
                int r = ty + 16 * i;
                int d = nb * 128 + 2 * tx + 32 * j;
                if (d < DD - 1) {
                    float2 f = unpack2(acc[i][j]);
                    *(float2*)(attbuf + r * DD + d) = f;
                }
            }
    }
    __syncthreads();

    // attentive mp-elementwise (cols [41,62)): X = attbuf row, Y = rt row
    float* wsT = Z;  // reuse: [200][20]
    for (int i = tid; i < DD * MPP; i += 256) {
        int d = i / MPP, m = i - d * MPP;
        wsT[d * MPP + m] = w_att[m * DD + d];
    }
    __syncthreads();
    {
        int l = tid >> 2, q = tid & 3;
        int row = rh * 64 + l;
        const float2* xp = (const float2*)(attbuf + l * DD + q * 50);
        const float2* yp = (const float2*)(rt + (size_t)(b * LL + row) * DD + q * 50);
        float cos_acc = 0.f;
        ull macc[MPP / 2];
#pragma unroll
        for (int mm = 0; mm < MPP / 2; mm++) macc[mm] = 0ULL;
#pragma unroll
        for (int i = 0; i < 25; i++) {
            float2 x = xp[i];
            float2 y = __ldg(yp + i);
            float p0 = x.x * y.x, p1 = x.y * y.y;
            cos_acc += p0 + p1;
            int d = q * 50 + 2 * i;
            ull pb0 = bcast2(p0), pb1 = bcast2(p1);
            const ull* w0 = (const ull*)&wsT[d * MPP];
            const ull* w1 = (const ull*)&wsT[(d + 1) * MPP];
#pragma unroll
            for (int mm = 0; mm < MPP / 2; mm++) {
                macc[mm] = ffma2u(pb0, w0[mm], macc[mm]);
                macc[mm] = ffma2u(pb1, w1[mm], macc[mm]);
            }
        }
        cos_acc += __shfl_xor_sync(0xffffffffu, cos_acc, 1);
        cos_acc += __shfl_xor_sync(0xffffffffu, cos_acc, 2);
#pragma unroll
        for (int mm = 0; mm < MPP / 2; mm++) {
            macc[mm] = addp2(macc[mm], __shfl_xor_sync(0xffffffffu, macc[mm], 1));
            macc[mm] = addp2(macc[mm], __shfl_xor_sync(0xffffffffu, macc[mm], 2));
        }
        if (q == 0) {
            float* o = out + (size_t)(b * LL + row) * OC + 41;
            o[0] = tanhf(cos_acc);
#pragma unroll
            for (int mm = 0; mm < MPP / 2; mm++) {
                float2 f = unpack2(macc[mm]);
                o[1 + 2 * mm] = tanhf(f.x);
                o[2 + 2 * mm] = tanhf(f.y);
            }
        }
    }
}

// ================= launch =================
extern "C" void kernel_launch(void* const* d_in, const int* in_sizes, int n_in,
                              void* d_out, int out_size) {
    const float* reps_lt = (const float*)d_in[0];
    const float* reps_rt = (const float*)d_in[1];
    const float* fw_h = (const float*)d_in[2];
    const float* bw_h = (const float*)d_in[3];
    const float* w_full = (const float*)d_in[4];
    const float* w_maxpool = (const float*)d_in[5];
    const float* w_att = (const float*)d_in[6];
    const float* w_maxatt = (const float*)d_in[7];
    const float* attn_w1 = (const float*)d_in[8];
    const float* attn_w2 = (const float*)d_in[9];
    const float* diag_w = (const float*)d_in[10];
    float* out = (float*)d_out;

    cudaFuncSetAttribute(megaA, cudaFuncAttributeMaxDynamicSharedMemorySize, SMEM_MP);
    cudaFuncSetAttribute(kernelB, cudaFuncAttributeMaxDynamicSharedMemorySize, SMEM_B);

    kernelP<<<BB, 256>>>(reps_lt);
    megaA<<<GRID_MEGA, 512, SMEM_MP>>>(reps_lt, reps_rt, fw_h, bw_h, w_full,
                                       w_maxpool, attn_w1, attn_w2, diag_w,
                                       w_maxatt, out);
    kernelB<<<dim3(BB, 2), 256, SMEM_B>>>(reps_lt, reps_rt, w_att, out);
}

// round 9
// speedup vs baseline: 2.2956x; 1.0939x over previous
#include <cuda_runtime.h>
#include <cuda_fp16.h>
#include <math.h>
#include <stdint.h>

#define BB 64
#define LL 128
#define DD 200
#define MPP 20
#define ATTN 50
#define OC 83

typedef unsigned long long ull;

// ---------------- scratch ----------------
__device__ __align__(16) float g_e_rt[BB * LL * ATTN];
__device__ __align__(16) float g_e_lt[BB * LL * ATTN];

// -------- packed fp32x2 helpers --------
__device__ __forceinline__ ull ffma2u(ull a, ull b, ull c) {
    ull d;
    asm("fma.rn.f32x2 %0, %1, %2, %3;" : "=l"(d) : "l"(a), "l"(b), "l"(c));
    return d;
}
__device__ __forceinline__ ull addp2(ull a, ull b) {
    ull d;
    asm("add.rn.f32x2 %0, %1, %2;" : "=l"(d) : "l"(a), "l"(b));
    return d;
}
__device__ __forceinline__ ull bcast2(float x) {
    ull r;
    asm("mov.b64 %0, {%1, %1};" : "=l"(r) : "f"(x));
    return r;
}
__device__ __forceinline__ float2 unpack2(ull v) {
    float2 f;
    asm("mov.b64 {%0, %1}, %2;" : "=f"(f.x), "=f"(f.y) : "l"(v));
    return f;
}

// -------- warp MMA helpers --------
__device__ __forceinline__ uint32_t smem_to_u32(const void* p) {
    uint32_t a;
    asm("{ .reg .u64 t; cvta.to.shared.u64 t, %1; cvt.u32.u64 %0, t; }" : "=r"(a) : "l"(p));
    return a;
}
__device__ __forceinline__ void ldsm_x4(uint32_t* r, uint32_t addr) {
    asm volatile("ldmatrix.sync.aligned.m8n8.x4.shared.b16 {%0,%1,%2,%3}, [%4];"
                 : "=r"(r[0]), "=r"(r[1]), "=r"(r[2]), "=r"(r[3]) : "r"(addr));
}
__device__ __forceinline__ void mma16816(float* c, const uint32_t* a, const uint32_t* b) {
    asm volatile(
        "mma.sync.aligned.m16n8k16.row.col.f32.f16.f16.f32 "
        "{%0,%1,%2,%3}, {%4,%5,%6,%7}, {%8,%9}, {%0,%1,%2,%3};"
        : "+f"(c[0]), "+f"(c[1]), "+f"(c[2]), "+f"(c[3])
        : "r"(a[0]), "r"(a[1]), "r"(a[2]), "r"(a[3]), "r"(b[0]), "r"(b[1]));
}

// ======================================================================
// maxpool: CTA = (b, m-group of 5). A = lt split fp16 once; per m: B = w_m.*rt
// ======================================================================
#define STRD 216
#define TILE_B (LL * STRD * 2)          // 55296 bytes per tile
#define OFF_AH 0
#define OFF_AL (TILE_B)
#define OFF_BH (2 * TILE_B)
#define SMEM_MP (3 * TILE_B)            // 165888
#define MGRP 5

__device__ __forceinline__ void maxpool_block(
        const float* __restrict__ lt, const float* __restrict__ rt,
        const float* __restrict__ w, float* __restrict__ out,
        int b, int mg0, char* smc, float (*red)[4]) {
    uint32_t sbase = smem_to_u32(smc);
    int tid = threadIdx.x, lane = tid & 31, wid = tid >> 5;

    // zero pad cols [200,208)
    for (int i = tid; i < 128 * 4; i += 512) {
        int r = i >> 2, c = i & 3;
        int off = (r * STRD + 200 + 2 * c) * 2;
        *(uint32_t*)(smc + OFF_AH + off) = 0;
        *(uint32_t*)(smc + OFF_AL + off) = 0;
        *(uint32_t*)(smc + OFF_BH + off) = 0;
    }
    // A: split lt once per CTA
    const float* ltb = lt + (size_t)b * LL * DD;
    const float* rtb = rt + (size_t)b * LL * DD;
    for (int i = tid; i < LL * 100; i += 512) {
        int r = i / 100, k = (i - r * 100) * 2;
        float2 x = *(const float2*)(ltb + r * DD + k);
        __half2 h2 = __float22half2_rn(x);
        float2 hf = __half22float2(h2);
        __half2 l2 = __float22half2_rn(make_float2(x.x - hf.x, x.y - hf.y));
        int off = (r * STRD + k) * 2;
        *(uint32_t*)(smc + OFF_AH + off) = *(uint32_t*)&h2;
        *(uint32_t*)(smc + OFF_AL + off) = *(uint32_t*)&l2;
    }

    int mbase = (wid >> 2) * 32, nbase = (wid & 3) * 32;
    int a_row = lane & 15;
    int a_col8 = (lane & 16) ? 8 : 0;
    int b_row = (lane & 7) + ((lane & 16) ? 8 : 0);
    int b_col8 = (lane & 8) ? 8 : 0;
    int wc = wid & 3;

#pragma unroll 1
    for (int mg = 0; mg < MGRP; mg++) {
        int m = mg0 + mg;
        // B: w_m .* rt, single fp16
        const float* wm = w + (size_t)m * DD;
        for (int i = tid; i < LL * 100; i += 512) {
            int r = i / 100, k = (i - r * 100) * 2;
            float2 xb = *(const float2*)(rtb + r * DD + k);
            float2 ww = *(const float2*)(wm + k);
            __half2 h2 = __float22half2_rn(make_float2(xb.x * ww.x, xb.y * ww.y));
            *(uint32_t*)(smc + OFF_BH + (r * STRD + k) * 2) = *(uint32_t*)&h2;
        }
        __syncthreads();

        float acc[2][4][4];
#pragma unroll
        for (int mt = 0; mt < 2; mt++)
#pragma unroll
            for (int nt = 0; nt < 4; nt++)
#pragma unroll
                for (int q = 0; q < 4; q++) acc[mt][nt][q] = 0.f;

#pragma unroll 1
        for (int kg = 0; kg < 13; kg++) {
            int kc = kg * 16;
            uint32_t ah[2][4], al[2][4];
#pragma unroll
            for (int mt = 0; mt < 2; mt++) {
                uint32_t row = mbase + 16 * mt + a_row;
                uint32_t boff = (row * STRD + kc + a_col8) * 2;
                ldsm_x4(ah[mt], sbase + OFF_AH + boff);
                ldsm_x4(al[mt], sbase + OFF_AL + boff);
            }
#pragma unroll
            for (int np = 0; np < 2; np++) {
                uint32_t row = nbase + np * 16 + b_row;
                uint32_t boff = (row * STRD + kc + b_col8) * 2;
                uint32_t bh[4];
                ldsm_x4(bh, sbase + OFF_BH + boff);
#pragma unroll
                for (int mt = 0; mt < 2; mt++) {
                    mma16816(acc[mt][2 * np], ah[mt], bh);
                    mma16816(acc[mt][2 * np + 1], ah[mt], bh + 2);
                }
#pragma unroll
                for (int mt = 0; mt < 2; mt++) {
                    mma16816(acc[mt][2 * np], al[mt], bh);
                    mma16816(acc[mt][2 * np + 1], al[mt], bh + 2);
                }
            }
        }

#pragma unroll
        for (int mt = 0; mt < 2; mt++) {
            float lo = -3.4e38f, hi = -3.4e38f;
#pragma unroll
            for (int nt = 0; nt < 4; nt++) {
                lo = fmaxf(lo, fmaxf(acc[mt][nt][0], acc[mt][nt][1]));
                hi = fmaxf(hi, fmaxf(acc[mt][nt][2], acc[mt][nt][3]));
            }
            lo = fmaxf(lo, __shfl_xor_sync(0xffffffffu, lo, 1));
            lo = fmaxf(lo, __shfl_xor_sync(0xffffffffu, lo, 2));
            hi = fmaxf(hi, __shfl_xor_sync(0xffffffffu, hi, 1));
            hi = fmaxf(hi, __shfl_xor_sync(0xffffffffu, hi, 2));
            if ((lane & 3) == 0) {
                int r = mbase + 16 * mt + (lane >> 2);
                red[r][wc] = lo;
                red[r + 8][wc] = hi;
            }
        }
        __syncthreads();
        if (tid < 128) {
            float v = fmaxf(fmaxf(red[tid][0], red[tid][1]),
                            fmaxf(red[tid][2], red[tid][3]));
            out[(size_t)(b * LL + tid) * OC + 21 + m] = tanhf(v);
        }
    }
}

// ================= branch: full match (cols [0,21)) =================
__device__ __forceinline__ void full_block(
        const float* __restrict__ lt, const float* __restrict__ fw,
        const float* __restrict__ bw, const float* __restrict__ wf,
        float* __restrict__ out, int b, float* sm) {
    float* hw = sm;  // [21][200]
    int tid = threadIdx.x;
    for (int idx = tid; idx < (MPP + 1) * DD; idx += 512) {
        int mm = idx / DD, d = idx - mm * DD;
        float hv = (d < DD / 2) ? fw[b * (DD / 2) + d] : bw[b * (DD / 2) + d - DD / 2];
        hw[idx] = (mm == 0) ? hv : wf[(mm - 1) * DD + d] * hv;
    }
    __syncthreads();
    if (tid < 128) {
        const ull* row = (const ull*)(lt + (size_t)(b * LL + tid) * DD);
        ull acc[MPP + 1];
#pragma unroll
        for (int mm = 0; mm <= MPP; mm++) acc[mm] = 0ULL;
        for (int d2 = 0; d2 < DD / 2; d2++) {
            ull x = __ldg(row + d2);
#pragma unroll
            for (int mm = 0; mm <= MPP; mm++)
                acc[mm] = ffma2u(x, *(const ull*)&hw[mm * DD + 2 * d2], acc[mm]);
        }
        float* o = out + (size_t)(b * LL + tid) * OC;
#pragma unroll
        for (int mm = 0; mm <= MPP; mm++) {
            float2 f = unpack2(acc[mm]);
            o[mm] = tanhf(f.x + f.y);
        }
    }
}

// ================= branch: attention projection =================
__device__ __forceinline__ void proj_block(
        const float* __restrict__ lt, const float* __restrict__ rt,
        const float* __restrict__ w1, const float* __restrict__ w2,
        const float* __restrict__ diag, int b, int side, float* sm) {
    float* ws = sm;            // [200][50]
    float* pbuf = sm + 10000;  // [50][128]
    int tid = threadIdx.x;
    const float* wsrc = side == 0 ? w1 : w2;
    for (int i = tid; i < DD * ATTN; i += 512) ws[i] = wsrc[i];
    __syncthreads();
    int l = tid & 127, dh = (tid >> 7) & 1;
    ull acc[ATTN / 2];
    if (tid < 256) {
        const float* base = side == 0 ? rt : lt;
        const float4* row = (const float4*)(base + (size_t)(b * LL + l) * DD + dh * 100);
#pragma unroll
        for (int a = 0; a < ATTN / 2; a++) acc[a] = 0ULL;
        for (int d4 = 0; d4 < 25; d4++) {
            float4 x = __ldg(row + d4);
            int d = dh * 100 + d4 * 4;
#pragma unroll
            for (int c = 0; c < 4; c++) {
                float xc = (c == 0) ? x.x : (c == 1) ? x.y : (c == 2) ? x.z : x.w;
                ull x2 = bcast2(xc);
                const ull* wr = (const ull*)&ws[(d + c) * ATTN];
#pragma unroll
                for (int a = 0; a < ATTN / 2; a++) acc[a] = ffma2u(x2, wr[a], acc[a]);
            }
        }
        if (dh == 1) {
#pragma unroll
            for (int a = 0; a < ATTN / 2; a++) {
                float2 f = unpack2(acc[a]);
                pbuf[(2 * a) * 128 + l] = f.x;
                pbuf[(2 * a + 1) * 128 + l] = f.y;
            }
        }
    }
    __syncthreads();
    if (tid < 256 && dh == 0) {
        float* e = (side == 0 ? g_e_rt : g_e_lt) + (size_t)(b * LL + l) * ATTN;
#pragma unroll
        for (int a = 0; a < ATTN / 2; a++) {
            float2 f = unpack2(acc[a]);
            float v0 = tanhf(f.x + pbuf[(2 * a) * 128 + l]);
            float v1 = tanhf(f.y + pbuf[(2 * a + 1) * 128 + l]);
            if (side == 0) {
                v0 *= __ldg(diag + 2 * a);
                v1 *= __ldg(diag + 2 * a + 1);
            }
            e[2 * a] = v0;
            e[2 * a + 1] = v1;
        }
    }
}

// ======= branch: max-attentive argmax + its mp-elementwise (cols [62,83)) =======
__device__ __forceinline__ void maxatt_block(
        const float* __restrict__ lt, const float* __restrict__ rt,
        const float* __restrict__ w_maxatt, float* __restrict__ out,
        int b, int rh, float* sm) {
    float* As = sm;
    float* Bs = sm + 512;
    float* nlt = sm + 1536;
    float* redv = sm + 1664;
    int* redi = (int*)(sm + 2688);
    float* wsT = sm + 3712;  // [200][20]
    int tid = threadIdx.x;
    int tx = tid & 15, ty = (tid >> 4) & 15;
    if (tid < 128) {
        const float4* p = (const float4*)(lt + (size_t)(b * LL + tid) * DD);
        float s = 0.f;
        for (int i = 0; i < DD / 4; i++) {
            float4 v = __ldg(p + i);
            s += v.x * v.x + v.y * v.y + v.z * v.z + v.w * v.w;
        }
        nlt[tid] = rsqrtf(fmaxf(s, 1e-6f));
    }
    for (int i = tid; i < DD * MPP; i += 512) {
        int d = i / MPP, m = i - d * MPP;
        wsT[d * MPP + m] = w_maxatt[m * DD + d];
    }
    int lrow = (tid >> 1) & 127, kq = tid & 1;
    int arow = (tid >> 1) & 63;
    const float4* bp = (const float4*)(lt + (size_t)(b * LL + lrow) * DD);
    const float4* ap = (const float4*)(rt + (size_t)(b * LL + rh * 64 + arow) * DD);
    ull acc[4][4];
#pragma unroll
    for (int i = 0; i < 4; i++)
#pragma unroll
        for (int j = 0; j < 4; j++) acc[i][j] = 0ULL;
    for (int kc = 0; kc < DD / 8; kc++) {
        if (tid < 256) {
            float4 bv = __ldg(bp + kc * 2 + kq);
            int kb = kq * 4;
            Bs[(kb + 0) * 128 + lrow] = bv.x;
            Bs[(kb + 1) * 128 + lrow] = bv.y;
            Bs[(kb + 2) * 128 + lrow] = bv.z;
            Bs[(kb + 3) * 128 + lrow] = bv.w;
            if (tid < 128) {
                float4 av = __ldg(ap + kc * 2 + kq);
                As[(kb + 0) * 64 + arow] = av.x;
                As[(kb + 1) * 64 + arow] = av.y;
                As[(kb + 2) * 64 + arow] = av.z;
                As[(kb + 3) * 64 + arow] = av.w;
            }
        }
        __syncthreads();
        if (tid < 256) {
#pragma unroll
            for (int k = 0; k < 8; k++) {
                ull a[4];
#pragma unroll
                for (int i = 0; i < 4; i++) a[i] = bcast2(As[k * 64 + ty + 16 * i]);
#pragma unroll
                for (int j = 0; j < 4; j++) {
                    ull bb = *(const ull*)&Bs[k * 128 + 2 * tx + 32 * j];
#pragma unroll
                    for (int i = 0; i < 4; i++) acc[i][j] = ffma2u(a[i], bb, acc[i][j]);
                }
            }
        }
        __syncthreads();
    }
    if (tid < 256) {
#pragma unroll
        for (int i = 0; i < 4; i++) {
            int r = ty + 16 * i;
            float best = -3.4e38f;
            int bi = 0;
#pragma unroll
            for (int j = 0; j < 4; j++) {
                int c = 2 * tx + 32 * j;
                float2 f = unpack2(acc[i][j]);
                float v0 = f.x * nlt[c];
                float v1 = f.y * nlt[c + 1];
                if (v0 > best) { best = v0; bi = c; }
                if (v1 > best) { best = v1; bi = c + 1; }
            }
            redv[r * 16 + tx] = best;
            redi[r * 16 + tx] = bi;
        }
    }
    __syncthreads();
    __shared__ int posbuf[64];
    if (tid < 64) {
        float best = redv[tid * 16];
        int bi = redi[tid * 16];
#pragma unroll
        for (int t = 1; t < 16; t++) {
            float v = redv[tid * 16 + t];
            int ii = redi[tid * 16 + t];
            if (v > best || (v == best && ii < bi)) { best = v; bi = ii; }
        }
        posbuf[tid] = bi;
    }
    __syncthreads();
    if (tid < 256) {
        int l = tid >> 2, q = tid & 3;
        int row = rh * 64 + l;
        const float2* xp = (const float2*)(rt + (size_t)(b * LL + row) * DD + q * 50);
        const float2* yp = (const float2*)(lt + (size_t)(b * LL + posbuf[l]) * DD + q * 50);
        float cos_acc = 0.f;
        ull macc[MPP / 2];
#pragma unroll
        for (int mm = 0; mm < MPP / 2; mm++) macc[mm] = 0ULL;
#pragma unroll
        for (int i = 0; i < 25; i++) {
            float2 x = __ldg(xp + i);
            float2 y = __ldg(yp + i);
            float p0 = x.x * y.x, p1 = x.y * y.y;
            cos_acc += p0 + p1;
            int d = q * 50 + 2 * i;
            ull pb0 = bcast2(p0), pb1 = bcast2(p1);
            const ull* w0 = (const ull*)&wsT[d * MPP];
            const ull* w1 = (const ull*)&wsT[(d + 1) * MPP];
#pragma unroll
            for (int mm = 0; mm < MPP / 2; mm++) {
                macc[mm] = ffma2u(pb0, w0[mm], macc[mm]);
                macc[mm] = ffma2u(pb1, w1[mm], macc[mm]);
            }
        }
        cos_acc += __shfl_xor_sync(0xffffffffu, cos_acc, 1);
        cos_acc += __shfl_xor_sync(0xffffffffu, cos_acc, 2);
#pragma unroll
        for (int mm = 0; mm < MPP / 2; mm++) {
            macc[mm] = addp2(macc[mm], __shfl_xor_sync(0xffffffffu, macc[mm], 1));
            macc[mm] = addp2(macc[mm], __shfl_xor_sync(0xffffffffu, macc[mm], 2));
        }
        if (q == 0) {
            float* o = out + (size_t)(b * LL + row) * OC + 62;
            o[0] = tanhf(cos_acc);
#pragma unroll
            for (int mm = 0; mm < MPP / 2; mm++) {
                float2 f = unpack2(macc[mm]);
                o[1 + 2 * mm] = tanhf(f.x);
                o[2 + 2 * mm] = tanhf(f.y);
            }
        }
    }
}

// ================= megaA =================
#define GRID_MP (BB * (MPP / MGRP))     // 256
#define GRID_MEGA (GRID_MP + BB + 2 * BB + 2 * BB)

__global__ __launch_bounds__(512, 1) void megaA(
        const float* __restrict__ lt, const float* __restrict__ rt,
        const float* __restrict__ fw, const float* __restrict__ bw,
        const float* __restrict__ w_full, const float* __restrict__ w_maxpool,
        const float* __restrict__ w1, const float* __restrict__ w2,
        const float* __restrict__ diag, const float* __restrict__ w_maxatt,
        float* __restrict__ out) {
    extern __shared__ char smc[];
    __shared__ float red[128][4];
    int bx = blockIdx.x;
    if (bx < GRID_MP) {
        maxpool_block(lt, rt, w_maxpool, out, bx >> 2, (bx & 3) * MGRP, smc, red);
    } else if (bx < GRID_MP + BB) {
        full_block(lt, fw, bw, w_full, out, bx - GRID_MP, (float*)smc);
    } else if (bx < GRID_MP + BB + 2 * BB) {
        int i = bx - GRID_MP - BB;
        proj_block(lt, rt, w1, w2, diag, i >> 1, i & 1, (float*)smc);
    } else {
        int i = bx - GRID_MP - 3 * BB;
        maxatt_block(lt, rt, w_maxatt, out, i >> 1, i & 1, (float*)smc);
    }
}

// ================= kernel B: logits + softmax + att_lt + attentive mp =================
#define SMEM_B ((64 * 129 + 64 * 50 + 50 * 128 + 128 * 200 + 64 + 64 * 200) * 4)

__global__ __launch_bounds__(256) void kernelB(
        const float* __restrict__ lt, const float* __restrict__ rt,
        const float* __restrict__ w_att, float* __restrict__ out) {
    extern __shared__ float sm[];
    float* Z = sm;
    float* ers = Z + 64 * 129;
    float* eltsT = ers + 64 * 50;
    float* lts = eltsT + 50 * 128;
    float* attbuf = lts + 128 * 200 + 64;
    int b = blockIdx.x, rh = blockIdx.y;
    int tid = threadIdx.x, tx = tid & 15, ty = tid >> 4;

    for (int i = tid; i < 64 * ATTN; i += 256)
        ers[i] = g_e_rt[((size_t)b * LL + rh * 64) * ATTN + i];
    for (int i = tid; i < LL * ATTN; i += 256) {
        int l = i / ATTN, a = i - l * ATTN;
        eltsT[a * LL + l] = g_e_lt[(size_t)b * LL * ATTN + i];
    }
    {
        const float4* src = (const float4*)(lt + (size_t)b * LL * DD);
        float4* dst = (float4*)lts;
        for (int i = tid; i < LL * DD / 4; i += 256) dst[i] = __ldg(src + i);
    }
    __syncthreads();

    {
        ull acc[4][4];
#pragma unroll
        for (int i = 0; i < 4; i++)
#pragma unroll
            for (int j = 0; j < 4; j++) acc[i][j] = 0ULL;
        for (int k = 0; k < ATTN; k++) {
            ull a[4];
#pragma unroll
            for (int i = 0; i < 4; i++) a[i] = bcast2(ers[(ty + 16 * i) * ATTN + k]);
#pragma unroll
            for (int j = 0; j < 4; j++) {
                ull bb = *(const ull*)&eltsT[k * LL + 2 * tx + 32 * j];
#pragma unroll
                for (int i = 0; i < 4; i++) acc[i][j] = ffma2u(a[i], bb, acc[i][j]);
            }
        }
#pragma unroll
        for (int i = 0; i < 4; i++)
#pragma unroll
            for (int j = 0; j < 4; j++) {
                int r = ty + 16 * i, c = 2 * tx + 32 * j;
                float2 f = unpack2(acc[i][j]);
                Z[r * 129 + c] = f.x;
                Z[r * 129 + c + 1] = f.y;
            }
    }
    __syncthreads();

    if (tid < 128) {
        int r = tid >> 1, h = tid & 1;
        float* zr = Z + r * 129 + h * 64;
        float mx = zr[0];
#pragma unroll 4
        for (int k = 1; k < 64; k++) mx = fmaxf(mx, zr[k]);
        mx = fmaxf(mx, __shfl_xor_sync(0xffffffffu, mx, 1));
        float s = 0.f;
#pragma unroll 4
        for (int k = 0; k < 64; k++) {
            float e = expf(zr[k] - mx);
            zr[k] = e;
            s += e;
        }
        s += __shfl_xor_sync(0xffffffffu, s, 1);
        float inv = 1.f / s;
#pragma unroll 4
        for (int k = 0; k < 64; k++) zr[k] *= inv;
    }
    __syncthreads();

    for (int nb = 0; nb < 2; nb++) {
        ull acc[4][4];
#pragma unroll
        for (int i = 0; i < 4; i++)
#pragma unroll
            for (int j = 0; j < 4; j++) acc[i][j] = 0ULL;
        for (int k = 0; k < 128; k++) {
            ull a[4];
#pragma unroll
            for (int i = 0; i < 4; i++) a[i] = bcast2(Z[(ty + 16 * i) * 129 + k]);
#pragma unroll
            for (int j = 0; j < 4; j++) {
                ull bb = *(const ull*)&lts[k * DD + nb * 128 + 2 * tx + 32 * j];
#pragma unroll
                for (int i = 0; i < 4; i++) acc[i][j] = ffma2u(a[i], bb, acc[i][j]);
            }
        }
#pragma unroll
        for (int i = 0; i < 4; i++)
#pragma unroll
            for (int j = 0; j < 4; j++) {
                int r = ty + 16 * i;
                int d = nb * 128 + 2 * tx + 32 * j;
                if (d < DD - 1) {
                    float2 f = unpack2(acc[i][j]);
                    *(float2*)(attbuf + r * DD + d) = f;
                }
            }
    }
    __syncthreads();

    float* wsT = Z;  // reuse: [200][20]
    for (int i = tid; i < DD * MPP; i += 256) {
        int d = i / MPP, m = i - d * MPP;
        wsT[d * MPP + m] = w_att[m * DD + d];
    }
    __syncthreads();
    {
        int l = tid >> 2, q = tid & 3;
        int row = rh * 64 + l;
        const float2* xp = (const float2*)(attbuf + l * DD + q * 50);
        const float2* yp = (const float2*)(rt + (size_t)(b * LL + row) * DD + q * 50);
        float cos_acc = 0.f;
        ull macc[MPP / 2];
#pragma unroll
        for (int mm = 0; mm < MPP / 2; mm++) macc[mm] = 0ULL;
#pragma unroll
        for (int i = 0; i < 25; i++) {
            float2 x = xp[i];
            float2 y = __ldg(yp + i);
            float p0 = x.x * y.x, p1 = x.y * y.y;
            cos_acc += p0 + p1;
            int d = q * 50 + 2 * i;
            ull pb0 = bcast2(p0), pb1 = bcast2(p1);
            const ull* w0 = (const ull*)&wsT[d * MPP];
            const ull* w1 = (const ull*)&wsT[(d + 1) * MPP];
#pragma unroll
            for (int mm = 0; mm < MPP / 2; mm++) {
                macc[mm] = ffma2u(pb0, w0[mm], macc[mm]);
                macc[mm] = ffma2u(pb1, w1[mm], macc[mm]);
            }
        }
        cos_acc += __shfl_xor_sync(0xffffffffu, cos_acc, 1);
        cos_acc += __shfl_xor_sync(0xffffffffu, cos_acc, 2);
#pragma unroll
        for (int mm = 0; mm < MPP / 2; mm++) {
            macc[mm] = addp2(macc[mm], __shfl_xor_sync(0xffffffffu, macc[mm], 1));
            macc[mm] = addp2(macc[mm], __shfl_xor_sync(0xffffffffu, macc[mm], 2));
        }
        if (q == 0) {
            float* o = out + (size_t)(b * LL + row) * OC + 41;
            o[0] = tanhf(cos_acc);
#pragma unroll
            for (int mm = 0; mm < MPP / 2; mm++) {
                float2 f = unpack2(macc[mm]);
                o[1 + 2 * mm] = tanhf(f.x);
                o[2 + 2 * mm] = tanhf(f.y);
            }
        }
    }
}

// ================= launch =================
extern "C" void kernel_launch(void* const* d_in, const int* in_sizes, int n_in,
                              void* d_out, int out_size) {
    const float* reps_lt = (const float*)d_in[0];
    const float* reps_rt = (const float*)d_in[1];
    const float* fw_h = (const float*)d_in[2];
    const float* bw_h = (const float*)d_in[3];
    const float* w_full = (const float*)d_in[4];
    const float* w_maxpool = (const float*)d_in[5];
    const float* w_att = (const float*)d_in[6];
    const float* w_maxatt = (const float*)d_in[7];
    const float* attn_w1 = (const float*)d_in[8];
    const float* attn_w2 = (const float*)d_in[9];
    const float* diag_w = (const float*)d_in[10];
    float* out = (float*)d_out;

    cudaFuncSetAttribute(megaA, cudaFuncAttributeMaxDynamicSharedMemorySize, SMEM_MP);
    cudaFuncSetAttribute(kernelB, cudaFuncAttributeMaxDynamicSharedMemorySize, SMEM_B);

    megaA<<<GRID_MEGA, 512, SMEM_MP>>>(reps_lt, reps_rt, fw_h, bw_h, w_full,
                                       w_maxpool, attn_w1, attn_w2, diag_w,
                                       w_maxatt, out);
    kernelB<<<dim3(BB, 2), 256, SMEM_B>>>(reps_lt, reps_rt, w_att, out);
}

// round 10
// speedup vs baseline: 2.5188x; 1.0972x over previous
#include <cuda_runtime.h>
#include <cuda_fp16.h>
#include <math.h>
#include <stdint.h>

#define BB 64
#define LL 128
#define DD 200
#define MPP 20
#define ATTN 50
#define OC 83

typedef unsigned long long ull;

// ---------------- scratch ----------------
__device__ __align__(16) float g_e_rt[BB * LL * ATTN];
__device__ __align__(16) float g_e_lt[BB * LL * ATTN];

// -------- packed fp32x2 helpers --------
__device__ __forceinline__ ull ffma2u(ull a, ull b, ull c) {
    ull d;
    asm("fma.rn.f32x2 %0, %1, %2, %3;" : "=l"(d) : "l"(a), "l"(b), "l"(c));
    return d;
}
__device__ __forceinline__ ull addp2(ull a, ull b) {
    ull d;
    asm("add.rn.f32x2 %0, %1, %2;" : "=l"(d) : "l"(a), "l"(b));
    return d;
}
__device__ __forceinline__ ull bcast2(float x) {
    ull r;
    asm("mov.b64 %0, {%1, %1};" : "=l"(r) : "f"(x));
    return r;
}
__device__ __forceinline__ float2 unpack2(ull v) {
    float2 f;
    asm("mov.b64 {%0, %1}, %2;" : "=f"(f.x), "=f"(f.y) : "l"(v));
    return f;
}

// -------- warp MMA helpers --------
__device__ __forceinline__ uint32_t smem_to_u32(const void* p) {
    uint32_t a;
    asm("{ .reg .u64 t; cvta.to.shared.u64 t, %1; cvt.u32.u64 %0, t; }" : "=r"(a) : "l"(p));
    return a;
}
__device__ __forceinline__ void ldsm_x4(uint32_t* r, uint32_t addr) {
    asm volatile("ldmatrix.sync.aligned.m8n8.x4.shared.b16 {%0,%1,%2,%3}, [%4];"
                 : "=r"(r[0]), "=r"(r[1]), "=r"(r[2]), "=r"(r[3]) : "r"(addr));
}
__device__ __forceinline__ void mma16816(float* c, const uint32_t* a, const uint32_t* b) {
    asm volatile(
        "mma.sync.aligned.m16n8k16.row.col.f32.f16.f16.f32 "
        "{%0,%1,%2,%3}, {%4,%5,%6,%7}, {%8,%9}, {%0,%1,%2,%3};"
        : "+f"(c[0]), "+f"(c[1]), "+f"(c[2]), "+f"(c[3])
        : "r"(a[0]), "r"(a[1]), "r"(a[2]), "r"(a[3]), "r"(b[0]), "r"(b[1]));
}

// ======================================================================
// maxpool: CTA = (b, m-group of 5). Plain fp16 A x B (single pass).
// smem: A tile 55296 + B tile 55296 = 110592 -> 2 CTAs/SM
// ======================================================================
#define STRD 216
#define TILE_B (LL * STRD * 2)
#define OFF_A 0
#define OFF_B (TILE_B)
#define SMEM_MP (2 * TILE_B)            // 110592
#define MGRP 5

__device__ __forceinline__ void maxpool_block(
        const float* __restrict__ lt, const float* __restrict__ rt,
        const float* __restrict__ w, float* __restrict__ out,
        int b, int mg0, char* smc, float (*red)[4]) {
    uint32_t sbase = smem_to_u32(smc);
    int tid = threadIdx.x, lane = tid & 31, wid = tid >> 5;

    // zero pad cols [200,208)
    for (int i = tid; i < 128 * 4; i += 512) {
        int r = i >> 2, c = i & 3;
        int off = (r * STRD + 200 + 2 * c) * 2;
        *(uint32_t*)(smc + OFF_A + off) = 0;
        *(uint32_t*)(smc + OFF_B + off) = 0;
    }
    // A: lt -> fp16 once per CTA
    const float* ltb = lt + (size_t)b * LL * DD;
    const float* rtb = rt + (size_t)b * LL * DD;
    for (int i = tid; i < LL * 100; i += 512) {
        int r = i / 100, k = (i - r * 100) * 2;
        float2 x = *(const float2*)(ltb + r * DD + k);
        __half2 h2 = __float22half2_rn(x);
        *(uint32_t*)(smc + OFF_A + (r * STRD + k) * 2) = *(uint32_t*)&h2;
    }

    int mbase = (wid >> 2) * 32, nbase = (wid & 3) * 32;
    int a_row = lane & 15;
    int a_col8 = (lane & 16) ? 8 : 0;
    int b_row = (lane & 7) + ((lane & 16) ? 8 : 0);
    int b_col8 = (lane & 8) ? 8 : 0;
    int wc = wid & 3;

#pragma unroll 1
    for (int mg = 0; mg < MGRP; mg++) {
        int m = mg0 + mg;
        const float* wm = w + (size_t)m * DD;
        for (int i = tid; i < LL * 100; i += 512) {
            int r = i / 100, k = (i - r * 100) * 2;
            float2 xb = *(const float2*)(rtb + r * DD + k);
            float2 ww = *(const float2*)(wm + k);
            __half2 h2 = __float22half2_rn(make_float2(xb.x * ww.x, xb.y * ww.y));
            *(uint32_t*)(smc + OFF_B + (r * STRD + k) * 2) = *(uint32_t*)&h2;
        }
        __syncthreads();

        float acc[2][4][4];
#pragma unroll
        for (int mt = 0; mt < 2; mt++)
#pragma unroll
            for (int nt = 0; nt < 4; nt++)
#pragma unroll
                for (int q = 0; q < 4; q++) acc[mt][nt][q] = 0.f;

#pragma unroll 1
        for (int kg = 0; kg < 13; kg++) {
            int kc = kg * 16;
            uint32_t ah[2][4];
#pragma unroll
            for (int mt = 0; mt < 2; mt++) {
                uint32_t row = mbase + 16 * mt + a_row;
                ldsm_x4(ah[mt], sbase + OFF_A + (row * STRD + kc + a_col8) * 2);
            }
#pragma unroll
            for (int np = 0; np < 2; np++) {
                uint32_t row = nbase + np * 16 + b_row;
                uint32_t bh[4];
                ldsm_x4(bh, sbase + OFF_B + (row * STRD + kc + b_col8) * 2);
#pragma unroll
                for (int mt = 0; mt < 2; mt++) {
                    mma16816(acc[mt][2 * np], ah[mt], bh);
                    mma16816(acc[mt][2 * np + 1], ah[mt], bh + 2);
                }
            }
        }

#pragma unroll
        for (int mt = 0; mt < 2; mt++) {
            float lo = -3.4e38f, hi = -3.4e38f;
#pragma unroll
            for (int nt = 0; nt < 4; nt++) {
                lo = fmaxf(lo, fmaxf(acc[mt][nt][0], acc[mt][nt][1]));
                hi = fmaxf(hi, fmaxf(acc[mt][nt][2], acc[mt][nt][3]));
            }
            lo = fmaxf(lo, __shfl_xor_sync(0xffffffffu, lo, 1));
            lo = fmaxf(lo, __shfl_xor_sync(0xffffffffu, lo, 2));
            hi = fmaxf(hi, __shfl_xor_sync(0xffffffffu, hi, 1));
            hi = fmaxf(hi, __shfl_xor_sync(0xffffffffu, hi, 2));
            if ((lane & 3) == 0) {
                int r = mbase + 16 * mt + (lane >> 2);
                red[r][wc] = lo;
                red[r + 8][wc] = hi;
            }
        }
        __syncthreads();
        if (tid < 128) {
            float v = fmaxf(fmaxf(red[tid][0], red[tid][1]),
                            fmaxf(red[tid][2], red[tid][3]));
            out[(size_t)(b * LL + tid) * OC + 21 + m] = tanhf(v);
        }
    }
}

// ================= branch: full match (cols [0,21)) =================
__device__ __forceinline__ void full_block(
        const float* __restrict__ lt, const float* __restrict__ fw,
        const float* __restrict__ bw, const float* __restrict__ wf,
        float* __restrict__ out, int b, float* sm) {
    float* hw = sm;  // [21][200]
    int tid = threadIdx.x;
    for (int idx = tid; idx < (MPP + 1) * DD; idx += 512) {
        int mm = idx / DD, d = idx - mm * DD;
        float hv = (d < DD / 2) ? fw[b * (DD / 2) + d] : bw[b * (DD / 2) + d - DD / 2];
        hw[idx] = (mm == 0) ? hv : wf[(mm - 1) * DD + d] * hv;
    }
    __syncthreads();
    if (tid < 128) {
        const ull* row = (const ull*)(lt + (size_t)(b * LL + tid) * DD);
        ull acc[MPP + 1];
#pragma unroll
        for (int mm = 0; mm <= MPP; mm++) acc[mm] = 0ULL;
        for (int d2 = 0; d2 < DD / 2; d2++) {
            ull x = __ldg(row + d2);
#pragma unroll
            for (int mm = 0; mm <= MPP; mm++)
                acc[mm] = ffma2u(x, *(const ull*)&hw[mm * DD + 2 * d2], acc[mm]);
        }
        float* o = out + (size_t)(b * LL + tid) * OC;
#pragma unroll
        for (int mm = 0; mm <= MPP; mm++) {
            float2 f = unpack2(acc[mm]);
            o[mm] = tanhf(f.x + f.y);
        }
    }
}

// ================= branch: attention projection =================
__device__ __forceinline__ void proj_block(
        const float* __restrict__ lt, const float* __restrict__ rt,
        const float* __restrict__ w1, const float* __restrict__ w2,
        const float* __restrict__ diag, int b, int side, float* sm) {
    float* ws = sm;            // [200][50]
    float* pbuf = sm + 10000;  // [50][128]
    int tid = threadIdx.x;
    const float* wsrc = side == 0 ? w1 : w2;
    for (int i = tid; i < DD * ATTN; i += 512) ws[i] = wsrc[i];
    __syncthreads();
    int l = tid & 127, dh = (tid >> 7) & 1;
    ull acc[ATTN / 2];
    if (tid < 256) {
        const float* base = side == 0 ? rt : lt;
        const float4* row = (const float4*)(base + (size_t)(b * LL + l) * DD + dh * 100);
#pragma unroll
        for (int a = 0; a < ATTN / 2; a++) acc[a] = 0ULL;
        for (int d4 = 0; d4 < 25; d4++) {
            float4 x = __ldg(row + d4);
            int d = dh * 100 + d4 * 4;
#pragma unroll
            for (int c = 0; c < 4; c++) {
                float xc = (c == 0) ? x.x : (c == 1) ? x.y : (c == 2) ? x.z : x.w;
                ull x2 = bcast2(xc);
                const ull* wr = (const ull*)&ws[(d + c) * ATTN];
#pragma unroll
                for (int a = 0; a < ATTN / 2; a++) acc[a] = ffma2u(x2, wr[a], acc[a]);
            }
        }
        if (dh == 1) {
#pragma unroll
            for (int a = 0; a < ATTN / 2; a++) {
                float2 f = unpack2(acc[a]);
                pbuf[(2 * a) * 128 + l] = f.x;
                pbuf[(2 * a + 1) * 128 + l] = f.y;
            }
        }
    }
    __syncthreads();
    if (tid < 256 && dh == 0) {
        float* e = (side == 0 ? g_e_rt : g_e_lt) + (size_t)(b * LL + l) * ATTN;
#pragma unroll
        for (int a = 0; a < ATTN / 2; a++) {
            float2 f = unpack2(acc[a]);
            float v0 = tanhf(f.x + pbuf[(2 * a) * 128 + l]);
            float v1 = tanhf(f.y + pbuf[(2 * a + 1) * 128 + l]);
            if (side == 0) {
                v0 *= __ldg(diag + 2 * a);
                v1 *= __ldg(diag + 2 * a + 1);
            }
            e[2 * a] = v0;
            e[2 * a + 1] = v1;
        }
    }
}

// ======= branch: max-attentive argmax + its mp-elementwise (cols [62,83)) =======
__device__ __forceinline__ void maxatt_block(
        const float* __restrict__ lt, const float* __restrict__ rt,
        const float* __restrict__ w_maxatt, float* __restrict__ out,
        int b, int rh, float* sm) {
    float* As = sm;
    float* Bs = sm + 512;
    float* nlt = sm + 1536;
    float* redv = sm + 1664;
    int* redi = (int*)(sm + 2688);
    float* wsT = sm + 3712;  // [200][20]
    int tid = threadIdx.x;
    int tx = tid & 15, ty = (tid >> 4) & 15;
    if (tid < 128) {
        const float4* p = (const float4*)(lt + (size_t)(b * LL + tid) * DD);
        float s = 0.f;
        for (int i = 0; i < DD / 4; i++) {
            float4 v = __ldg(p + i);
            s += v.x * v.x + v.y * v.y + v.z * v.z + v.w * v.w;
        }
        nlt[tid] = rsqrtf(fmaxf(s, 1e-6f));
    }
    for (int i = tid; i < DD * MPP; i += 512) {
        int d = i / MPP, m = i - d * MPP;
        wsT[d * MPP + m] = w_maxatt[m * DD + d];
    }
    int lrow = (tid >> 1) & 127, kq = tid & 1;
    int arow = (tid >> 1) & 63;
    const float4* bp = (const float4*)(lt + (size_t)(b * LL + lrow) * DD);
    const float4* ap = (const float4*)(rt + (size_t)(b * LL + rh * 64 + arow) * DD);
    ull acc[4][4];
#pragma unroll
    for (int i = 0; i < 4; i++)
#pragma unroll
        for (int j = 0; j < 4; j++) acc[i][j] = 0ULL;
    for (int kc = 0; kc < DD / 8; kc++) {
        if (tid < 256) {
            float4 bv = __ldg(bp + kc * 2 + kq);
            int kb = kq * 4;
            Bs[(kb + 0) * 128 + lrow] = bv.x;
            Bs[(kb + 1) * 128 + lrow] = bv.y;
            Bs[(kb + 2) * 128 + lrow] = bv.z;
            Bs[(kb + 3) * 128 + lrow] = bv.w;
            if (tid < 128) {
                float4 av = __ldg(ap + kc * 2 + kq);
                As[(kb + 0) * 64 + arow] = av.x;
                As[(kb + 1) * 64 + arow] = av.y;
                As[(kb + 2) * 64 + arow] = av.z;
                As[(kb + 3) * 64 + arow] = av.w;
            }
        }
        __syncthreads();
        if (tid < 256) {
#pragma unroll
            for (int k = 0; k < 8; k++) {
                ull a[4];
#pragma unroll
                for (int i = 0; i < 4; i++) a[i] = bcast2(As[k * 64 + ty + 16 * i]);
#pragma unroll
                for (int j = 0; j < 4; j++) {
                    ull bb = *(const ull*)&Bs[k * 128 + 2 * tx + 32 * j];
#pragma unroll
                    for (int i = 0; i < 4; i++) acc[i][j] = ffma2u(a[i], bb, acc[i][j]);
                }
            }
        }
        __syncthreads();
    }
    if (tid < 256) {
#pragma unroll
        for (int i = 0; i < 4; i++) {
            int r = ty + 16 * i;
            float best = -3.4e38f;
            int bi = 0;
#pragma unroll
            for (int j = 0; j < 4; j++) {
                int c = 2 * tx + 32 * j;
                float2 f = unpack2(acc[i][j]);
                float v0 = f.x * nlt[c];
                float v1 = f.y * nlt[c + 1];
                if (v0 > best) { best = v0; bi = c; }
                if (v1 > best) { best = v1; bi = c + 1; }
            }
            redv[r * 16 + tx] = best;
            redi[r * 16 + tx] = bi;
        }
    }
    __syncthreads();
    __shared__ int posbuf[64];
    if (tid < 64) {
        float best = redv[tid * 16];
        int bi = redi[tid * 16];
#pragma unroll
        for (int t = 1; t < 16; t++) {
            float v = redv[tid * 16 + t];
            int ii = redi[tid * 16 + t];
            if (v > best || (v == best && ii < bi)) { best = v; bi = ii; }
        }
        posbuf[tid] = bi;
    }
    __syncthreads();
    if (tid < 256) {
        int l = tid >> 2, q = tid & 3;
        int row = rh * 64 + l;
        const float2* xp = (const float2*)(rt + (size_t)(b * LL + row) * DD + q * 50);
        const float2* yp = (const float2*)(lt + (size_t)(b * LL + posbuf[l]) * DD + q * 50);
        float cos_acc = 0.f;
        ull macc[MPP / 2];
#pragma unroll
        for (int mm = 0; mm < MPP / 2; mm++) macc[mm] = 0ULL;
#pragma unroll
        for (int i = 0; i < 25; i++) {
            float2 x = __ldg(xp + i);
            float2 y = __ldg(yp + i);
            float p0 = x.x * y.x, p1 = x.y * y.y;
            cos_acc += p0 + p1;
            int d = q * 50 + 2 * i;
            ull pb0 = bcast2(p0), pb1 = bcast2(p1);
            const ull* w0 = (const ull*)&wsT[d * MPP];
            const ull* w1 = (const ull*)&wsT[(d + 1) * MPP];
#pragma unroll
            for (int mm = 0; mm < MPP / 2; mm++) {
                macc[mm] = ffma2u(pb0, w0[mm], macc[mm]);
                macc[mm] = ffma2u(pb1, w1[mm], macc[mm]);
            }
        }
        cos_acc += __shfl_xor_sync(0xffffffffu, cos_acc, 1);
        cos_acc += __shfl_xor_sync(0xffffffffu, cos_acc, 2);
#pragma unroll
        for (int mm = 0; mm < MPP / 2; mm++) {
            macc[mm] = addp2(macc[mm], __shfl_xor_sync(0xffffffffu, macc[mm], 1));
            macc[mm] = addp2(macc[mm], __shfl_xor_sync(0xffffffffu, macc[mm], 2));
        }
        if (q == 0) {
            float* o = out + (size_t)(b * LL + row) * OC + 62;
            o[0] = tanhf(cos_acc);
#pragma unroll
            for (int mm = 0; mm < MPP / 2; mm++) {
                float2 f = unpack2(macc[mm]);
                o[1 + 2 * mm] = tanhf(f.x);
                o[2 + 2 * mm] = tanhf(f.y);
            }
        }
    }
}

// ================= megaA =================
#define GRID_MP (BB * (MPP / MGRP))     // 256
#define GRID_MEGA (GRID_MP + BB + 2 * BB + 2 * BB)

__global__ __launch_bounds__(512, 2) void megaA(
        const float* __restrict__ lt, const float* __restrict__ rt,
        const float* __restrict__ fw, const float* __restrict__ bw,
        const float* __restrict__ w_full, const float* __restrict__ w_maxpool,
        const float* __restrict__ w1, const float* __restrict__ w2,
        const float* __restrict__ diag, const float* __restrict__ w_maxatt,
        float* __restrict__ out) {
    extern __shared__ char smc[];
    __shared__ float red[128][4];
    int bx = blockIdx.x;
    if (bx < GRID_MP) {
        maxpool_block(lt, rt, w_maxpool, out, bx >> 2, (bx & 3) * MGRP, smc, red);
    } else if (bx < GRID_MP + BB) {
        full_block(lt, fw, bw, w_full, out, bx - GRID_MP, (float*)smc);
    } else if (bx < GRID_MP + BB + 2 * BB) {
        int i = bx - GRID_MP - BB;
        proj_block(lt, rt, w1, w2, diag, i >> 1, i & 1, (float*)smc);
    } else {
        int i = bx - GRID_MP - 3 * BB;
        maxatt_block(lt, rt, w_maxatt, out, i >> 1, i & 1, (float*)smc);
    }
}

// ================= kernel B: logits + softmax + att_lt + attentive mp (512 thr) =================
#define SMEM_B ((64 * 129 + 64 * 50 + 50 * 128 + 128 * 200 + 64 + 64 * 200) * 4)

__global__ __launch_bounds__(512) void kernelB(
        const float* __restrict__ lt, const float* __restrict__ rt,
        const float* __restrict__ w_att, float* __restrict__ out) {
    extern __shared__ float sm[];
    float* Z = sm;
    float* ers = Z + 64 * 129;
    float* eltsT = ers + 64 * 50;
    float* lts = eltsT + 50 * 128;
    float* attbuf = lts + 128 * 200 + 64;
    int b = blockIdx.x, rh = blockIdx.y;
    int tid = threadIdx.x, tx = tid & 31, ty = tid >> 5;

    for (int i = tid; i < 64 * ATTN; i += 512)
        ers[i] = g_e_rt[((size_t)b * LL + rh * 64) * ATTN + i];
    for (int i = tid; i < LL * ATTN; i += 512) {
        int l = i / ATTN, a = i - l * ATTN;
        eltsT[a * LL + l] = g_e_lt[(size_t)b * LL * ATTN + i];
    }
    {
        const float4* src = (const float4*)(lt + (size_t)b * LL * DD);
        float4* dst = (float4*)lts;
        for (int i = tid; i < LL * DD / 4; i += 512) dst[i] = __ldg(src + i);
    }
    __syncthreads();

    // phase 1: Z[64x128] = ers @ eltsT
    {
        ull acc[4][2];
#pragma unroll
        for (int i = 0; i < 4; i++)
#pragma unroll
            for (int j = 0; j < 2; j++) acc[i][j] = 0ULL;
        for (int k = 0; k < ATTN; k++) {
            ull a[4];
#pragma unroll
            for (int i = 0; i < 4; i++) a[i] = bcast2(ers[(ty + 16 * i) * ATTN + k]);
#pragma unroll
            for (int j = 0; j < 2; j++) {
                ull bb = *(const ull*)&eltsT[k * LL + 2 * tx + 64 * j];
#pragma unroll
                for (int i = 0; i < 4; i++) acc[i][j] = ffma2u(a[i], bb, acc[i][j]);
            }
        }
#pragma unroll
        for (int i = 0; i < 4; i++)
#pragma unroll
            for (int j = 0; j < 2; j++) {
                int r = ty + 16 * i, c = 2 * tx + 64 * j;
                float2 f = unpack2(acc[i][j]);
                Z[r * 129 + c] = f.x;
                Z[r * 129 + c + 1] = f.y;
            }
    }
    __syncthreads();

    // softmax: 4 threads per row
    if (tid < 256) {
        int r = tid >> 2, h = tid & 3;
        float* zr = Z + r * 129 + h * 32;
        float mx = zr[0];
#pragma unroll 4
        for (int k = 1; k < 32; k++) mx = fmaxf(mx, zr[k]);
        mx = fmaxf(mx, __shfl_xor_sync(0xffffffffu, mx, 1));
        mx = fmaxf(mx, __shfl_xor_sync(0xffffffffu, mx, 2));
        float s = 0.f;
#pragma unroll 4
        for (int k = 0; k < 32; k++) {
            float e = expf(zr[k] - mx);
            zr[k] = e;
            s += e;
        }
        s += __shfl_xor_sync(0xffffffffu, s, 1);
        s += __shfl_xor_sync(0xffffffffu, s, 2);
        float inv = 1.f / s;
#pragma unroll 4
        for (int k = 0; k < 32; k++) zr[k] *= inv;
    }
    __syncthreads();

    // phase 2: attbuf[64x200] = Z @ lts
    for (int nb = 0; nb < 2; nb++) {
        ull acc[4][2];
#pragma unroll
        for (int i = 0; i < 4; i++)
#pragma unroll
            for (int j = 0; j < 2; j++) acc[i][j] = 0ULL;
        for (int k = 0; k < 128; k++) {
            ull a[4];
#pragma unroll
            for (int i = 0; i < 4; i++) a[i] = bcast2(Z[(ty + 16 * i) * 129 + k]);
#pragma unroll
            for (int j = 0; j < 2; j++) {
                ull bb = *(const ull*)&lts[k * DD + nb * 128 + 2 * tx + 64 * j];
#pragma unroll
                for (int i = 0; i < 4; i++) acc[i][j] = ffma2u(a[i], bb, acc[i][j]);
            }
        }
#pragma unroll
        for (int i = 0; i < 4; i++)
#pragma unroll
            for (int j = 0; j < 2; j++) {
                int r = ty + 16 * i;
                int d = nb * 128 + 2 * tx + 64 * j;
                if (d < DD) {
                    float2 f = unpack2(acc[i][j]);
                    *(float2*)(attbuf + r * DD + d) = f;
                }
            }
    }
    __syncthreads();

    // attentive mp-elementwise (cols [41,62)): 8 threads/row
    float* wsT = Z;  // reuse: [200][20]
    for (int i = tid; i < DD * MPP; i += 512) {
        int d = i / MPP, m = i - d * MPP;
        wsT[d * MPP + m] = w_att[m * DD + d];
    }
    __syncthreads();
    {
        int l = tid >> 3, q = tid & 7;
        int row = rh * 64 + l;
        const float* xp = attbuf + l * DD + q * 25;
        const float* yp = rt + (size_t)(b * LL + row) * DD + q * 25;
        float cos_acc = 0.f;
        ull macc[MPP / 2];
#pragma unroll
        for (int mm = 0; mm < MPP / 2; mm++) macc[mm] = 0ULL;
#pragma unroll
        for (int i = 0; i < 25; i++) {
            float p = xp[i] * __ldg(yp + i);
            cos_acc += p;
            ull pb = bcast2(p);
            const ull* wr = (const ull*)&wsT[(q * 25 + i) * MPP];
#pragma unroll
            for (int mm = 0; mm < MPP / 2; mm++) macc[mm] = ffma2u(pb, wr[mm], macc[mm]);
        }
        cos_acc += __shfl_xor_sync(0xffffffffu, cos_acc, 1);
        cos_acc += __shfl_xor_sync(0xffffffffu, cos_acc, 2);
        cos_acc += __shfl_xor_sync(0xffffffffu, cos_acc, 4);
#pragma unroll
        for (int mm = 0; mm < MPP / 2; mm++) {
            macc[mm] = addp2(macc[mm], __shfl_xor_sync(0xffffffffu, macc[mm], 1));
            macc[mm] = addp2(macc[mm], __shfl_xor_sync(0xffffffffu, macc[mm], 2));
            macc[mm] = addp2(macc[mm], __shfl_xor_sync(0xffffffffu, macc[mm], 4));
        }
        if (q == 0) {
            float* o = out + (size_t)(b * LL + row) * OC + 41;
            o[0] = tanhf(cos_acc);
#pragma unroll
            for (int mm = 0; mm < MPP / 2; mm++) {
                float2 f = unpack2(macc[mm]);
                o[1 + 2 * mm] = tanhf(f.x);
                o[2 + 2 * mm] = tanhf(f.y);
            }
        }
    }
}

// ================= launch =================
extern "C" void kernel_launch(void* const* d_in, const int* in_sizes, int n_in,
                              void* d_out, int out_size) {
    const float* reps_lt = (const float*)d_in[0];
    const float* reps_rt = (const float*)d_in[1];
    const float* fw_h = (const float*)d_in[2];
    const float* bw_h = (const float*)d_in[3];
    const float* w_full = (const float*)d_in[4];
    const float* w_maxpool = (const float*)d_in[5];
    const float* w_att = (const float*)d_in[6];
    const float* w_maxatt = (const float*)d_in[7];
    const float* attn_w1 = (const float*)d_in[8];
    const float* attn_w2 = (const float*)d_in[9];
    const float* diag_w = (const float*)d_in[10];
    float* out = (float*)d_out;

    cudaFuncSetAttribute(megaA, cudaFuncAttributeMaxDynamicSharedMemorySize, SMEM_MP);
    cudaFuncSetAttribute(kernelB, cudaFuncAttributeMaxDynamicSharedMemorySize, SMEM_B);

    megaA<<<GRID_MEGA, 512, SMEM_MP>>>(reps_lt, reps_rt, fw_h, bw_h, w_full,
                                       w_maxpool, attn_w1, attn_w2, diag_w,
                                       w_maxatt, out);
    kernelB<<<dim3(BB, 2), 512, SMEM_B>>>(reps_lt, reps_rt, w_att, out);
}

// round 11
// speedup vs baseline: 2.9463x; 1.1697x over previous
#include <cuda_runtime.h>
#include <cuda_fp16.h>
#include <math.h>
#include <stdint.h>

#define BB 64
#define LL 128
#define DD 200
#define MPP 20
#define ATTN 50
#define OC 83

typedef unsigned long long ull;

// ---------------- scratch ----------------
__device__ __align__(16) float g_e_rt[BB * LL * ATTN];
__device__ __align__(16) float g_e_lt[BB * LL * ATTN];

// -------- packed fp32x2 helpers --------
__device__ __forceinline__ ull ffma2u(ull a, ull b, ull c) {
    ull d;
    asm("fma.rn.f32x2 %0, %1, %2, %3;" : "=l"(d) : "l"(a), "l"(b), "l"(c));
    return d;
}
__device__ __forceinline__ ull addp2(ull a, ull b) {
    ull d;
    asm("add.rn.f32x2 %0, %1, %2;" : "=l"(d) : "l"(a), "l"(b));
    return d;
}
__device__ __forceinline__ ull bcast2(float x) {
    ull r;
    asm("mov.b64 %0, {%1, %1};" : "=l"(r) : "f"(x));
    return r;
}
__device__ __forceinline__ float2 unpack2(ull v) {
    float2 f;
    asm("mov.b64 {%0, %1}, %2;" : "=f"(f.x), "=f"(f.y) : "l"(v));
    return f;
}

// -------- warp MMA helpers --------
__device__ __forceinline__ uint32_t smem_to_u32(const void* p) {
    uint32_t a;
    asm("{ .reg .u64 t; cvta.to.shared.u64 t, %1; cvt.u32.u64 %0, t; }" : "=r"(a) : "l"(p));
    return a;
}
__device__ __forceinline__ void ldsm_x4(uint32_t* r, uint32_t addr) {
    asm volatile("ldmatrix.sync.aligned.m8n8.x4.shared.b16 {%0,%1,%2,%3}, [%4];"
                 : "=r"(r[0]), "=r"(r[1]), "=r"(r[2]), "=r"(r[3]) : "r"(addr));
}
__device__ __forceinline__ void mma16816(float* c, const uint32_t* a, const uint32_t* b) {
    asm volatile(
        "mma.sync.aligned.m16n8k16.row.col.f32.f16.f16.f32 "
        "{%0,%1,%2,%3}, {%4,%5,%6,%7}, {%8,%9}, {%0,%1,%2,%3};"
        : "+f"(c[0]), "+f"(c[1]), "+f"(c[2]), "+f"(c[3])
        : "r"(a[0]), "r"(a[1]), "r"(a[2]), "r"(a[3]), "r"(b[0]), "r"(b[1]));
}

// ======================================================================
// maxpool: CTA = (b, m-group of 5). Plain fp16 A x B (single pass).
// ======================================================================
#define STRD 216
#define TILE_B (LL * STRD * 2)
#define OFF_A 0
#define OFF_B (TILE_B)
#define SMEM_MP (2 * TILE_B)            // 110592
#define MGRP 5

__device__ __forceinline__ void maxpool_block(
        const float* __restrict__ lt, const float* __restrict__ rt,
        const float* __restrict__ w, float* __restrict__ out,
        int b, int mg0, char* smc, float (*red)[4]) {
    uint32_t sbase = smem_to_u32(smc);
    int tid = threadIdx.x, lane = tid & 31, wid = tid >> 5;

    for (int i = tid; i < 128 * 4; i += 512) {
        int r = i >> 2, c = i & 3;
        int off = (r * STRD + 200 + 2 * c) * 2;
        *(uint32_t*)(smc + OFF_A + off) = 0;
        *(uint32_t*)(smc + OFF_B + off) = 0;
    }
    const float* ltb = lt + (size_t)b * LL * DD;
    const float* rtb = rt + (size_t)b * LL * DD;
    for (int i = tid; i < LL * 100; i += 512) {
        int r = i / 100, k = (i - r * 100) * 2;
        float2 x = *(const float2*)(ltb + r * DD + k);
        __half2 h2 = __float22half2_rn(x);
        *(uint32_t*)(smc + OFF_A + (r * STRD + k) * 2) = *(uint32_t*)&h2;
    }

    int mbase = (wid >> 2) * 32, nbase = (wid & 3) * 32;
    int a_row = lane & 15;
    int a_col8 = (lane & 16) ? 8 : 0;
    int b_row = (lane & 7) + ((lane & 16) ? 8 : 0);
    int b_col8 = (lane & 8) ? 8 : 0;
    int wc = wid & 3;

#pragma unroll 1
    for (int mg = 0; mg < MGRP; mg++) {
        int m = mg0 + mg;
        const float* wm = w + (size_t)m * DD;
        for (int i = tid; i < LL * 100; i += 512) {
            int r = i / 100, k = (i - r * 100) * 2;
            float2 xb = *(const float2*)(rtb + r * DD + k);
            float2 ww = *(const float2*)(wm + k);
            __half2 h2 = __float22half2_rn(make_float2(xb.x * ww.x, xb.y * ww.y));
            *(uint32_t*)(smc + OFF_B + (r * STRD + k) * 2) = *(uint32_t*)&h2;
        }
        __syncthreads();

        float acc[2][4][4];
#pragma unroll
        for (int mt = 0; mt < 2; mt++)
#pragma unroll
            for (int nt = 0; nt < 4; nt++)
#pragma unroll
                for (int q = 0; q < 4; q++) acc[mt][nt][q] = 0.f;

#pragma unroll 1
        for (int kg = 0; kg < 13; kg++) {
            int kc = kg * 16;
            uint32_t ah[2][4];
#pragma unroll
            for (int mt = 0; mt < 2; mt++) {
                uint32_t row = mbase + 16 * mt + a_row;
                ldsm_x4(ah[mt], sbase + OFF_A + (row * STRD + kc + a_col8) * 2);
            }
#pragma unroll
            for (int np = 0; np < 2; np++) {
                uint32_t row = nbase + np * 16 + b_row;
                uint32_t bh[4];
                ldsm_x4(bh, sbase + OFF_B + (row * STRD + kc + b_col8) * 2);
#pragma unroll
                for (int mt = 0; mt < 2; mt++) {
                    mma16816(acc[mt][2 * np], ah[mt], bh);
                    mma16816(acc[mt][2 * np + 1], ah[mt], bh + 2);
                }
            }
        }

#pragma unroll
        for (int mt = 0; mt < 2; mt++) {
            float lo = -3.4e38f, hi = -3.4e38f;
#pragma unroll
            for (int nt = 0; nt < 4; nt++) {
                lo = fmaxf(lo, fmaxf(acc[mt][nt][0], acc[mt][nt][1]));
                hi = fmaxf(hi, fmaxf(acc[mt][nt][2], acc[mt][nt][3]));
            }
            lo = fmaxf(lo, __shfl_xor_sync(0xffffffffu, lo, 1));
            lo = fmaxf(lo, __shfl_xor_sync(0xffffffffu, lo, 2));
            hi = fmaxf(hi, __shfl_xor_sync(0xffffffffu, hi, 1));
            hi = fmaxf(hi, __shfl_xor_sync(0xffffffffu, hi, 2));
            if ((lane & 3) == 0) {
                int r = mbase + 16 * mt + (lane >> 2);
                red[r][wc] = lo;
                red[r + 8][wc] = hi;
            }
        }
        __syncthreads();
        if (tid < 128) {
            float v = fmaxf(fmaxf(red[tid][0], red[tid][1]),
                            fmaxf(red[tid][2], red[tid][3]));
            out[(size_t)(b * LL + tid) * OC + 21 + m] = tanhf(v);
        }
    }
}

// ================= branch: full match (cols [0,21)) =================
__device__ __forceinline__ void full_block(
        const float* __restrict__ lt, const float* __restrict__ fw,
        const float* __restrict__ bw, const float* __restrict__ wf,
        float* __restrict__ out, int b, float* sm) {
    float* hw = sm;
    int tid = threadIdx.x;
    for (int idx = tid; idx < (MPP + 1) * DD; idx += 512) {
        int mm = idx / DD, d = idx - mm * DD;
        float hv = (d < DD / 2) ? fw[b * (DD / 2) + d] : bw[b * (DD / 2) + d - DD / 2];
        hw[idx] = (mm == 0) ? hv : wf[(mm - 1) * DD + d] * hv;
    }
    __syncthreads();
    if (tid < 128) {
        const ull* row = (const ull*)(lt + (size_t)(b * LL + tid) * DD);
        ull acc[MPP + 1];
#pragma unroll
        for (int mm = 0; mm <= MPP; mm++) acc[mm] = 0ULL;
        for (int d2 = 0; d2 < DD / 2; d2++) {
            ull x = __ldg(row + d2);
#pragma unroll
            for (int mm = 0; mm <= MPP; mm++)
                acc[mm] = ffma2u(x, *(const ull*)&hw[mm * DD + 2 * d2], acc[mm]);
        }
        float* o = out + (size_t)(b * LL + tid) * OC;
#pragma unroll
        for (int mm = 0; mm <= MPP; mm++) {
            float2 f = unpack2(acc[mm]);
            o[mm] = tanhf(f.x + f.y);
        }
    }
}

// ================= branch: attention projection =================
__device__ __forceinline__ void proj_block(
        const float* __restrict__ lt, const float* __restrict__ rt,
        const float* __restrict__ w1, const float* __restrict__ w2,
        const float* __restrict__ diag, int b, int side, float* sm) {
    float* ws = sm;
    float* pbuf = sm + 10000;
    int tid = threadIdx.x;
    const float* wsrc = side == 0 ? w1 : w2;
    for (int i = tid; i < DD * ATTN; i += 512) ws[i] = wsrc[i];
    __syncthreads();
    int l = tid & 127, dh = (tid >> 7) & 1;
    ull acc[ATTN / 2];
    if (tid < 256) {
        const float* base = side == 0 ? rt : lt;
        const float4* row = (const float4*)(base + (size_t)(b * LL + l) * DD + dh * 100);
#pragma unroll
        for (int a = 0; a < ATTN / 2; a++) acc[a] = 0ULL;
        for (int d4 = 0; d4 < 25; d4++) {
            float4 x = __ldg(row + d4);
            int d = dh * 100 + d4 * 4;
#pragma unroll
            for (int c = 0; c < 4; c++) {
                float xc = (c == 0) ? x.x : (c == 1) ? x.y : (c == 2) ? x.z : x.w;
                ull x2 = bcast2(xc);
                const ull* wr = (const ull*)&ws[(d + c) * ATTN];
#pragma unroll
                for (int a = 0; a < ATTN / 2; a++) acc[a] = ffma2u(x2, wr[a], acc[a]);
            }
        }
        if (dh == 1) {
#pragma unroll
            for (int a = 0; a < ATTN / 2; a++) {
                float2 f = unpack2(acc[a]);
                pbuf[(2 * a) * 128 + l] = f.x;
                pbuf[(2 * a + 1) * 128 + l] = f.y;
            }
        }
    }
    __syncthreads();
    if (tid < 256 && dh == 0) {
        float* e = (side == 0 ? g_e_rt : g_e_lt) + (size_t)(b * LL + l) * ATTN;
#pragma unroll
        for (int a = 0; a < ATTN / 2; a++) {
            float2 f = unpack2(acc[a]);
            float v0 = tanhf(f.x + pbuf[(2 * a) * 128 + l]);
            float v1 = tanhf(f.y + pbuf[(2 * a + 1) * 128 + l]);
            if (side == 0) {
                v0 *= __ldg(diag + 2 * a);
                v1 *= __ldg(diag + 2 * a + 1);
            }
            e[2 * a] = v0;
            e[2 * a + 1] = v1;
        }
    }
}

// ======= branch: max-attentive argmax + its mp-elementwise (cols [62,83)) =======
__device__ __forceinline__ void maxatt_block(
        const float* __restrict__ lt, const float* __restrict__ rt,
        const float* __restrict__ w_maxatt, float* __restrict__ out,
        int b, int rh, float* sm) {
    float* As = sm;
    float* Bs = sm + 512;
    float* nlt = sm + 1536;
    float* redv = sm + 1664;
    int* redi = (int*)(sm + 2688);
    float* wsT = sm + 3712;
    int tid = threadIdx.x;
    int tx = tid & 15, ty = (tid >> 4) & 15;
    if (tid < 128) {
        const float4* p = (const float4*)(lt + (size_t)(b * LL + tid) * DD);
        float s = 0.f;
        for (int i = 0; i < DD / 4; i++) {
            float4 v = __ldg(p + i);
            s += v.x * v.x + v.y * v.y + v.z * v.z + v.w * v.w;
        }
        nlt[tid] = rsqrtf(fmaxf(s, 1e-6f));
    }
    for (int i = tid; i < DD * MPP; i += 512) {
        int d = i / MPP, m = i - d * MPP;
        wsT[d * MPP + m] = w_maxatt[m * DD + d];
    }
    int lrow = (tid >> 1) & 127, kq = tid & 1;
    int arow = (tid >> 1) & 63;
    const float4* bp = (const float4*)(lt + (size_t)(b * LL + lrow) * DD);
    const float4* ap = (const float4*)(rt + (size_t)(b * LL + rh * 64 + arow) * DD);
    ull acc[4][4];
#pragma unroll
    for (int i = 0; i < 4; i++)
#pragma unroll
        for (int j = 0; j < 4; j++) acc[i][j] = 0ULL;
    for (int kc = 0; kc < DD / 8; kc++) {
        if (tid < 256) {
            float4 bv = __ldg(bp + kc * 2 + kq);
            int kb = kq * 4;
            Bs[(kb + 0) * 128 + lrow] = bv.x;
            Bs[(kb + 1) * 128 + lrow] = bv.y;
            Bs[(kb + 2) * 128 + lrow] = bv.z;
            Bs[(kb + 3) * 128 + lrow] = bv.w;
            if (tid < 128) {
                float4 av = __ldg(ap + kc * 2 + kq);
                As[(kb + 0) * 64 + arow] = av.x;
                As[(kb + 1) * 64 + arow] = av.y;
                As[(kb + 2) * 64 + arow] = av.z;
                As[(kb + 3) * 64 + arow] = av.w;
            }
        }
        __syncthreads();
        if (tid < 256) {
#pragma unroll
            for (int k = 0; k < 8; k++) {
                ull a[4];
#pragma unroll
                for (int i = 0; i < 4; i++) a[i] = bcast2(As[k * 64 + ty + 16 * i]);
#pragma unroll
                for (int j = 0; j < 4; j++) {
                    ull bb = *(const ull*)&Bs[k * 128 + 2 * tx + 32 * j];
#pragma unroll
                    for (int i = 0; i < 4; i++) acc[i][j] = ffma2u(a[i], bb, acc[i][j]);
                }
            }
        }
        __syncthreads();
    }
    if (tid < 256) {
#pragma unroll
        for (int i = 0; i < 4; i++) {
            int r = ty + 16 * i;
            float best = -3.4e38f;
            int bi = 0;
#pragma unroll
            for (int j = 0; j < 4; j++) {
                int c = 2 * tx + 32 * j;
                float2 f = unpack2(acc[i][j]);
                float v0 = f.x * nlt[c];
                float v1 = f.y * nlt[c + 1];
                if (v0 > best) { best = v0; bi = c; }
                if (v1 > best) { best = v1; bi = c + 1; }
            }
            redv[r * 16 + tx] = best;
            redi[r * 16 + tx] = bi;
        }
    }
    __syncthreads();
    __shared__ int posbuf[64];
    if (tid < 64) {
        float best = redv[tid * 16];
        int bi = redi[tid * 16];
#pragma unroll
        for (int t = 1; t < 16; t++) {
            float v = redv[tid * 16 + t];
            int ii = redi[tid * 16 + t];
            if (v > best || (v == best && ii < bi)) { best = v; bi = ii; }
        }
        posbuf[tid] = bi;
    }
    __syncthreads();
    if (tid < 256) {
        int l = tid >> 2, q = tid & 3;
        int row = rh * 64 + l;
        const float2* xp = (const float2*)(rt + (size_t)(b * LL + row) * DD + q * 50);
        const float2* yp = (const float2*)(lt + (size_t)(b * LL + posbuf[l]) * DD + q * 50);
        float cos_acc = 0.f;
        ull macc[MPP / 2];
#pragma unroll
        for (int mm = 0; mm < MPP / 2; mm++) macc[mm] = 0ULL;
#pragma unroll
        for (int i = 0; i < 25; i++) {
            float2 x = __ldg(xp + i);
            float2 y = __ldg(yp + i);
            float p0 = x.x * y.x, p1 = x.y * y.y;
            cos_acc += p0 + p1;
            int d = q * 50 + 2 * i;
            ull pb0 = bcast2(p0), pb1 = bcast2(p1);
            const ull* w0 = (const ull*)&wsT[d * MPP];
            const ull* w1 = (const ull*)&wsT[(d + 1) * MPP];
#pragma unroll
            for (int mm = 0; mm < MPP / 2; mm++) {
                macc[mm] = ffma2u(pb0, w0[mm], macc[mm]);
                macc[mm] = ffma2u(pb1, w1[mm], macc[mm]);
            }
        }
        cos_acc += __shfl_xor_sync(0xffffffffu, cos_acc, 1);
        cos_acc += __shfl_xor_sync(0xffffffffu, cos_acc, 2);
#pragma unroll
        for (int mm = 0; mm < MPP / 2; mm++) {
            macc[mm] = addp2(macc[mm], __shfl_xor_sync(0xffffffffu, macc[mm], 1));
            macc[mm] = addp2(macc[mm], __shfl_xor_sync(0xffffffffu, macc[mm], 2));
        }
        if (q == 0) {
            float* o = out + (size_t)(b * LL + row) * OC + 62;
            o[0] = tanhf(cos_acc);
#pragma unroll
            for (int mm = 0; mm < MPP / 2; mm++) {
                float2 f = unpack2(macc[mm]);
                o[1 + 2 * mm] = tanhf(f.x);
                o[2 + 2 * mm] = tanhf(f.y);
            }
        }
    }
}

// ================= megaA =================
#define GRID_MP (BB * (MPP / MGRP))     // 256
#define GRID_MEGA (GRID_MP + BB + 2 * BB + 2 * BB)

__global__ __launch_bounds__(512, 2) void megaA(
        const float* __restrict__ lt, const float* __restrict__ rt,
        const float* __restrict__ fw, const float* __restrict__ bw,
        const float* __restrict__ w_full, const float* __restrict__ w_maxpool,
        const float* __restrict__ w1, const float* __restrict__ w2,
        const float* __restrict__ diag, const float* __restrict__ w_maxatt,
        float* __restrict__ out) {
    extern __shared__ char smc[];
    __shared__ float red[128][4];
    int bx = blockIdx.x;
    if (bx < GRID_MP) {
        maxpool_block(lt, rt, w_maxpool, out, bx >> 2, (bx & 3) * MGRP, smc, red);
    } else if (bx < GRID_MP + BB) {
        full_block(lt, fw, bw, w_full, out, bx - GRID_MP, (float*)smc);
    } else if (bx < GRID_MP + BB + 2 * BB) {
        int i = bx - GRID_MP - BB;
        proj_block(lt, rt, w1, w2, diag, i >> 1, i & 1, (float*)smc);
    } else {
        int i = bx - GRID_MP - 3 * BB;
        maxatt_block(lt, rt, w_maxatt, out, i >> 1, i & 1, (float*)smc);
    }
}

// ================= kernel B: mma-based logits + softmax + att_lt + attentive mp ======
// floats: Z[64*129] | attbuf[64*200] ; halves after: ers_h[64*72] elts_h[128*72]
//          Zh[64*136] ltsT[256*136]
#define SMB_Z 0
#define SMB_ATT (64 * 129)
#define SMB_HALF (SMB_ATT + 64 * 200)
#define SMEM_B ((SMB_HALF + (64 * 72 + 128 * 72 + 64 * 136 + 256 * 136) / 2) * 4)

__global__ __launch_bounds__(512) void kernelB(
        const float* __restrict__ lt, const float* __restrict__ rt,
        const float* __restrict__ w_att, float* __restrict__ out) {
    extern __shared__ float sm[];
    float* Z = sm + SMB_Z;
    float* attbuf = sm + SMB_ATT;
    __half* ers_h = (__half*)(sm + SMB_HALF);
    __half* elts_h = ers_h + 64 * 72;
    __half* Zh = elts_h + 128 * 72;
    __half* ltsT = Zh + 64 * 136;
    int b = blockIdx.x, rh = blockIdx.y;
    int tid = threadIdx.x, lane = tid & 31, wid = tid >> 5;

    // stage ers_h [64 x 72] (k pad 50->72 with zeros)
    const float* ersrc = g_e_rt + ((size_t)b * LL + rh * 64) * ATTN;
    for (int i = tid; i < 64 * 36; i += 512) {
        int r = i / 36, kk = (i - r * 36) * 2;
        float v0 = (kk < 50) ? ersrc[r * 50 + kk] : 0.f;
        float v1 = (kk + 1 < 50) ? ersrc[r * 50 + kk + 1] : 0.f;
        *(__half2*)&ers_h[r * 72 + kk] = __float22half2_rn(make_float2(v0, v1));
    }
    // stage elts_h [128 x 72]
    const float* elsrc = g_e_lt + (size_t)b * LL * ATTN;
    for (int i = tid; i < 128 * 36; i += 512) {
        int r = i / 36, kk = (i - r * 36) * 2;
        float v0 = (kk < 50) ? elsrc[r * 50 + kk] : 0.f;
        float v1 = (kk + 1 < 50) ? elsrc[r * 50 + kk + 1] : 0.f;
        *(__half2*)&elts_h[r * 72 + kk] = __float22half2_rn(make_float2(v0, v1));
    }
    // stage ltsT [256 x 136]: ltsT[d][l] = lt[l][d], d pad 200->256 zeros
    const float* ltb = lt + (size_t)b * LL * DD;
    for (int i = tid; i < 256 * 64; i += 512) {
        int d = i & 255, lp = (i >> 8) * 2;
        float v0 = 0.f, v1 = 0.f;
        if (d < 200) {
            v0 = __ldg(ltb + lp * DD + d);
            v1 = __ldg(ltb + (lp + 1) * DD + d);
        }
        *(__half2*)&ltsT[d * 136 + lp] = __float22half2_rn(make_float2(v0, v1));
    }
    __syncthreads();

    uint32_t ers_b = smem_to_u32(ers_h);
    uint32_t elts_b = smem_to_u32(elts_h);
    uint32_t zh_b = smem_to_u32(Zh);
    uint32_t ltsT_b = smem_to_u32(ltsT);

    int wm = wid >> 2, wn = wid & 3;
    int mbase = wm * 16;
    int a_row = lane & 15;
    int a_col8 = (lane & 16) ? 8 : 0;
    int b_row = (lane & 7) + ((lane & 16) ? 8 : 0);
    int b_col8 = (lane & 8) ? 8 : 0;

    // phase 1: Z[64x128] = ers @ elts^T via mma (K=64)
    {
        int nbase = wn * 32;
        float acc[4][4];
#pragma unroll
        for (int t = 0; t < 4; t++)
#pragma unroll
            for (int q = 0; q < 4; q++) acc[t][q] = 0.f;
#pragma unroll
        for (int kt = 0; kt < 4; kt++) {
            uint32_t a[4];
            ldsm_x4(a, ers_b + ((mbase + a_row) * 72 + kt * 16 + a_col8) * 2);
#pragma unroll
            for (int np = 0; np < 2; np++) {
                uint32_t bh[4];
                ldsm_x4(bh, elts_b + ((nbase + np * 16 + b_row) * 72 + kt * 16 + b_col8) * 2);
                mma16816(acc[2 * np], a, bh);
                mma16816(acc[2 * np + 1], a, bh + 2);
            }
        }
        int rr = mbase + (lane >> 2);
#pragma unroll
        for (int t = 0; t < 4; t++) {
            int c = nbase + t * 8 + 2 * (lane & 3);
            Z[rr * 129 + c] = acc[t][0];
            Z[rr * 129 + c + 1] = acc[t][1];
            Z[(rr + 8) * 129 + c] = acc[t][2];
            Z[(rr + 8) * 129 + c + 1] = acc[t][3];
        }
    }
    __syncthreads();

    // softmax: 4 threads per row
    if (tid < 256) {
        int r = tid >> 2, h = tid & 3;
        float* zr = Z + r * 129 + h * 32;
        float mx = zr[0];
#pragma unroll 4
        for (int k = 1; k < 32; k++) mx = fmaxf(mx, zr[k]);
        mx = fmaxf(mx, __shfl_xor_sync(0xffffffffu, mx, 1));
        mx = fmaxf(mx, __shfl_xor_sync(0xffffffffu, mx, 2));
        float s = 0.f;
#pragma unroll 4
        for (int k = 0; k < 32; k++) {
            float e = expf(zr[k] - mx);
            zr[k] = e;
            s += e;
        }
        s += __shfl_xor_sync(0xffffffffu, s, 1);
        s += __shfl_xor_sync(0xffffffffu, s, 2);
        float inv = 1.f / s;
#pragma unroll 4
        for (int k = 0; k < 32; k++) zr[k] *= inv;
    }
    __syncthreads();

    // Zh convert [64 x 136] (K=128)
    for (int i = tid; i < 64 * 64; i += 512) {
        int r = i >> 6, kp = (i & 63) * 2;
        *(__half2*)&Zh[r * 136 + kp] =
            __float22half2_rn(make_float2(Z[r * 129 + kp], Z[r * 129 + kp + 1]));
    }
    __syncthreads();

    // phase 2: attbuf[64x200] = Z @ lt via mma (N pad 256, K=128)
    {
        int nbase = wn * 64;
        float acc[8][4];
#pragma unroll
        for (int t = 0; t < 8; t++)
#pragma unroll
            for (int q = 0; q < 4; q++) acc[t][q] = 0.f;
#pragma unroll
        for (int kt = 0; kt < 8; kt++) {
            uint32_t a[4];
            ldsm_x4(a, zh_b + ((mbase + a_row) * 136 + kt * 16 + a_col8) * 2);
#pragma unroll
            for (int np = 0; np < 4; np++) {
                uint32_t bh[4];
                ldsm_x4(bh, ltsT_b + ((nbase + np * 16 + b_row) * 136 + kt * 16 + b_col8) * 2);
                mma16816(acc[2 * np], a, bh);
                mma16816(acc[2 * np + 1], a, bh + 2);
            }
        }
        int rr = mbase + (lane >> 2);
#pragma unroll
        for (int t = 0; t < 8; t++) {
            int d = nbase + t * 8 + 2 * (lane & 3);
            if (d < 200) {
                attbuf[rr * DD + d] = acc[t][0];
                attbuf[rr * DD + d + 1] = acc[t][1];
                attbuf[(rr + 8) * DD + d] = acc[t][2];
                attbuf[(rr + 8) * DD + d + 1] = acc[t][3];
            }
        }
    }
    __syncthreads();

    // attentive mp-elementwise (cols [41,62)): 8 threads/row
    float* wsT = Z;  // reuse Z: [200][20]
    for (int i = tid; i < DD * MPP; i += 512) {
        int d = i / MPP, m = i - d * MPP;
        wsT[d * MPP + m] = w_att[m * DD + d];
    }
    __syncthreads();
    {
        int l = tid >> 3, q = tid & 7;
        int row = rh * 64 + l;
        const float* xp = attbuf + l * DD + q * 25;
        const float* yp = rt + (size_t)(b * LL + row) * DD + q * 25;
        float cos_acc = 0.f;
        ull macc[MPP / 2];
#pragma unroll
        for (int mm = 0; mm < MPP / 2; mm++) macc[mm] = 0ULL;
#pragma unroll
        for (int i = 0; i < 25; i++) {
            float p = xp[i] * __ldg(yp + i);
            cos_acc += p;
            ull pb = bcast2(p);
            const ull* wr = (const ull*)&wsT[(q * 25 + i) * MPP];
#pragma unroll
            for (int mm = 0; mm < MPP / 2; mm++) macc[mm] = ffma2u(pb, wr[mm], macc[mm]);
        }
        cos_acc += __shfl_xor_sync(0xffffffffu, cos_acc, 1);
        cos_acc += __shfl_xor_sync(0xffffffffu, cos_acc, 2);
        cos_acc += __shfl_xor_sync(0xffffffffu, cos_acc, 4);
#pragma unroll
        for (int mm = 0; mm < MPP / 2; mm++) {
            macc[mm] = addp2(macc[mm], __shfl_xor_sync(0xffffffffu, macc[mm], 1));
            macc[mm] = addp2(macc[mm], __shfl_xor_sync(0xffffffffu, macc[mm], 2));
            macc[mm] = addp2(macc[mm], __shfl_xor_sync(0xffffffffu, macc[mm], 4));
        }
        if (q == 0) {
            float* o = out + (size_t)(b * LL + row) * OC + 41;
            o[0] = tanhf(cos_acc);
#pragma unroll
            for (int mm = 0; mm < MPP / 2; mm++) {
                float2 f = unpack2(macc[mm]);
                o[1 + 2 * mm] = tanhf(f.x);
                o[2 + 2 * mm] = tanhf(f.y);
            }
        }
    }
}

// ================= launch =================
extern "C" void kernel_launch(void* const* d_in, const int* in_sizes, int n_in,
                              void* d_out, int out_size) {
    const float* reps_lt = (const float*)d_in[0];
    const float* reps_rt = (const float*)d_in[1];
    const float* fw_h = (const float*)d_in[2];
    const float* bw_h = (const float*)d_in[3];
    const float* w_full = (const float*)d_in[4];
    const float* w_maxpool = (const float*)d_in[5];
    const float* w_att = (const float*)d_in[6];
    const float* w_maxatt = (const float*)d_in[7];
    const float* attn_w1 = (const float*)d_in[8];
    const float* attn_w2 = (const float*)d_in[9];
    const float* diag_w = (const float*)d_in[10];
    float* out = (float*)d_out;

    cudaFuncSetAttribute(megaA, cudaFuncAttributeMaxDynamicSharedMemorySize, SMEM_MP);
    cudaFuncSetAttribute(kernelB, cudaFuncAttributeMaxDynamicSharedMemorySize, SMEM_B);

    megaA<<<GRID_MEGA, 512, SMEM_MP>>>(reps_lt, reps_rt, fw_h, bw_h, w_full,
                                       w_maxpool, attn_w1, attn_w2, diag_w,
                                       w_maxatt, out);
    kernelB<<<dim3(BB, 2), 512, SMEM_B>>>(reps_lt, reps_rt, w_att, out);
}